// round 10
// baseline (speedup 1.0000x reference)
#include <cuda_runtime.h>
#include <math.h>

#define BSZ 32
#define PP 196
#define ENCD 2048
#define ATTD 512
#define DECD 512
#define VV 10000
#define LL 52
#define TT 51
#define GRID 296

#define OFF_PRED  0L
#define OFF_TOKS  ((long)BSZ*TT*VV)
#define OFF_DLEN  (OFF_TOKS + (long)BSZ*LL)
#define OFF_ALPHA (OFF_DLEN + (long)BSZ)
#define OFF_SORT  (OFF_ALPHA + (long)BSZ*TT*PP)

// ---------------- static device scratch ----------------
__device__ float g_enc[6272L*512];
__device__ float g_embg[51L*32*2048];
__device__ float g_pHH[8L*32*2048];
__device__ float g_pBeta[8L*32*2048];
__device__ float g_pIH[32L*32*2048];
__device__ float g_mean[32*2048];
__device__ float g_h[32*512];
__device__ float g_c[32*512];
__device__ float g_hnall[1664L*512];
__device__ float g_x2[32*2048];
__device__ float g_alpha[32*196];
__device__ float g_bcomb[2048];
__device__ int   g_sort[32];
__device__ int   g_dlen[32];
__device__ int   g_act[TT];
__device__ int   g_toks[32*LL];
__device__ unsigned g_barcnt;
__device__ volatile unsigned g_bargen;

__device__ __forceinline__ float sigm(float x) { return 1.f / (1.f + expf(-x)); }

// ---------------- grid-wide software barrier (nanosleep backoff) ----------------
__device__ __forceinline__ void gridbar() {
    __syncthreads();
    if (threadIdx.x == 0) {
        __threadfence();
        unsigned gen = g_bargen;
        if (atomicAdd(&g_barcnt, 1u) == GRID - 1) {
            g_barcnt = 0;
            __threadfence();
            g_bargen = gen + 1;
        } else {
            while (g_bargen == gen) { __nanosleep(150); }
        }
        __threadfence();
    }
    __syncthreads();
}

// ---------------- 32-row GEMM partial tile, register-prefetch pipelined ----------------
__device__ void gemm32(const float* __restrict__ X, int ldx,
                       const int* __restrict__ gidx, int gstride,
                       const float* __restrict__ W, int ldw, int wcol0,
                       int Nfull, int nbase, int k0, int klen,
                       float* __restrict__ part, int Nld, float* pool)
{
    float* Xs = pool;                 // 32k x 36
    float* Ws = pool + 1184;          // 32k x 264
    int* roff = (int*)(pool + 1184 + 32*264);
    const int tid = threadIdx.x;
    __syncthreads();
    if (tid < 32) roff[tid] = (gidx ? gidx[tid * gstride] : tid) * ldx;
    __syncthreads();

    const int m0 = (tid >> 5) * 4;
    const int n0 = (tid & 31) * 8;
    const int xm = tid >> 3, xk = (tid & 7) * 4;
    const int wn = tid >> 3, wk = (tid & 7) * 4;

    float acc[4][8];
    #pragma unroll
    for (int i = 0; i < 4; i++)
        #pragma unroll
        for (int j = 0; j < 8; j++) acc[i][j] = 0.f;

    float4 xv = *(const float4*)(X + roff[xm] + k0 + xk);
    float4 wv[8];
    #pragma unroll
    for (int j = 0; j < 8; j++) {
        int ng = nbase + j*32 + wn;
        wv[j] = (ng < Nfull) ? *(const float4*)(W + (long)ng*ldw + wcol0 + k0 + wk)
                             : make_float4(0.f, 0.f, 0.f, 0.f);
    }

    for (int kk = 0; kk < klen; kk += 32) {
        Xs[(xk+0)*36 + xm] = xv.x; Xs[(xk+1)*36 + xm] = xv.y;
        Xs[(xk+2)*36 + xm] = xv.z; Xs[(xk+3)*36 + xm] = xv.w;
        #pragma unroll
        for (int j = 0; j < 8; j++) {
            int n = j*32 + wn;
            Ws[(wk+0)*264 + n] = wv[j].x; Ws[(wk+1)*264 + n] = wv[j].y;
            Ws[(wk+2)*264 + n] = wv[j].z; Ws[(wk+3)*264 + n] = wv[j].w;
        }
        __syncthreads();
        if (kk + 32 < klen) {
            int kc = k0 + kk + 32;
            xv = *(const float4*)(X + roff[xm] + kc + xk);
            #pragma unroll
            for (int j = 0; j < 8; j++) {
                int ng = nbase + j*32 + wn;
                wv[j] = (ng < Nfull) ? *(const float4*)(W + (long)ng*ldw + wcol0 + kc + wk)
                                     : make_float4(0.f, 0.f, 0.f, 0.f);
            }
        }
        #pragma unroll
        for (int k = 0; k < 32; k++) {
            float4 a = *(const float4*)&Xs[k*36 + m0];
            float av[4] = {a.x, a.y, a.z, a.w};
            float4 w0 = *(const float4*)&Ws[k*264 + n0];
            float4 w1 = *(const float4*)&Ws[k*264 + n0 + 4];
            float wvv[8] = {w0.x,w0.y,w0.z,w0.w,w1.x,w1.y,w1.z,w1.w};
            #pragma unroll
            for (int i = 0; i < 4; i++)
                #pragma unroll
                for (int j = 0; j < 8; j++)
                    acc[i][j] = fmaf(av[i], wvv[j], acc[i][j]);
        }
        __syncthreads();
    }
    #pragma unroll
    for (int i = 0; i < 4; i++)
        #pragma unroll
        for (int j = 0; j < 8; j++)
            part[(long)(m0+i)*Nld + nbase + n0 + j] = acc[i][j];
}

// ---------------- 128x64 dense tile, K=2048, pipelined: enc_att ----------------
__device__ void enc_task(int tm, int tn, const float* __restrict__ img,
                         const float* __restrict__ W_enc, const float* __restrict__ b_enc,
                         float* pool)
{
    float* As = pool;
    float* Bs = pool + 4224;
    int* rowb = (int*)(pool + 6400);
    const int tid = threadIdx.x;
    __syncthreads();
    if (tid < 128) {
        int rr = tm*128 + tid;
        int b = rr / PP, p = rr - b*PP;
        rowb[tid] = (g_sort[b]*PP + p) * ENCD;
    }
    __syncthreads();
    float acc[8][4];
    #pragma unroll
    for (int i = 0; i < 8; i++)
        #pragma unroll
        for (int j = 0; j < 4; j++) acc[i][j] = 0.f;
    const int ty = tid >> 4, tx = tid & 15;
    const int m0 = ty*8, n0 = tx*4;
    const int am = tid >> 3, ak = (tid & 7) * 4;
    const int bn = tid >> 3, bk = (tid & 7) * 4;

    float4 av4[4], bv4[2];
    #pragma unroll
    for (int j = 0; j < 4; j++)
        av4[j] = *(const float4*)(img + rowb[j*32 + am] + ak);
    #pragma unroll
    for (int j = 0; j < 2; j++)
        bv4[j] = *(const float4*)(W_enc + (long)(tn*64 + j*32 + bn)*ENCD + bk);

    for (int kc = 0; kc < ENCD; kc += 32) {
        #pragma unroll
        for (int j = 0; j < 4; j++) {
            int m = j*32 + am;
            As[(ak+0)*132+m] = av4[j].x; As[(ak+1)*132+m] = av4[j].y;
            As[(ak+2)*132+m] = av4[j].z; As[(ak+3)*132+m] = av4[j].w;
        }
        #pragma unroll
        for (int j = 0; j < 2; j++) {
            int n = j*32 + bn;
            Bs[(bk+0)*68+n] = bv4[j].x; Bs[(bk+1)*68+n] = bv4[j].y;
            Bs[(bk+2)*68+n] = bv4[j].z; Bs[(bk+3)*68+n] = bv4[j].w;
        }
        __syncthreads();
        if (kc + 32 < ENCD) {
            #pragma unroll
            for (int j = 0; j < 4; j++)
                av4[j] = *(const float4*)(img + rowb[j*32 + am] + kc + 32 + ak);
            #pragma unroll
            for (int j = 0; j < 2; j++)
                bv4[j] = *(const float4*)(W_enc + (long)(tn*64 + j*32 + bn)*ENCD + kc + 32 + bk);
        }
        #pragma unroll
        for (int k = 0; k < 32; k++) {
            float4 a0 = *(const float4*)&As[k*132 + m0];
            float4 a1 = *(const float4*)&As[k*132 + m0 + 4];
            float4 b0 = *(const float4*)&Bs[k*68 + n0];
            float avv[8] = {a0.x,a0.y,a0.z,a0.w,a1.x,a1.y,a1.z,a1.w};
            float bvv[4] = {b0.x,b0.y,b0.z,b0.w};
            #pragma unroll
            for (int i = 0; i < 8; i++)
                #pragma unroll
                for (int j = 0; j < 4; j++)
                    acc[i][j] = fmaf(avv[i], bvv[j], acc[i][j]);
        }
        __syncthreads();
    }
    #pragma unroll
    for (int i = 0; i < 8; i++) {
        int row = tm*128 + m0 + i;
        #pragma unroll
        for (int j = 0; j < 4; j++) {
            int col = tn*64 + n0 + j;
            g_enc[(long)row*512 + col] = acc[i][j] + b_enc[col];
        }
    }
}

// ---------------- 128x64 dense tile, K=512, pipelined: final FC ----------------
__device__ void fc_task(int tm, int tn,
                        const float* __restrict__ W_fc, const float* __restrict__ b_fc,
                        float* __restrict__ out, float* pool)
{
    float* As = pool;
    float* Bs = pool + 4224;
    const int tid = threadIdx.x;
    __syncthreads();
    float acc[8][4];
    #pragma unroll
    for (int i = 0; i < 8; i++)
        #pragma unroll
        for (int j = 0; j < 4; j++) acc[i][j] = 0.f;
    const int ty = tid >> 4, tx = tid & 15;
    const int m0 = ty*8, n0 = tx*4;
    const int am = tid >> 3, ak = (tid & 7) * 4;
    const int bn = tid >> 3, bk = (tid & 7) * 4;

    float4 av4[4], bv4[2];
    #pragma unroll
    for (int j = 0; j < 4; j++)
        av4[j] = *(const float4*)(g_hnall + (long)(tm*128 + j*32 + am)*512 + ak);
    #pragma unroll
    for (int j = 0; j < 2; j++) {
        int ng = tn*64 + j*32 + bn;
        bv4[j] = (ng < VV) ? *(const float4*)(W_fc + (long)ng*512 + bk)
                           : make_float4(0.f,0.f,0.f,0.f);
    }

    for (int kc = 0; kc < 512; kc += 32) {
        #pragma unroll
        for (int j = 0; j < 4; j++) {
            int m = j*32 + am;
            As[(ak+0)*132+m] = av4[j].x; As[(ak+1)*132+m] = av4[j].y;
            As[(ak+2)*132+m] = av4[j].z; As[(ak+3)*132+m] = av4[j].w;
        }
        #pragma unroll
        for (int j = 0; j < 2; j++) {
            int n = j*32 + bn;
            Bs[(bk+0)*68+n] = bv4[j].x; Bs[(bk+1)*68+n] = bv4[j].y;
            Bs[(bk+2)*68+n] = bv4[j].z; Bs[(bk+3)*68+n] = bv4[j].w;
        }
        __syncthreads();
        if (kc + 32 < 512) {
            #pragma unroll
            for (int j = 0; j < 4; j++)
                av4[j] = *(const float4*)(g_hnall + (long)(tm*128 + j*32 + am)*512 + kc + 32 + ak);
            #pragma unroll
            for (int j = 0; j < 2; j++) {
                int ng = tn*64 + j*32 + bn;
                bv4[j] = (ng < VV) ? *(const float4*)(W_fc + (long)ng*512 + kc + 32 + bk)
                                   : make_float4(0.f,0.f,0.f,0.f);
            }
        }
        #pragma unroll
        for (int k = 0; k < 32; k++) {
            float4 a0 = *(const float4*)&As[k*132 + m0];
            float4 a1 = *(const float4*)&As[k*132 + m0 + 4];
            float4 b0 = *(const float4*)&Bs[k*68 + n0];
            float avv[8] = {a0.x,a0.y,a0.z,a0.w,a1.x,a1.y,a1.z,a1.w};
            float bvv[4] = {b0.x,b0.y,b0.z,b0.w};
            #pragma unroll
            for (int i = 0; i < 8; i++)
                #pragma unroll
                for (int j = 0; j < 4; j++)
                    acc[i][j] = fmaf(avv[i], bvv[j], acc[i][j]);
        }
        __syncthreads();
    }
    #pragma unroll
    for (int i = 0; i < 8; i++) {
        int r = tm*128 + m0 + i;
        if (r < TT*BSZ) {
            int tt = r >> 5, bb = r & 31;
            bool act = tt < g_dlen[bb];
            long obase = OFF_PRED + ((long)bb*TT + tt)*VV;
            #pragma unroll
            for (int j = 0; j < 4; j++) {
                int col = tn*64 + n0 + j;
                if (col < VV) out[obase + col] = act ? (acc[i][j] + b_fc[col]) : 0.f;
            }
        }
    }
}

// ---------------- attention: inline dec_att + scores + softmax ----------------
__device__ void attn_task(int b, int t,
                          const float* __restrict__ W_dec, const float* __restrict__ b_dec,
                          const float* __restrict__ w_full, const float* __restrict__ b_full,
                          float* __restrict__ out, float* pool)
{
    float* hs    = pool;            // 512
    float* dec_s = pool + 512;      // 512
    float* wf    = pool + 1024;     // 512
    float* sc    = pool + 1536;     // 256
    float* red   = pool + 1792;     // 256
    const int tid = threadIdx.x;
    __syncthreads();
    for (int a = tid; a < 512; a += 256) {
        hs[a] = g_h[b*512 + a];
        wf[a] = w_full[a];
    }
    __syncthreads();
    #pragma unroll
    for (int rep = 0; rep < 2; rep++) {
        int a = tid + rep*256;
        const float* wr = W_dec + (long)a*512;
        float s = b_dec[a];
        #pragma unroll 8
        for (int k = 0; k < 512; k += 4) {
            float4 w = *(const float4*)(wr + k);
            s = fmaf(hs[k], w.x, s);
            s = fmaf(hs[k+1], w.y, s);
            s = fmaf(hs[k+2], w.z, s);
            s = fmaf(hs[k+3], w.w, s);
        }
        dec_s[a] = s;
    }
    __syncthreads();
    int wid = tid >> 5, lane = tid & 31;
    float bf = b_full[0];
    for (int p = wid; p < PP; p += 8) {
        const float* er = g_enc + ((long)b*PP + p)*512 + lane*16;
        const float* ds = dec_s + lane*16;
        const float* wl = wf + lane*16;
        float s = 0.f;
        #pragma unroll
        for (int q = 0; q < 4; q++) {
            float4 e = *(const float4*)(er + q*4);
            float4 d = *(const float4*)(ds + q*4);
            float4 w = *(const float4*)(wl + q*4);
            s = fmaf(fmaxf(e.x + d.x, 0.f), w.x, s);
            s = fmaf(fmaxf(e.y + d.y, 0.f), w.y, s);
            s = fmaf(fmaxf(e.z + d.z, 0.f), w.z, s);
            s = fmaf(fmaxf(e.w + d.w, 0.f), w.w, s);
        }
        #pragma unroll
        for (int off = 16; off > 0; off >>= 1) s += __shfl_xor_sync(0xffffffffu, s, off);
        if (lane == 0) sc[p] = s + bf;
    }
    __syncthreads();
    float v = (tid < PP) ? sc[tid] : -3.0e38f;
    red[tid] = v; __syncthreads();
    for (int s2 = 128; s2 > 0; s2 >>= 1) {
        if (tid < s2) red[tid] = fmaxf(red[tid], red[tid + s2]);
        __syncthreads();
    }
    float mx = red[0];
    __syncthreads();
    float ev = (tid < PP) ? expf(sc[tid] - mx) : 0.f;
    red[tid] = ev; __syncthreads();
    for (int s2 = 128; s2 > 0; s2 >>= 1) {
        if (tid < s2) red[tid] += red[tid + s2];
        __syncthreads();
    }
    float inv = 1.f / red[0];
    if (tid < PP) {
        float al = ev * inv;
        g_alpha[b*PP + tid] = al;
        out[OFF_ALPHA + ((long)b*TT + t)*PP + tid] = al;
    }
}

// ---------------- main persistent kernel ----------------
__global__ void __launch_bounds__(256, 2)
persist(const float* __restrict__ img, const int* __restrict__ toks, const int* __restrict__ lens,
        const float* __restrict__ W_enc, const float* __restrict__ b_enc,
        const float* __restrict__ W_dec, const float* __restrict__ b_dec,
        const float* __restrict__ w_full, const float* __restrict__ b_full,
        const float* __restrict__ emb,
        const float* __restrict__ W_ih, const float* __restrict__ b_ih,
        const float* __restrict__ W_hh, const float* __restrict__ b_hh,
        const float* __restrict__ W_h0, const float* __restrict__ b_h0,
        const float* __restrict__ W_c0, const float* __restrict__ b_c0,
        const float* __restrict__ W_beta, const float* __restrict__ b_beta,
        const float* __restrict__ W_fc, const float* __restrict__ b_fc,
        float* __restrict__ out)
{
    __shared__ __align__(16) float pool[9700];
    const int bid = blockIdx.x;
    const int tid = threadIdx.x;

    // ---- P0 ----
    if (bid == 0) {
        if (tid < BSZ) {
            int li = lens[tid];
            int r = 0;
            for (int j = 0; j < BSZ; j++) {
                int lj = lens[j];
                if (lj > li || (lj == li && j < tid)) r++;
            }
            g_sort[r] = tid;
        }
        __syncthreads();
        if (tid < BSZ) {
            int si = g_sort[tid];
            int dl = lens[si] - 1;
            g_dlen[tid] = dl;
            out[OFF_DLEN + tid] = (float)dl;
            out[OFF_SORT + tid] = (float)si;
        }
        __syncthreads();
        if (tid < TT) {
            int a = 0;
            for (int j = 0; j < BSZ; j++) a += (g_dlen[j] > tid) ? 1 : 0;
            g_act[tid] = a;
        }
        for (int idx = tid; idx < BSZ*LL; idx += 256) {
            int b = idx / LL, l = idx - b*LL;
            int tk = toks[g_sort[b]*LL + l];
            g_toks[idx] = tk;
            out[OFF_TOKS + idx] = (float)tk;
        }
    } else if (bid == 1) {
        for (int i = tid; i < 2048; i += 256) g_bcomb[i] = b_ih[i] + b_hh[i];
    } else if (bid == 2) {
        for (int i = tid; i < 32*512; i += 256) g_hnall[1632L*512 + i] = 0.f;
    }
    gridbar();

    // ---- P1: enc_att (392) | embg (408) | mean (32) ----
    for (int task = bid; task < 832; task += GRID) {
        if (task < 392) {
            enc_task(task >> 3, task & 7, img, W_enc, b_enc, pool);
        } else if (task < 800) {
            int id = task - 392;
            int tt = id >> 3, nt = id & 7;
            gemm32(emb, 512, g_toks + tt, LL, W_ih, 2560, 0,
                   2048, nt*256, 0, 512, g_embg + (long)tt*65536, 2048, pool);
        } else {
            int b = task - 800;
            __syncthreads();
            long srow = (long)g_sort[b] * PP * ENCD;
            int e0 = tid * 8;
            float a[8] = {0,0,0,0,0,0,0,0};
            #pragma unroll 4
            for (int p = 0; p < PP; p++) {
                const float* r = img + srow + (long)p*ENCD + e0;
                float4 v0 = *(const float4*)r;
                float4 v1 = *(const float4*)(r + 4);
                a[0]+=v0.x; a[1]+=v0.y; a[2]+=v0.z; a[3]+=v0.w;
                a[4]+=v1.x; a[5]+=v1.y; a[6]+=v1.z; a[7]+=v1.w;
            }
            #pragma unroll
            for (int i = 0; i < 8; i++)
                g_mean[b*2048 + e0 + i] = a[i] * (1.f/196.f);
        }
    }
    gridbar();

    // ---- P2: h0/c0 partials ----
    for (int task = bid; task < 32; task += GRID) {
        int half = task >> 4, nt = (task >> 3) & 1, sk = task & 7;
        gemm32(g_mean, 2048, (const int*)0, 0, half ? W_c0 : W_h0, 2048, 0,
               512, nt*256, sk*256, 256, g_pIH + (long)(half*8 + sk)*16384, 512, pool);
    }
    gridbar();

    // ---- P3: reduce h0/c0 ----
    for (int task = bid; task < 32; task += GRID) {
        int b = task;
        for (int j = tid; j < 512; j += 256) {
            float s = b_h0[j], s2 = b_c0[j];
            #pragma unroll
            for (int s8 = 0; s8 < 8; s8++) {
                s  += g_pIH[s8*16384 + b*512 + j];
                s2 += g_pIH[(8+s8)*16384 + b*512 + j];
            }
            g_h[b*512 + j] = s;
            g_c[b*512 + j] = s2;
        }
    }
    gridbar();

    // ---- decode loop: 4 phases/step ----
    for (int t = 0; t < TT; t++) {
        const int A = g_act[t];

        // PhA: attn(32, inline dec) | hh SK8(64) | beta SK8(64) = 160
        for (int task = bid; task < 160; task += GRID) {
            if (task < 32) {
                int b = task;
                if (b < A) {
                    attn_task(b, t, W_dec, b_dec, w_full, b_full, out, pool);
                } else if (tid < PP) {
                    out[OFF_ALPHA + ((long)b*TT + t)*PP + tid] = 0.f;
                }
            } else if (task < 96) {
                int rid = task - 32, nt = rid >> 3, sk = rid & 7;
                gemm32(g_h, 512, (const int*)0, 0, W_hh, 512, 0,
                       2048, nt*256, sk*64, 64, g_pHH + (long)sk*65536, 2048, pool);
            } else {
                int rid = task - 96, nt = rid >> 3, sk = rid & 7;
                gemm32(g_h, 512, (const int*)0, 0, W_beta, 512, 0,
                       2048, nt*256, sk*64, 64, g_pBeta + (long)sk*65536, 2048, pool);
            }
        }
        gridbar();

        // PhB: awe * sigm(beta) -> x2 (64 tasks: b x 1024-col halves), only active b
        for (int task = bid; task < 64; task += GRID) {
            int b = task >> 1, ch = task & 1;
            if (b >= A) continue;
            float* al = pool;
            __syncthreads();
            if (tid < PP) al[tid] = g_alpha[b*PP + tid];
            __syncthreads();
            int c0 = ch*1024 + tid*4;
            const float* base = img + ((long)(g_sort[b]*PP))*ENCD + c0;
            float4 s = make_float4(0.f,0.f,0.f,0.f);
            #pragma unroll 4
            for (int p = 0; p < PP; p++) {
                float4 v = *(const float4*)(base + (long)p*ENCD);
                float a = al[p];
                s.x = fmaf(a, v.x, s.x); s.y = fmaf(a, v.y, s.y);
                s.z = fmaf(a, v.z, s.z); s.w = fmaf(a, v.w, s.w);
            }
            // beta gate computed inline from partials
            float4 bt = *(const float4*)(b_beta + c0);
            #pragma unroll
            for (int sk = 0; sk < 8; sk++) {
                float4 p = *(const float4*)(g_pBeta + (long)sk*65536 + b*2048 + c0);
                bt.x+=p.x; bt.y+=p.y; bt.z+=p.z; bt.w+=p.w;
            }
            s.x *= sigm(bt.x); s.y *= sigm(bt.y); s.z *= sigm(bt.z); s.w *= sigm(bt.w);
            *(float4*)(g_x2 + b*2048 + c0) = s;
        }
        gridbar();

        // PhC: x2 @ W_ih[:,512:]^T (256 tasks: 8 ntiles x SK32 k64)
        for (int task = bid; task < 256; task += GRID) {
            int nt = task >> 5, sk = task & 31;
            gemm32(g_x2, 2048, (const int*)0, 0, W_ih, 2560, 512,
                   2048, nt*256, sk*64, 64, g_pIH + (long)sk*65536, 2048, pool);
        }
        gridbar();

        // PhD: LSTM with fully-inlined gate reduce (64 tasks), only active b
        for (int task = bid; task < 64; task += GRID) {
            int b = task >> 1, half = task & 1;
            if (b >= A) continue;
            int j = half*256 + tid;
            const float* eb = g_embg + (long)t*65536 + b*2048;
            float gi = g_bcomb[j]        + eb[j];
            float gf = g_bcomb[j + 512]  + eb[j + 512];
            float gg = g_bcomb[j + 1024] + eb[j + 1024];
            float go = g_bcomb[j + 1536] + eb[j + 1536];
            #pragma unroll
            for (int sk = 0; sk < 8; sk++) {
                const float* p = g_pHH + (long)sk*65536 + b*2048;
                gi += p[j]; gf += p[j + 512]; gg += p[j + 1024]; go += p[j + 1536];
            }
            #pragma unroll
            for (int sk = 0; sk < 32; sk++) {
                const float* p = g_pIH + (long)sk*65536 + b*2048;
                gi += p[j]; gf += p[j + 512]; gg += p[j + 1024]; go += p[j + 1536];
            }
            float c = g_c[b*512 + j];
            float cn = sigm(gf)*c + sigm(gi)*tanhf(gg);
            float hn = sigm(go)*tanhf(cn);
            g_hnall[((long)t*32 + b)*512 + j] = hn;
            g_c[b*512 + j] = cn;
            g_h[b*512 + j] = hn;
        }
        gridbar();
    }

    // ---- epilogue: preds = Hn_all @ W_fc^T + b_fc ----
    for (int task = bid; task < 13*157; task += GRID) {
        int tm = task / 157, tn = task - tm*157;
        fc_task(tm, tn, W_fc, b_fc, out, pool);
    }
}

// ---------------- host launcher ----------------
extern "C" void kernel_launch(void* const* d_in, const int* in_sizes, int n_in,
                              void* d_out, int out_size) {
    persist<<<GRID, 256>>>(
        (const float*)d_in[0],  (const int*)d_in[1],   (const int*)d_in[2],
        (const float*)d_in[3],  (const float*)d_in[4],
        (const float*)d_in[5],  (const float*)d_in[6],
        (const float*)d_in[7],  (const float*)d_in[8],
        (const float*)d_in[9],
        (const float*)d_in[10], (const float*)d_in[11],
        (const float*)d_in[12], (const float*)d_in[13],
        (const float*)d_in[14], (const float*)d_in[15],
        (const float*)d_in[16], (const float*)d_in[17],
        (const float*)d_in[18], (const float*)d_in[19],
        (const float*)d_in[20], (const float*)d_in[21],
        (float*)d_out);
    (void)in_sizes; (void)n_in; (void)out_size;
}

// round 11
// speedup vs baseline: 1.2626x; 1.2626x over previous
#include <cuda_runtime.h>
#include <math.h>

#define BSZ 32
#define PP 196
#define ENCD 2048
#define ATTD 512
#define DECD 512
#define VV 10000
#define LL 52
#define TT 51
#define GRID 296

#define OFF_PRED  0L
#define OFF_TOKS  ((long)BSZ*TT*VV)
#define OFF_DLEN  (OFF_TOKS + (long)BSZ*LL)
#define OFF_ALPHA (OFF_DLEN + (long)BSZ)
#define OFF_SORT  (OFF_ALPHA + (long)BSZ*TT*PP)

// ---------------- static device scratch ----------------
__device__ float g_enc[6272L*512];
__device__ float g_embg[51L*32*2048];
__device__ float g_pDec[8L*32*512];
__device__ float g_pHH[8L*32*2048];
__device__ float g_pBeta[8L*32*2048];
__device__ float g_pIH[32L*32*2048];
__device__ float g_mean[32*2048];
__device__ float g_h[32*512];
__device__ float g_c[32*512];
__device__ float g_hnall[1664L*512];
__device__ float g_gates[32*2048];
__device__ float g_betasig[32*2048];
__device__ float g_x2[32*2048];
__device__ float g_alpha[32*196];
__device__ float g_bcomb[2048];
__device__ int   g_sort[32];
__device__ int   g_dlen[32];
__device__ int   g_act[TT];
__device__ int   g_toks[32*LL];
__device__ unsigned g_sub[8*64];       // 8 sub-counters, 256B apart
__device__ unsigned g_root;
__device__ volatile unsigned g_bargen;

__device__ __forceinline__ float sigm(float x) { return 1.f / (1.f + expf(-x)); }

// ---------------- hierarchical grid barrier (8 parallel sub-counters) ----------------
__device__ __forceinline__ void gridbar() {
    __syncthreads();
    if (threadIdx.x == 0) {
        __threadfence();
        unsigned gen = g_bargen;
        int s = blockIdx.x & 7;        // 296 = 8 * 37 exactly
        if (atomicAdd(&g_sub[s*64], 1u) == 36) {
            g_sub[s*64] = 0;
            if (atomicAdd(&g_root, 1u) == 7) {
                g_root = 0;
                __threadfence();
                g_bargen = gen + 1;
            }
        }
        while (g_bargen == gen) { __nanosleep(150); }
        __threadfence();
    }
    __syncthreads();
}

// ---------------- 32-row GEMM partial tile, register-prefetch pipelined ----------------
__device__ void gemm32(const float* __restrict__ X, int ldx,
                       const int* __restrict__ gidx, int gstride,
                       const float* __restrict__ W, int ldw, int wcol0,
                       int Nfull, int nbase, int k0, int klen,
                       float* __restrict__ part, int Nld, float* pool)
{
    float* Xs = pool;                 // 32k x 36
    float* Ws = pool + 1184;          // 32k x 264
    int* roff = (int*)(pool + 1184 + 32*264);
    const int tid = threadIdx.x;
    __syncthreads();
    if (tid < 32) roff[tid] = (gidx ? gidx[tid * gstride] : tid) * ldx;
    __syncthreads();

    const int m0 = (tid >> 5) * 4;
    const int n0 = (tid & 31) * 8;
    const int xm = tid >> 3, xk = (tid & 7) * 4;
    const int wn = tid >> 3, wk = (tid & 7) * 4;

    float acc[4][8];
    #pragma unroll
    for (int i = 0; i < 4; i++)
        #pragma unroll
        for (int j = 0; j < 8; j++) acc[i][j] = 0.f;

    float4 xv = *(const float4*)(X + roff[xm] + k0 + xk);
    float4 wv[8];
    #pragma unroll
    for (int j = 0; j < 8; j++) {
        int ng = nbase + j*32 + wn;
        wv[j] = (ng < Nfull) ? *(const float4*)(W + (long)ng*ldw + wcol0 + k0 + wk)
                             : make_float4(0.f, 0.f, 0.f, 0.f);
    }

    for (int kk = 0; kk < klen; kk += 32) {
        Xs[(xk+0)*36 + xm] = xv.x; Xs[(xk+1)*36 + xm] = xv.y;
        Xs[(xk+2)*36 + xm] = xv.z; Xs[(xk+3)*36 + xm] = xv.w;
        #pragma unroll
        for (int j = 0; j < 8; j++) {
            int n = j*32 + wn;
            Ws[(wk+0)*264 + n] = wv[j].x; Ws[(wk+1)*264 + n] = wv[j].y;
            Ws[(wk+2)*264 + n] = wv[j].z; Ws[(wk+3)*264 + n] = wv[j].w;
        }
        __syncthreads();
        if (kk + 32 < klen) {
            int kc = k0 + kk + 32;
            xv = *(const float4*)(X + roff[xm] + kc + xk);
            #pragma unroll
            for (int j = 0; j < 8; j++) {
                int ng = nbase + j*32 + wn;
                wv[j] = (ng < Nfull) ? *(const float4*)(W + (long)ng*ldw + wcol0 + kc + wk)
                                     : make_float4(0.f, 0.f, 0.f, 0.f);
            }
        }
        #pragma unroll
        for (int k = 0; k < 32; k++) {
            float4 a = *(const float4*)&Xs[k*36 + m0];
            float av[4] = {a.x, a.y, a.z, a.w};
            float4 w0 = *(const float4*)&Ws[k*264 + n0];
            float4 w1 = *(const float4*)&Ws[k*264 + n0 + 4];
            float wvv[8] = {w0.x,w0.y,w0.z,w0.w,w1.x,w1.y,w1.z,w1.w};
            #pragma unroll
            for (int i = 0; i < 4; i++)
                #pragma unroll
                for (int j = 0; j < 8; j++)
                    acc[i][j] = fmaf(av[i], wvv[j], acc[i][j]);
        }
        __syncthreads();
    }
    #pragma unroll
    for (int i = 0; i < 4; i++)
        #pragma unroll
        for (int j = 0; j < 8; j++)
            part[(long)(m0+i)*Nld + nbase + n0 + j] = acc[i][j];
}

// ---------------- 128x64 dense tile, K=2048, pipelined: enc_att ----------------
__device__ void enc_task(int tm, int tn, const float* __restrict__ img,
                         const float* __restrict__ W_enc, const float* __restrict__ b_enc,
                         float* pool)
{
    float* As = pool;
    float* Bs = pool + 4224;
    int* rowb = (int*)(pool + 6400);
    const int tid = threadIdx.x;
    __syncthreads();
    if (tid < 128) {
        int rr = tm*128 + tid;
        int b = rr / PP, p = rr - b*PP;
        rowb[tid] = (g_sort[b]*PP + p) * ENCD;
    }
    __syncthreads();
    float acc[8][4];
    #pragma unroll
    for (int i = 0; i < 8; i++)
        #pragma unroll
        for (int j = 0; j < 4; j++) acc[i][j] = 0.f;
    const int ty = tid >> 4, tx = tid & 15;
    const int m0 = ty*8, n0 = tx*4;
    const int am = tid >> 3, ak = (tid & 7) * 4;
    const int bn = tid >> 3, bk = (tid & 7) * 4;

    float4 av4[4], bv4[2];
    #pragma unroll
    for (int j = 0; j < 4; j++)
        av4[j] = *(const float4*)(img + rowb[j*32 + am] + ak);
    #pragma unroll
    for (int j = 0; j < 2; j++)
        bv4[j] = *(const float4*)(W_enc + (long)(tn*64 + j*32 + bn)*ENCD + bk);

    for (int kc = 0; kc < ENCD; kc += 32) {
        #pragma unroll
        for (int j = 0; j < 4; j++) {
            int m = j*32 + am;
            As[(ak+0)*132+m] = av4[j].x; As[(ak+1)*132+m] = av4[j].y;
            As[(ak+2)*132+m] = av4[j].z; As[(ak+3)*132+m] = av4[j].w;
        }
        #pragma unroll
        for (int j = 0; j < 2; j++) {
            int n = j*32 + bn;
            Bs[(bk+0)*68+n] = bv4[j].x; Bs[(bk+1)*68+n] = bv4[j].y;
            Bs[(bk+2)*68+n] = bv4[j].z; Bs[(bk+3)*68+n] = bv4[j].w;
        }
        __syncthreads();
        if (kc + 32 < ENCD) {
            #pragma unroll
            for (int j = 0; j < 4; j++)
                av4[j] = *(const float4*)(img + rowb[j*32 + am] + kc + 32 + ak);
            #pragma unroll
            for (int j = 0; j < 2; j++)
                bv4[j] = *(const float4*)(W_enc + (long)(tn*64 + j*32 + bn)*ENCD + kc + 32 + bk);
        }
        #pragma unroll
        for (int k = 0; k < 32; k++) {
            float4 a0 = *(const float4*)&As[k*132 + m0];
            float4 a1 = *(const float4*)&As[k*132 + m0 + 4];
            float4 b0 = *(const float4*)&Bs[k*68 + n0];
            float avv[8] = {a0.x,a0.y,a0.z,a0.w,a1.x,a1.y,a1.z,a1.w};
            float bvv[4] = {b0.x,b0.y,b0.z,b0.w};
            #pragma unroll
            for (int i = 0; i < 8; i++)
                #pragma unroll
                for (int j = 0; j < 4; j++)
                    acc[i][j] = fmaf(avv[i], bvv[j], acc[i][j]);
        }
        __syncthreads();
    }
    #pragma unroll
    for (int i = 0; i < 8; i++) {
        int row = tm*128 + m0 + i;
        #pragma unroll
        for (int j = 0; j < 4; j++) {
            int col = tn*64 + n0 + j;
            g_enc[(long)row*512 + col] = acc[i][j] + b_enc[col];
        }
    }
}

// ---------------- 128x64 dense tile, K=512, pipelined: final FC ----------------
__device__ void fc_task(int tm, int tn,
                        const float* __restrict__ W_fc, const float* __restrict__ b_fc,
                        float* __restrict__ out, float* pool)
{
    float* As = pool;
    float* Bs = pool + 4224;
    const int tid = threadIdx.x;
    __syncthreads();
    float acc[8][4];
    #pragma unroll
    for (int i = 0; i < 8; i++)
        #pragma unroll
        for (int j = 0; j < 4; j++) acc[i][j] = 0.f;
    const int ty = tid >> 4, tx = tid & 15;
    const int m0 = ty*8, n0 = tx*4;
    const int am = tid >> 3, ak = (tid & 7) * 4;
    const int bn = tid >> 3, bk = (tid & 7) * 4;

    float4 av4[4], bv4[2];
    #pragma unroll
    for (int j = 0; j < 4; j++)
        av4[j] = *(const float4*)(g_hnall + (long)(tm*128 + j*32 + am)*512 + ak);
    #pragma unroll
    for (int j = 0; j < 2; j++) {
        int ng = tn*64 + j*32 + bn;
        bv4[j] = (ng < VV) ? *(const float4*)(W_fc + (long)ng*512 + bk)
                           : make_float4(0.f,0.f,0.f,0.f);
    }

    for (int kc = 0; kc < 512; kc += 32) {
        #pragma unroll
        for (int j = 0; j < 4; j++) {
            int m = j*32 + am;
            As[(ak+0)*132+m] = av4[j].x; As[(ak+1)*132+m] = av4[j].y;
            As[(ak+2)*132+m] = av4[j].z; As[(ak+3)*132+m] = av4[j].w;
        }
        #pragma unroll
        for (int j = 0; j < 2; j++) {
            int n = j*32 + bn;
            Bs[(bk+0)*68+n] = bv4[j].x; Bs[(bk+1)*68+n] = bv4[j].y;
            Bs[(bk+2)*68+n] = bv4[j].z; Bs[(bk+3)*68+n] = bv4[j].w;
        }
        __syncthreads();
        if (kc + 32 < 512) {
            #pragma unroll
            for (int j = 0; j < 4; j++)
                av4[j] = *(const float4*)(g_hnall + (long)(tm*128 + j*32 + am)*512 + kc + 32 + ak);
            #pragma unroll
            for (int j = 0; j < 2; j++) {
                int ng = tn*64 + j*32 + bn;
                bv4[j] = (ng < VV) ? *(const float4*)(W_fc + (long)ng*512 + kc + 32 + bk)
                                   : make_float4(0.f,0.f,0.f,0.f);
            }
        }
        #pragma unroll
        for (int k = 0; k < 32; k++) {
            float4 a0 = *(const float4*)&As[k*132 + m0];
            float4 a1 = *(const float4*)&As[k*132 + m0 + 4];
            float4 b0 = *(const float4*)&Bs[k*68 + n0];
            float avv[8] = {a0.x,a0.y,a0.z,a0.w,a1.x,a1.y,a1.z,a1.w};
            float bvv[4] = {b0.x,b0.y,b0.z,b0.w};
            #pragma unroll
            for (int i = 0; i < 8; i++)
                #pragma unroll
                for (int j = 0; j < 4; j++)
                    acc[i][j] = fmaf(avv[i], bvv[j], acc[i][j]);
        }
        __syncthreads();
    }
    #pragma unroll
    for (int i = 0; i < 8; i++) {
        int r = tm*128 + m0 + i;
        if (r < TT*BSZ) {
            int tt = r >> 5, bb = r & 31;
            bool act = tt < g_dlen[bb];
            long obase = OFF_PRED + ((long)bb*TT + tt)*VV;
            #pragma unroll
            for (int j = 0; j < 4; j++) {
                int col = tn*64 + n0 + j;
                if (col < VV) out[obase + col] = act ? (acc[i][j] + b_fc[col]) : 0.f;
            }
        }
    }
}

// ---------------- attention: reduce pDec + scores + softmax ----------------
__device__ void attn_task(int b, int t, const float* __restrict__ b_dec,
                          const float* __restrict__ w_full, const float* __restrict__ b_full,
                          float* __restrict__ out, float* pool)
{
    float* dec_s = pool;
    float* wf    = pool + 512;
    float* sc    = pool + 1024;
    float* red   = pool + 1280;
    const int tid = threadIdx.x;
    __syncthreads();
    for (int a = tid; a < 512; a += 256) {
        float s = b_dec[a];
        #pragma unroll
        for (int sk = 0; sk < 8; sk++) s += g_pDec[sk*16384 + b*512 + a];
        dec_s[a] = s;
        wf[a] = w_full[a];
    }
    __syncthreads();
    int wid = tid >> 5, lane = tid & 31;
    float bf = b_full[0];
    for (int p = wid; p < PP; p += 8) {
        const float* er = g_enc + ((long)b*PP + p)*512 + lane*16;
        const float* ds = dec_s + lane*16;
        const float* wl = wf + lane*16;
        float s = 0.f;
        #pragma unroll
        for (int q = 0; q < 4; q++) {
            float4 e = *(const float4*)(er + q*4);
            float4 d = *(const float4*)(ds + q*4);
            float4 w = *(const float4*)(wl + q*4);
            s = fmaf(fmaxf(e.x + d.x, 0.f), w.x, s);
            s = fmaf(fmaxf(e.y + d.y, 0.f), w.y, s);
            s = fmaf(fmaxf(e.z + d.z, 0.f), w.z, s);
            s = fmaf(fmaxf(e.w + d.w, 0.f), w.w, s);
        }
        #pragma unroll
        for (int off = 16; off > 0; off >>= 1) s += __shfl_xor_sync(0xffffffffu, s, off);
        if (lane == 0) sc[p] = s + bf;
    }
    __syncthreads();
    float v = (tid < PP) ? sc[tid] : -3.0e38f;
    red[tid] = v; __syncthreads();
    for (int s2 = 128; s2 > 0; s2 >>= 1) {
        if (tid < s2) red[tid] = fmaxf(red[tid], red[tid + s2]);
        __syncthreads();
    }
    float mx = red[0];
    __syncthreads();
    float ev = (tid < PP) ? expf(sc[tid] - mx) : 0.f;
    red[tid] = ev; __syncthreads();
    for (int s2 = 128; s2 > 0; s2 >>= 1) {
        if (tid < s2) red[tid] += red[tid + s2];
        __syncthreads();
    }
    float inv = 1.f / red[0];
    if (tid < PP) {
        float al = ev * inv;
        g_alpha[b*PP + tid] = al;
        out[OFF_ALPHA + ((long)b*TT + t)*PP + tid] = al;
    }
}

// ---------------- main persistent kernel ----------------
__global__ void __launch_bounds__(256, 2)
persist(const float* __restrict__ img, const int* __restrict__ toks, const int* __restrict__ lens,
        const float* __restrict__ W_enc, const float* __restrict__ b_enc,
        const float* __restrict__ W_dec, const float* __restrict__ b_dec,
        const float* __restrict__ w_full, const float* __restrict__ b_full,
        const float* __restrict__ emb,
        const float* __restrict__ W_ih, const float* __restrict__ b_ih,
        const float* __restrict__ W_hh, const float* __restrict__ b_hh,
        const float* __restrict__ W_h0, const float* __restrict__ b_h0,
        const float* __restrict__ W_c0, const float* __restrict__ b_c0,
        const float* __restrict__ W_beta, const float* __restrict__ b_beta,
        const float* __restrict__ W_fc, const float* __restrict__ b_fc,
        float* __restrict__ out)
{
    __shared__ __align__(16) float pool[9700];
    const int bid = blockIdx.x;
    const int tid = threadIdx.x;

    // ---- P0 ----
    if (bid == 0) {
        if (tid < BSZ) {
            int li = lens[tid];
            int r = 0;
            for (int j = 0; j < BSZ; j++) {
                int lj = lens[j];
                if (lj > li || (lj == li && j < tid)) r++;
            }
            g_sort[r] = tid;
        }
        __syncthreads();
        if (tid < BSZ) {
            int si = g_sort[tid];
            int dl = lens[si] - 1;
            g_dlen[tid] = dl;
            out[OFF_DLEN + tid] = (float)dl;
            out[OFF_SORT + tid] = (float)si;
        }
        __syncthreads();
        if (tid < TT) {
            int a = 0;
            for (int j = 0; j < BSZ; j++) a += (g_dlen[j] > tid) ? 1 : 0;
            g_act[tid] = a;
        }
        for (int idx = tid; idx < BSZ*LL; idx += 256) {
            int b = idx / LL, l = idx - b*LL;
            int tk = toks[g_sort[b]*LL + l];
            g_toks[idx] = tk;
            out[OFF_TOKS + idx] = (float)tk;
        }
    } else if (bid == 1) {
        for (int i = tid; i < 2048; i += 256) g_bcomb[i] = b_ih[i] + b_hh[i];
    } else if (bid == 2) {
        for (int i = tid; i < 32*512; i += 256) g_hnall[1632L*512 + i] = 0.f;
    }
    gridbar();

    // ---- P1: enc_att (392) | embg (408) | mean (32) ----
    for (int task = bid; task < 832; task += GRID) {
        if (task < 392) {
            enc_task(task >> 3, task & 7, img, W_enc, b_enc, pool);
        } else if (task < 800) {
            int id = task - 392;
            int tt = id >> 3, nt = id & 7;
            gemm32(emb, 512, g_toks + tt, LL, W_ih, 2560, 0,
                   2048, nt*256, 0, 512, g_embg + (long)tt*65536, 2048, pool);
        } else {
            int b = task - 800;
            __syncthreads();
            long srow = (long)g_sort[b] * PP * ENCD;
            int e0 = tid * 8;
            float a[8] = {0,0,0,0,0,0,0,0};
            #pragma unroll 4
            for (int p = 0; p < PP; p++) {
                const float* r = img + srow + (long)p*ENCD + e0;
                float4 v0 = *(const float4*)r;
                float4 v1 = *(const float4*)(r + 4);
                a[0]+=v0.x; a[1]+=v0.y; a[2]+=v0.z; a[3]+=v0.w;
                a[4]+=v1.x; a[5]+=v1.y; a[6]+=v1.z; a[7]+=v1.w;
            }
            #pragma unroll
            for (int i = 0; i < 8; i++)
                g_mean[b*2048 + e0 + i] = a[i] * (1.f/196.f);
        }
    }
    gridbar();

    // ---- P2: h0/c0 partials ----
    for (int task = bid; task < 32; task += GRID) {
        int half = task >> 4, nt = (task >> 3) & 1, sk = task & 7;
        gemm32(g_mean, 2048, (const int*)0, 0, half ? W_c0 : W_h0, 2048, 0,
               512, nt*256, sk*256, 256, g_pIH + (long)(half*8 + sk)*16384, 512, pool);
    }
    gridbar();

    // ---- P3: reduce h0/c0 ----
    for (int task = bid; task < 32; task += GRID) {
        int b = task;
        for (int j = tid; j < 512; j += 256) {
            float s = b_h0[j], s2 = b_c0[j];
            #pragma unroll
            for (int s8 = 0; s8 < 8; s8++) {
                s  += g_pIH[s8*16384 + b*512 + j];
                s2 += g_pIH[(8+s8)*16384 + b*512 + j];
            }
            g_h[b*512 + j] = s;
            g_c[b*512 + j] = s2;
        }
    }
    gridbar();

    // ---- decode loop (R9 structure: 5 phases, active-prefix skipping) ----
    for (int t = 0; t < TT; t++) {
        const int A = g_act[t];

        // Ph1: dec(16) | hh(64) | beta(64)
        for (int task = bid; task < 144; task += GRID) {
            if (task < 16) {
                int nt = task >> 3, sk = task & 7;
                gemm32(g_h, 512, (const int*)0, 0, W_dec, 512, 0,
                       512, nt*256, sk*64, 64, g_pDec + (long)sk*16384, 512, pool);
            } else if (task < 80) {
                int rid = task - 16, nt = rid >> 3, sk = rid & 7;
                gemm32(g_h, 512, (const int*)0, 0, W_hh, 512, 0,
                       2048, nt*256, sk*64, 64, g_pHH + (long)sk*65536, 2048, pool);
            } else {
                int rid = task - 80, nt = rid >> 3, sk = rid & 7;
                gemm32(g_h, 512, (const int*)0, 0, W_beta, 512, 0,
                       2048, nt*256, sk*64, 64, g_pBeta + (long)sk*65536, 2048, pool);
            }
        }
        gridbar();

        // Ph2: attn(32) | gates-base(32) | beta-sigmoid(64)
        for (int task = bid; task < 128; task += GRID) {
            if (task < 32) {
                int b = task;
                if (b < A) {
                    attn_task(b, t, b_dec, w_full, b_full, out, pool);
                } else if (tid < PP) {
                    out[OFF_ALPHA + ((long)b*TT + t)*PP + tid] = 0.f;
                }
            } else if (task < 64) {
                int b = task - 32;
                if (b >= A) continue;
                int c0 = tid * 8;
                float4 s0 = *(const float4*)(g_bcomb + c0);
                float4 s1 = *(const float4*)(g_bcomb + c0 + 4);
                float4 e0 = *(const float4*)(g_embg + (long)t*65536 + b*2048 + c0);
                float4 e1 = *(const float4*)(g_embg + (long)t*65536 + b*2048 + c0 + 4);
                s0.x+=e0.x; s0.y+=e0.y; s0.z+=e0.z; s0.w+=e0.w;
                s1.x+=e1.x; s1.y+=e1.y; s1.z+=e1.z; s1.w+=e1.w;
                #pragma unroll
                for (int sk = 0; sk < 8; sk++) {
                    float4 p0 = *(const float4*)(g_pHH + (long)sk*65536 + b*2048 + c0);
                    float4 p1 = *(const float4*)(g_pHH + (long)sk*65536 + b*2048 + c0 + 4);
                    s0.x+=p0.x; s0.y+=p0.y; s0.z+=p0.z; s0.w+=p0.w;
                    s1.x+=p1.x; s1.y+=p1.y; s1.z+=p1.z; s1.w+=p1.w;
                }
                *(float4*)(g_gates + b*2048 + c0) = s0;
                *(float4*)(g_gates + b*2048 + c0 + 4) = s1;
            } else {
                int rid = task - 64;
                int b = rid >> 1, half = rid & 1;
                if (b >= A) continue;
                int c0 = half*1024 + tid*4;
                float4 s = *(const float4*)(b_beta + c0);
                #pragma unroll
                for (int sk = 0; sk < 8; sk++) {
                    float4 p = *(const float4*)(g_pBeta + (long)sk*65536 + b*2048 + c0);
                    s.x+=p.x; s.y+=p.y; s.z+=p.z; s.w+=p.w;
                }
                float4 o;
                o.x = sigm(s.x); o.y = sigm(s.y); o.z = sigm(s.z); o.w = sigm(s.w);
                *(float4*)(g_betasig + b*2048 + c0) = o;
            }
        }
        gridbar();

        // Ph3: awe * gate -> x2 (64 tasks), only active b
        for (int task = bid; task < 64; task += GRID) {
            int b = task >> 1, ch = task & 1;
            if (b >= A) continue;
            float* al = pool;
            __syncthreads();
            if (tid < PP) al[tid] = g_alpha[b*PP + tid];
            __syncthreads();
            int c0 = ch*1024 + tid*4;
            const float* base = img + ((long)(g_sort[b]*PP))*ENCD + c0;
            float4 s = make_float4(0.f,0.f,0.f,0.f);
            #pragma unroll 4
            for (int p = 0; p < PP; p++) {
                float4 v = *(const float4*)(base + (long)p*ENCD);
                float a = al[p];
                s.x = fmaf(a, v.x, s.x); s.y = fmaf(a, v.y, s.y);
                s.z = fmaf(a, v.z, s.z); s.w = fmaf(a, v.w, s.w);
            }
            float4 g = *(const float4*)(g_betasig + b*2048 + c0);
            s.x *= g.x; s.y *= g.y; s.z *= g.z; s.w *= g.w;
            *(float4*)(g_x2 + b*2048 + c0) = s;
        }
        gridbar();

        // Ph4: x2 @ W_ih[:,512:]^T (256 tasks: 8 ntiles x SK32 k64)
        for (int task = bid; task < 256; task += GRID) {
            int nt = task >> 5, sk = task & 31;
            gemm32(g_x2, 2048, (const int*)0, 0, W_ih, 2560, 512,
                   2048, nt*256, sk*64, 64, g_pIH + (long)sk*65536, 2048, pool);
        }
        gridbar();

        // Ph5: gate reduce + LSTM pointwise (64 tasks), only active b
        for (int task = bid; task < 64; task += GRID) {
            int b = task >> 1, half = task & 1;
            if (b >= A) continue;
            int j = half*256 + tid;
            float gi = g_gates[b*2048 + j];
            float gf = g_gates[b*2048 + j + 512];
            float gg = g_gates[b*2048 + j + 1024];
            float go = g_gates[b*2048 + j + 1536];
            #pragma unroll
            for (int sk = 0; sk < 32; sk++) {
                const float* p = g_pIH + (long)sk*65536 + b*2048;
                gi += p[j]; gf += p[j + 512]; gg += p[j + 1024]; go += p[j + 1536];
            }
            float c = g_c[b*512 + j];
            float cn = sigm(gf)*c + sigm(gi)*tanhf(gg);
            float hn = sigm(go)*tanhf(cn);
            g_hnall[((long)t*32 + b)*512 + j] = hn;
            g_c[b*512 + j] = cn;
            g_h[b*512 + j] = hn;
        }
        gridbar();
    }

    // ---- epilogue: preds = Hn_all @ W_fc^T + b_fc ----
    for (int task = bid; task < 13*157; task += GRID) {
        int tm = task / 157, tn = task - tm*157;
        fc_task(tm, tn, W_fc, b_fc, out, pool);
    }
}

// ---------------- host launcher ----------------
extern "C" void kernel_launch(void* const* d_in, const int* in_sizes, int n_in,
                              void* d_out, int out_size) {
    persist<<<GRID, 256>>>(
        (const float*)d_in[0],  (const int*)d_in[1],   (const int*)d_in[2],
        (const float*)d_in[3],  (const float*)d_in[4],
        (const float*)d_in[5],  (const float*)d_in[6],
        (const float*)d_in[7],  (const float*)d_in[8],
        (const float*)d_in[9],
        (const float*)d_in[10], (const float*)d_in[11],
        (const float*)d_in[12], (const float*)d_in[13],
        (const float*)d_in[14], (const float*)d_in[15],
        (const float*)d_in[16], (const float*)d_in[17],
        (const float*)d_in[18], (const float*)d_in[19],
        (const float*)d_in[20], (const float*)d_in[21],
        (float*)d_out);
    (void)in_sizes; (void)n_in; (void)out_size;
}

// round 12
// speedup vs baseline: 1.4907x; 1.1806x over previous
#include <cuda_runtime.h>
#include <math.h>

#define BSZ 32
#define PP 196
#define ENCD 2048
#define ATTD 512
#define DECD 512
#define VV 10000
#define LL 52
#define TT 51
#define GRID 296

#define OFF_PRED  0L
#define OFF_TOKS  ((long)BSZ*TT*VV)
#define OFF_DLEN  (OFF_TOKS + (long)BSZ*LL)
#define OFF_ALPHA (OFF_DLEN + (long)BSZ)
#define OFF_SORT  (OFF_ALPHA + (long)BSZ*TT*PP)

// ---------------- static device scratch ----------------
__device__ float g_enc[6272L*512];
__device__ float g_embg[51L*32*2048];
__device__ float g_pDec[16L*32*512];
__device__ float g_pHH[16L*32*2048];
__device__ float g_pBeta[16L*32*2048];
__device__ float g_pIH[32L*32*2048];
__device__ float g_mean[32*2048];
__device__ float g_h[32*512];
__device__ float g_c[32*512];
__device__ float g_hnall[1664L*512];
__device__ float g_gates[32*2048];
__device__ float g_betasig[32*2048];
__device__ float g_x2[32*2048];
__device__ float g_alpha[32*196];
__device__ float g_bcomb[2048];
__device__ int   g_sort[32];
__device__ int   g_dlen[32];
__device__ int   g_act[TT];
__device__ int   g_toks[32*LL];
__device__ unsigned g_barcnt;
__device__ volatile unsigned g_bargen;

__device__ __forceinline__ float sigm(float x) { return 1.f / (1.f + expf(-x)); }

// ---------------- grid-wide software barrier (R9-proven) ----------------
__device__ __forceinline__ void gridbar() {
    __syncthreads();
    if (threadIdx.x == 0) {
        __threadfence();
        unsigned gen = g_bargen;
        if (atomicAdd(&g_barcnt, 1u) == GRID - 1) {
            g_barcnt = 0;
            __threadfence();
            g_bargen = gen + 1;
        } else {
            while (g_bargen == gen) { __nanosleep(150); }
        }
        __threadfence();
    }
    __syncthreads();
}

// ---------------- 32-row GEMM partial tile, conflict-free column mapping ----------------
// Each lane accumulates columns {nbase + 4L .. +3} and {nbase + 128 + 4L .. +3}
__device__ void gemm32(const float* __restrict__ X, int ldx,
                       const int* __restrict__ gidx, int gstride,
                       const float* __restrict__ W, int ldw, int wcol0,
                       int Nfull, int nbase, int k0, int klen,
                       float* __restrict__ part, int Nld, float* pool)
{
    float* Xs = pool;                 // 32k x 36
    float* Ws = pool + 1184;          // 32k x 264
    int* roff = (int*)(pool + 1184 + 32*264);
    const int tid = threadIdx.x;
    __syncthreads();
    if (tid < 32) roff[tid] = (gidx ? gidx[tid * gstride] : tid) * ldx;
    __syncthreads();

    const int m0 = (tid >> 5) * 4;
    const int lane4 = (tid & 31) * 4;       // conflict-free column base
    const int xm = tid >> 3, xk = (tid & 7) * 4;
    const int wn = tid >> 3, wk = (tid & 7) * 4;

    float acc[4][8];
    #pragma unroll
    for (int i = 0; i < 4; i++)
        #pragma unroll
        for (int j = 0; j < 8; j++) acc[i][j] = 0.f;

    float4 xv = *(const float4*)(X + roff[xm] + k0 + xk);
    float4 wv[8];
    #pragma unroll
    for (int j = 0; j < 8; j++) {
        int ng = nbase + j*32 + wn;
        wv[j] = (ng < Nfull) ? *(const float4*)(W + (long)ng*ldw + wcol0 + k0 + wk)
                             : make_float4(0.f, 0.f, 0.f, 0.f);
    }

    for (int kk = 0; kk < klen; kk += 32) {
        Xs[(xk+0)*36 + xm] = xv.x; Xs[(xk+1)*36 + xm] = xv.y;
        Xs[(xk+2)*36 + xm] = xv.z; Xs[(xk+3)*36 + xm] = xv.w;
        #pragma unroll
        for (int j = 0; j < 8; j++) {
            int n = j*32 + wn;
            Ws[(wk+0)*264 + n] = wv[j].x; Ws[(wk+1)*264 + n] = wv[j].y;
            Ws[(wk+2)*264 + n] = wv[j].z; Ws[(wk+3)*264 + n] = wv[j].w;
        }
        __syncthreads();
        if (kk + 32 < klen) {
            int kc = k0 + kk + 32;
            xv = *(const float4*)(X + roff[xm] + kc + xk);
            #pragma unroll
            for (int j = 0; j < 8; j++) {
                int ng = nbase + j*32 + wn;
                wv[j] = (ng < Nfull) ? *(const float4*)(W + (long)ng*ldw + wcol0 + kc + wk)
                                     : make_float4(0.f, 0.f, 0.f, 0.f);
            }
        }
        #pragma unroll
        for (int k = 0; k < 32; k++) {
            float4 a = *(const float4*)&Xs[k*36 + m0];
            float av[4] = {a.x, a.y, a.z, a.w};
            float4 w0 = *(const float4*)&Ws[k*264 + lane4];          // banks 4L: 4-phase optimal
            float4 w1 = *(const float4*)&Ws[k*264 + 128 + lane4];
            float wvv[8] = {w0.x,w0.y,w0.z,w0.w,w1.x,w1.y,w1.z,w1.w};
            #pragma unroll
            for (int i = 0; i < 4; i++)
                #pragma unroll
                for (int j = 0; j < 8; j++)
                    acc[i][j] = fmaf(av[i], wvv[j], acc[i][j]);
        }
        __syncthreads();
    }
    // two float4 stores per row (columns 4L.. and 128+4L..)
    #pragma unroll
    for (int i = 0; i < 4; i++) {
        float4 o0 = make_float4(acc[i][0], acc[i][1], acc[i][2], acc[i][3]);
        float4 o1 = make_float4(acc[i][4], acc[i][5], acc[i][6], acc[i][7]);
        *(float4*)&part[(long)(m0+i)*Nld + nbase + lane4]       = o0;
        *(float4*)&part[(long)(m0+i)*Nld + nbase + 128 + lane4] = o1;
    }
}

// ---------------- 128x64 dense tile, K=2048, pipelined: enc_att ----------------
__device__ void enc_task(int tm, int tn, const float* __restrict__ img,
                         const float* __restrict__ W_enc, const float* __restrict__ b_enc,
                         float* pool)
{
    float* As = pool;
    float* Bs = pool + 4224;
    int* rowb = (int*)(pool + 6400);
    const int tid = threadIdx.x;
    __syncthreads();
    if (tid < 128) {
        int rr = tm*128 + tid;
        int b = rr / PP, p = rr - b*PP;
        rowb[tid] = (g_sort[b]*PP + p) * ENCD;
    }
    __syncthreads();
    float acc[8][4];
    #pragma unroll
    for (int i = 0; i < 8; i++)
        #pragma unroll
        for (int j = 0; j < 4; j++) acc[i][j] = 0.f;
    const int ty = tid >> 4, tx = tid & 15;
    const int m0 = ty*8, n0 = tx*4;
    const int am = tid >> 3, ak = (tid & 7) * 4;
    const int bn = tid >> 3, bk = (tid & 7) * 4;

    float4 av4[4], bv4[2];
    #pragma unroll
    for (int j = 0; j < 4; j++)
        av4[j] = *(const float4*)(img + rowb[j*32 + am] + ak);
    #pragma unroll
    for (int j = 0; j < 2; j++)
        bv4[j] = *(const float4*)(W_enc + (long)(tn*64 + j*32 + bn)*ENCD + bk);

    for (int kc = 0; kc < ENCD; kc += 32) {
        #pragma unroll
        for (int j = 0; j < 4; j++) {
            int m = j*32 + am;
            As[(ak+0)*132+m] = av4[j].x; As[(ak+1)*132+m] = av4[j].y;
            As[(ak+2)*132+m] = av4[j].z; As[(ak+3)*132+m] = av4[j].w;
        }
        #pragma unroll
        for (int j = 0; j < 2; j++) {
            int n = j*32 + bn;
            Bs[(bk+0)*68+n] = bv4[j].x; Bs[(bk+1)*68+n] = bv4[j].y;
            Bs[(bk+2)*68+n] = bv4[j].z; Bs[(bk+3)*68+n] = bv4[j].w;
        }
        __syncthreads();
        if (kc + 32 < ENCD) {
            #pragma unroll
            for (int j = 0; j < 4; j++)
                av4[j] = *(const float4*)(img + rowb[j*32 + am] + kc + 32 + ak);
            #pragma unroll
            for (int j = 0; j < 2; j++)
                bv4[j] = *(const float4*)(W_enc + (long)(tn*64 + j*32 + bn)*ENCD + kc + 32 + bk);
        }
        #pragma unroll
        for (int k = 0; k < 32; k++) {
            float4 a0 = *(const float4*)&As[k*132 + m0];
            float4 a1 = *(const float4*)&As[k*132 + m0 + 4];
            float4 b0 = *(const float4*)&Bs[k*68 + n0];
            float avv[8] = {a0.x,a0.y,a0.z,a0.w,a1.x,a1.y,a1.z,a1.w};
            float bvv[4] = {b0.x,b0.y,b0.z,b0.w};
            #pragma unroll
            for (int i = 0; i < 8; i++)
                #pragma unroll
                for (int j = 0; j < 4; j++)
                    acc[i][j] = fmaf(avv[i], bvv[j], acc[i][j]);
        }
        __syncthreads();
    }
    #pragma unroll
    for (int i = 0; i < 8; i++) {
        int row = tm*128 + m0 + i;
        #pragma unroll
        for (int j = 0; j < 4; j++) {
            int col = tn*64 + n0 + j;
            g_enc[(long)row*512 + col] = acc[i][j] + b_enc[col];
        }
    }
}

// ---------------- 128x64 dense tile, K=512, pipelined: final FC ----------------
__device__ void fc_task(int tm, int tn,
                        const float* __restrict__ W_fc, const float* __restrict__ b_fc,
                        float* __restrict__ out, float* pool)
{
    float* As = pool;
    float* Bs = pool + 4224;
    const int tid = threadIdx.x;
    __syncthreads();
    float acc[8][4];
    #pragma unroll
    for (int i = 0; i < 8; i++)
        #pragma unroll
        for (int j = 0; j < 4; j++) acc[i][j] = 0.f;
    const int ty = tid >> 4, tx = tid & 15;
    const int m0 = ty*8, n0 = tx*4;
    const int am = tid >> 3, ak = (tid & 7) * 4;
    const int bn = tid >> 3, bk = (tid & 7) * 4;

    float4 av4[4], bv4[2];
    #pragma unroll
    for (int j = 0; j < 4; j++)
        av4[j] = *(const float4*)(g_hnall + (long)(tm*128 + j*32 + am)*512 + ak);
    #pragma unroll
    for (int j = 0; j < 2; j++) {
        int ng = tn*64 + j*32 + bn;
        bv4[j] = (ng < VV) ? *(const float4*)(W_fc + (long)ng*512 + bk)
                           : make_float4(0.f,0.f,0.f,0.f);
    }

    for (int kc = 0; kc < 512; kc += 32) {
        #pragma unroll
        for (int j = 0; j < 4; j++) {
            int m = j*32 + am;
            As[(ak+0)*132+m] = av4[j].x; As[(ak+1)*132+m] = av4[j].y;
            As[(ak+2)*132+m] = av4[j].z; As[(ak+3)*132+m] = av4[j].w;
        }
        #pragma unroll
        for (int j = 0; j < 2; j++) {
            int n = j*32 + bn;
            Bs[(bk+0)*68+n] = bv4[j].x; Bs[(bk+1)*68+n] = bv4[j].y;
            Bs[(bk+2)*68+n] = bv4[j].z; Bs[(bk+3)*68+n] = bv4[j].w;
        }
        __syncthreads();
        if (kc + 32 < 512) {
            #pragma unroll
            for (int j = 0; j < 4; j++)
                av4[j] = *(const float4*)(g_hnall + (long)(tm*128 + j*32 + am)*512 + kc + 32 + ak);
            #pragma unroll
            for (int j = 0; j < 2; j++) {
                int ng = tn*64 + j*32 + bn;
                bv4[j] = (ng < VV) ? *(const float4*)(W_fc + (long)ng*512 + kc + 32 + bk)
                                   : make_float4(0.f,0.f,0.f,0.f);
            }
        }
        #pragma unroll
        for (int k = 0; k < 32; k++) {
            float4 a0 = *(const float4*)&As[k*132 + m0];
            float4 a1 = *(const float4*)&As[k*132 + m0 + 4];
            float4 b0 = *(const float4*)&Bs[k*68 + n0];
            float avv[8] = {a0.x,a0.y,a0.z,a0.w,a1.x,a1.y,a1.z,a1.w};
            float bvv[4] = {b0.x,b0.y,b0.z,b0.w};
            #pragma unroll
            for (int i = 0; i < 8; i++)
                #pragma unroll
                for (int j = 0; j < 4; j++)
                    acc[i][j] = fmaf(avv[i], bvv[j], acc[i][j]);
        }
        __syncthreads();
    }
    #pragma unroll
    for (int i = 0; i < 8; i++) {
        int r = tm*128 + m0 + i;
        if (r < TT*BSZ) {
            int tt = r >> 5, bb = r & 31;
            bool act = tt < g_dlen[bb];
            long obase = OFF_PRED + ((long)bb*TT + tt)*VV;
            #pragma unroll
            for (int j = 0; j < 4; j++) {
                int col = tn*64 + n0 + j;
                if (col < VV) out[obase + col] = act ? (acc[i][j] + b_fc[col]) : 0.f;
            }
        }
    }
}

// ---------------- attention: reduce pDec + scores + softmax ----------------
__device__ void attn_task(int b, int t, const float* __restrict__ b_dec,
                          const float* __restrict__ w_full, const float* __restrict__ b_full,
                          float* __restrict__ out, float* pool)
{
    float* dec_s = pool;
    float* wf    = pool + 512;
    float* sc    = pool + 1024;
    float* red   = pool + 1280;
    const int tid = threadIdx.x;
    __syncthreads();
    for (int a = tid; a < 512; a += 256) {
        float s = b_dec[a];
        #pragma unroll
        for (int sk = 0; sk < 16; sk++) s += g_pDec[sk*16384 + b*512 + a];
        dec_s[a] = s;
        wf[a] = w_full[a];
    }
    __syncthreads();
    int wid = tid >> 5, lane = tid & 31;
    float bf = b_full[0];
    for (int p = wid; p < PP; p += 8) {
        const float* er = g_enc + ((long)b*PP + p)*512 + lane*16;
        const float* ds = dec_s + lane*16;
        const float* wl = wf + lane*16;
        float s = 0.f;
        #pragma unroll
        for (int q = 0; q < 4; q++) {
            float4 e = *(const float4*)(er + q*4);
            float4 d = *(const float4*)(ds + q*4);
            float4 w = *(const float4*)(wl + q*4);
            s = fmaf(fmaxf(e.x + d.x, 0.f), w.x, s);
            s = fmaf(fmaxf(e.y + d.y, 0.f), w.y, s);
            s = fmaf(fmaxf(e.z + d.z, 0.f), w.z, s);
            s = fmaf(fmaxf(e.w + d.w, 0.f), w.w, s);
        }
        #pragma unroll
        for (int off = 16; off > 0; off >>= 1) s += __shfl_xor_sync(0xffffffffu, s, off);
        if (lane == 0) sc[p] = s + bf;
    }
    __syncthreads();
    float v = (tid < PP) ? sc[tid] : -3.0e38f;
    red[tid] = v; __syncthreads();
    for (int s2 = 128; s2 > 0; s2 >>= 1) {
        if (tid < s2) red[tid] = fmaxf(red[tid], red[tid + s2]);
        __syncthreads();
    }
    float mx = red[0];
    __syncthreads();
    float ev = (tid < PP) ? expf(sc[tid] - mx) : 0.f;
    red[tid] = ev; __syncthreads();
    for (int s2 = 128; s2 > 0; s2 >>= 1) {
        if (tid < s2) red[tid] += red[tid + s2];
        __syncthreads();
    }
    float inv = 1.f / red[0];
    if (tid < PP) {
        float al = ev * inv;
        g_alpha[b*PP + tid] = al;
        out[OFF_ALPHA + ((long)b*TT + t)*PP + tid] = al;
    }
}

// ---------------- main persistent kernel ----------------
__global__ void __launch_bounds__(256, 2)
persist(const float* __restrict__ img, const int* __restrict__ toks, const int* __restrict__ lens,
        const float* __restrict__ W_enc, const float* __restrict__ b_enc,
        const float* __restrict__ W_dec, const float* __restrict__ b_dec,
        const float* __restrict__ w_full, const float* __restrict__ b_full,
        const float* __restrict__ emb,
        const float* __restrict__ W_ih, const float* __restrict__ b_ih,
        const float* __restrict__ W_hh, const float* __restrict__ b_hh,
        const float* __restrict__ W_h0, const float* __restrict__ b_h0,
        const float* __restrict__ W_c0, const float* __restrict__ b_c0,
        const float* __restrict__ W_beta, const float* __restrict__ b_beta,
        const float* __restrict__ W_fc, const float* __restrict__ b_fc,
        float* __restrict__ out)
{
    __shared__ __align__(16) float pool[9700];
    const int bid = blockIdx.x;
    const int tid = threadIdx.x;

    // ---- P0 ----
    if (bid == 0) {
        if (tid < BSZ) {
            int li = lens[tid];
            int r = 0;
            for (int j = 0; j < BSZ; j++) {
                int lj = lens[j];
                if (lj > li || (lj == li && j < tid)) r++;
            }
            g_sort[r] = tid;
        }
        __syncthreads();
        if (tid < BSZ) {
            int si = g_sort[tid];
            int dl = lens[si] - 1;
            g_dlen[tid] = dl;
            out[OFF_DLEN + tid] = (float)dl;
            out[OFF_SORT + tid] = (float)si;
        }
        __syncthreads();
        if (tid < TT) {
            int a = 0;
            for (int j = 0; j < BSZ; j++) a += (g_dlen[j] > tid) ? 1 : 0;
            g_act[tid] = a;
        }
        for (int idx = tid; idx < BSZ*LL; idx += 256) {
            int b = idx / LL, l = idx - b*LL;
            int tk = toks[g_sort[b]*LL + l];
            g_toks[idx] = tk;
            out[OFF_TOKS + idx] = (float)tk;
        }
    } else if (bid == 1) {
        for (int i = tid; i < 2048; i += 256) g_bcomb[i] = b_ih[i] + b_hh[i];
    } else if (bid == 2) {
        for (int i = tid; i < 32*512; i += 256) g_hnall[1632L*512 + i] = 0.f;
    }
    gridbar();

    // ---- P1: enc_att (392) | embg (408) | mean (32) ----
    for (int task = bid; task < 832; task += GRID) {
        if (task < 392) {
            enc_task(task >> 3, task & 7, img, W_enc, b_enc, pool);
        } else if (task < 800) {
            int id = task - 392;
            int tt = id >> 3, nt = id & 7;
            gemm32(emb, 512, g_toks + tt, LL, W_ih, 2560, 0,
                   2048, nt*256, 0, 512, g_embg + (long)tt*65536, 2048, pool);
        } else {
            int b = task - 800;
            __syncthreads();
            long srow = (long)g_sort[b] * PP * ENCD;
            int e0 = tid * 8;
            float a[8] = {0,0,0,0,0,0,0,0};
            #pragma unroll 4
            for (int p = 0; p < PP; p++) {
                const float* r = img + srow + (long)p*ENCD + e0;
                float4 v0 = *(const float4*)r;
                float4 v1 = *(const float4*)(r + 4);
                a[0]+=v0.x; a[1]+=v0.y; a[2]+=v0.z; a[3]+=v0.w;
                a[4]+=v1.x; a[5]+=v1.y; a[6]+=v1.z; a[7]+=v1.w;
            }
            #pragma unroll
            for (int i = 0; i < 8; i++)
                g_mean[b*2048 + e0 + i] = a[i] * (1.f/196.f);
        }
    }
    gridbar();

    // ---- P2: h0/c0 partials ----
    for (int task = bid; task < 32; task += GRID) {
        int half = task >> 4, nt = (task >> 3) & 1, sk = task & 7;
        gemm32(g_mean, 2048, (const int*)0, 0, half ? W_c0 : W_h0, 2048, 0,
               512, nt*256, sk*256, 256, g_pIH + (long)(half*8 + sk)*16384, 512, pool);
    }
    gridbar();

    // ---- P3: reduce h0/c0 ----
    for (int task = bid; task < 32; task += GRID) {
        int b = task;
        for (int j = tid; j < 512; j += 256) {
            float s = b_h0[j], s2 = b_c0[j];
            #pragma unroll
            for (int s8 = 0; s8 < 8; s8++) {
                s  += g_pIH[s8*16384 + b*512 + j];
                s2 += g_pIH[(8+s8)*16384 + b*512 + j];
            }
            g_h[b*512 + j] = s;
            g_c[b*512 + j] = s2;
        }
    }
    gridbar();

    // ---- decode loop (R9 structure; Ph1 split to 288 tasks) ----
    for (int t = 0; t < TT; t++) {
        const int A = g_act[t];

        // Ph1: dec SK16(32) | hh SK16(128) | beta SK16(128) = 288
        for (int task = bid; task < 288; task += GRID) {
            if (task < 32) {
                int nt = task >> 4, sk = task & 15;
                gemm32(g_h, 512, (const int*)0, 0, W_dec, 512, 0,
                       512, nt*256, sk*32, 32, g_pDec + (long)sk*16384, 512, pool);
            } else if (task < 160) {
                int rid = task - 32, nt = rid >> 4, sk = rid & 15;
                gemm32(g_h, 512, (const int*)0, 0, W_hh, 512, 0,
                       2048, nt*256, sk*32, 32, g_pHH + (long)sk*65536, 2048, pool);
            } else {
                int rid = task - 160, nt = rid >> 4, sk = rid & 15;
                gemm32(g_h, 512, (const int*)0, 0, W_beta, 512, 0,
                       2048, nt*256, sk*32, 32, g_pBeta + (long)sk*65536, 2048, pool);
            }
        }
        gridbar();

        // Ph2: attn(32) | gates-base(32) | beta-sigmoid(64)
        for (int task = bid; task < 128; task += GRID) {
            if (task < 32) {
                int b = task;
                if (b < A) {
                    attn_task(b, t, b_dec, w_full, b_full, out, pool);
                } else if (tid < PP) {
                    out[OFF_ALPHA + ((long)b*TT + t)*PP + tid] = 0.f;
                }
            } else if (task < 64) {
                int b = task - 32;
                if (b >= A) continue;
                int c0 = tid * 8;
                float4 s0 = *(const float4*)(g_bcomb + c0);
                float4 s1 = *(const float4*)(g_bcomb + c0 + 4);
                float4 e0 = *(const float4*)(g_embg + (long)t*65536 + b*2048 + c0);
                float4 e1 = *(const float4*)(g_embg + (long)t*65536 + b*2048 + c0 + 4);
                s0.x+=e0.x; s0.y+=e0.y; s0.z+=e0.z; s0.w+=e0.w;
                s1.x+=e1.x; s1.y+=e1.y; s1.z+=e1.z; s1.w+=e1.w;
                #pragma unroll
                for (int sk = 0; sk < 16; sk++) {
                    float4 p0 = *(const float4*)(g_pHH + (long)sk*65536 + b*2048 + c0);
                    float4 p1 = *(const float4*)(g_pHH + (long)sk*65536 + b*2048 + c0 + 4);
                    s0.x+=p0.x; s0.y+=p0.y; s0.z+=p0.z; s0.w+=p0.w;
                    s1.x+=p1.x; s1.y+=p1.y; s1.z+=p1.z; s1.w+=p1.w;
                }
                *(float4*)(g_gates + b*2048 + c0) = s0;
                *(float4*)(g_gates + b*2048 + c0 + 4) = s1;
            } else {
                int rid = task - 64;
                int b = rid >> 1, half = rid & 1;
                if (b >= A) continue;
                int c0 = half*1024 + tid*4;
                float4 s = *(const float4*)(b_beta + c0);
                #pragma unroll
                for (int sk = 0; sk < 16; sk++) {
                    float4 p = *(const float4*)(g_pBeta + (long)sk*65536 + b*2048 + c0);
                    s.x+=p.x; s.y+=p.y; s.z+=p.z; s.w+=p.w;
                }
                float4 o;
                o.x = sigm(s.x); o.y = sigm(s.y); o.z = sigm(s.z); o.w = sigm(s.w);
                *(float4*)(g_betasig + b*2048 + c0) = o;
            }
        }
        gridbar();

        // Ph3: awe * gate -> x2 (64 tasks), only active b
        for (int task = bid; task < 64; task += GRID) {
            int b = task >> 1, ch = task & 1;
            if (b >= A) continue;
            float* al = pool;
            __syncthreads();
            if (tid < PP) al[tid] = g_alpha[b*PP + tid];
            __syncthreads();
            int c0 = ch*1024 + tid*4;
            const float* base = img + ((long)(g_sort[b]*PP))*ENCD + c0;
            float4 s = make_float4(0.f,0.f,0.f,0.f);
            #pragma unroll 4
            for (int p = 0; p < PP; p++) {
                float4 v = *(const float4*)(base + (long)p*ENCD);
                float a = al[p];
                s.x = fmaf(a, v.x, s.x); s.y = fmaf(a, v.y, s.y);
                s.z = fmaf(a, v.z, s.z); s.w = fmaf(a, v.w, s.w);
            }
            float4 g = *(const float4*)(g_betasig + b*2048 + c0);
            s.x *= g.x; s.y *= g.y; s.z *= g.z; s.w *= g.w;
            *(float4*)(g_x2 + b*2048 + c0) = s;
        }
        gridbar();

        // Ph4: x2 @ W_ih[:,512:]^T (256 tasks: 8 ntiles x SK32 k64)
        for (int task = bid; task < 256; task += GRID) {
            int nt = task >> 5, sk = task & 31;
            gemm32(g_x2, 2048, (const int*)0, 0, W_ih, 2560, 512,
                   2048, nt*256, sk*64, 64, g_pIH + (long)sk*65536, 2048, pool);
        }
        gridbar();

        // Ph5: gate reduce + LSTM pointwise (64 tasks), only active b
        for (int task = bid; task < 64; task += GRID) {
            int b = task >> 1, half = task & 1;
            if (b >= A) continue;
            int j = half*256 + tid;
            float gi = g_gates[b*2048 + j];
            float gf = g_gates[b*2048 + j + 512];
            float gg = g_gates[b*2048 + j + 1024];
            float go = g_gates[b*2048 + j + 1536];
            #pragma unroll
            for (int sk = 0; sk < 32; sk++) {
                const float* p = g_pIH + (long)sk*65536 + b*2048;
                gi += p[j]; gf += p[j + 512]; gg += p[j + 1024]; go += p[j + 1536];
            }
            float c = g_c[b*512 + j];
            float cn = sigm(gf)*c + sigm(gi)*tanhf(gg);
            float hn = sigm(go)*tanhf(cn);
            g_hnall[((long)t*32 + b)*512 + j] = hn;
            g_c[b*512 + j] = cn;
            g_h[b*512 + j] = hn;
        }
        gridbar();
    }

    // ---- epilogue: preds = Hn_all @ W_fc^T + b_fc ----
    for (int task = bid; task < 13*157; task += GRID) {
        int tm = task / 157, tn = task - tm*157;
        fc_task(tm, tn, W_fc, b_fc, out, pool);
    }
}

// ---------------- host launcher ----------------
extern "C" void kernel_launch(void* const* d_in, const int* in_sizes, int n_in,
                              void* d_out, int out_size) {
    persist<<<GRID, 256>>>(
        (const float*)d_in[0],  (const int*)d_in[1],   (const int*)d_in[2],
        (const float*)d_in[3],  (const float*)d_in[4],
        (const float*)d_in[5],  (const float*)d_in[6],
        (const float*)d_in[7],  (const float*)d_in[8],
        (const float*)d_in[9],
        (const float*)d_in[10], (const float*)d_in[11],
        (const float*)d_in[12], (const float*)d_in[13],
        (const float*)d_in[14], (const float*)d_in[15],
        (const float*)d_in[16], (const float*)d_in[17],
        (const float*)d_in[18], (const float*)d_in[19],
        (const float*)d_in[20], (const float*)d_in[21],
        (float*)d_out);
    (void)in_sizes; (void)n_in; (void)out_size;
}

// round 13
// speedup vs baseline: 1.8369x; 1.2323x over previous
#include <cuda_runtime.h>
#include <math.h>

#define BSZ 32
#define PP 196
#define ENCD 2048
#define ATTD 512
#define DECD 512
#define VV 10000
#define LL 52
#define TT 51
#define GRID 296

#define OFF_PRED  0L
#define OFF_TOKS  ((long)BSZ*TT*VV)
#define OFF_DLEN  (OFF_TOKS + (long)BSZ*LL)
#define OFF_ALPHA (OFF_DLEN + (long)BSZ)
#define OFF_SORT  (OFF_ALPHA + (long)BSZ*TT*PP)

// ---------------- static device scratch ----------------
__device__ float g_enc[6272L*512];
__device__ float g_embg[51L*32*2048];
__device__ float g_pDec[16L*32*512];
__device__ float g_pHH[16L*32*2048];
__device__ float g_pBeta[16L*32*2048];
__device__ float g_pIH[32L*32*2048];
__device__ float g_mean[32*2048];
__device__ float g_h[32*512];
__device__ float g_c[32*512];
__device__ float g_hnall[1664L*512];
__device__ float g_gates[32*2048];
__device__ float g_betasig[32*2048];
__device__ float g_x2[32*2048];
__device__ float g_alpha[32*196];
__device__ float g_bcomb[2048];
__device__ int   g_sort[32];
__device__ int   g_dlen[32];
__device__ int   g_act[TT];
__device__ int   g_toks[32*LL];
__device__ unsigned g_barcnt;
__device__ volatile unsigned g_bargen;

__device__ __forceinline__ float sigm(float x) { return 1.f / (1.f + expf(-x)); }

// ---------------- grid-wide software barrier ----------------
__device__ __forceinline__ void gridbar() {
    __syncthreads();
    if (threadIdx.x == 0) {
        __threadfence();
        unsigned gen = g_bargen;
        if (atomicAdd(&g_barcnt, 1u) == GRID - 1) {
            g_barcnt = 0;
            __threadfence();
            g_bargen = gen + 1;
        } else {
            while (g_bargen == gen) { __nanosleep(150); }
        }
        __threadfence();
    }
    __syncthreads();
}

// ---------------- 32-row GEMM partial tile, conflict-free column mapping ----------------
__device__ void gemm32(const float* __restrict__ X, int ldx,
                       const int* __restrict__ gidx, int gstride,
                       const float* __restrict__ W, int ldw, int wcol0,
                       int Nfull, int nbase, int k0, int klen,
                       float* __restrict__ part, int Nld, float* pool)
{
    float* Xs = pool;                 // 32k x 36
    float* Ws = pool + 1184;          // 32k x 264
    int* roff = (int*)(pool + 1184 + 32*264);
    const int tid = threadIdx.x;
    __syncthreads();
    if (tid < 32) roff[tid] = (gidx ? gidx[tid * gstride] : tid) * ldx;
    __syncthreads();

    const int m0 = (tid >> 5) * 4;
    const int lane4 = (tid & 31) * 4;
    const int xm = tid >> 3, xk = (tid & 7) * 4;
    const int wn = tid >> 3, wk = (tid & 7) * 4;

    float acc[4][8];
    #pragma unroll
    for (int i = 0; i < 4; i++)
        #pragma unroll
        for (int j = 0; j < 8; j++) acc[i][j] = 0.f;

    float4 xv = *(const float4*)(X + roff[xm] + k0 + xk);
    float4 wv[8];
    #pragma unroll
    for (int j = 0; j < 8; j++) {
        int ng = nbase + j*32 + wn;
        wv[j] = (ng < Nfull) ? *(const float4*)(W + (long)ng*ldw + wcol0 + k0 + wk)
                             : make_float4(0.f, 0.f, 0.f, 0.f);
    }

    for (int kk = 0; kk < klen; kk += 32) {
        Xs[(xk+0)*36 + xm] = xv.x; Xs[(xk+1)*36 + xm] = xv.y;
        Xs[(xk+2)*36 + xm] = xv.z; Xs[(xk+3)*36 + xm] = xv.w;
        #pragma unroll
        for (int j = 0; j < 8; j++) {
            int n = j*32 + wn;
            Ws[(wk+0)*264 + n] = wv[j].x; Ws[(wk+1)*264 + n] = wv[j].y;
            Ws[(wk+2)*264 + n] = wv[j].z; Ws[(wk+3)*264 + n] = wv[j].w;
        }
        __syncthreads();
        if (kk + 32 < klen) {
            int kc = k0 + kk + 32;
            xv = *(const float4*)(X + roff[xm] + kc + xk);
            #pragma unroll
            for (int j = 0; j < 8; j++) {
                int ng = nbase + j*32 + wn;
                wv[j] = (ng < Nfull) ? *(const float4*)(W + (long)ng*ldw + wcol0 + kc + wk)
                                     : make_float4(0.f, 0.f, 0.f, 0.f);
            }
        }
        #pragma unroll
        for (int k = 0; k < 32; k++) {
            float4 a = *(const float4*)&Xs[k*36 + m0];
            float av[4] = {a.x, a.y, a.z, a.w};
            float4 w0 = *(const float4*)&Ws[k*264 + lane4];
            float4 w1 = *(const float4*)&Ws[k*264 + 128 + lane4];
            float wvv[8] = {w0.x,w0.y,w0.z,w0.w,w1.x,w1.y,w1.z,w1.w};
            #pragma unroll
            for (int i = 0; i < 4; i++)
                #pragma unroll
                for (int j = 0; j < 8; j++)
                    acc[i][j] = fmaf(av[i], wvv[j], acc[i][j]);
        }
        __syncthreads();
    }
    #pragma unroll
    for (int i = 0; i < 4; i++) {
        float4 o0 = make_float4(acc[i][0], acc[i][1], acc[i][2], acc[i][3]);
        float4 o1 = make_float4(acc[i][4], acc[i][5], acc[i][6], acc[i][7]);
        *(float4*)&part[(long)(m0+i)*Nld + nbase + lane4]       = o0;
        *(float4*)&part[(long)(m0+i)*Nld + nbase + 128 + lane4] = o1;
    }
}

// ---------------- 128x64 dense tile, K=2048, pipelined: enc_att ----------------
__device__ void enc_task(int tm, int tn, const float* __restrict__ img,
                         const float* __restrict__ W_enc, const float* __restrict__ b_enc,
                         float* pool)
{
    float* As = pool;
    float* Bs = pool + 4224;
    int* rowb = (int*)(pool + 6400);
    const int tid = threadIdx.x;
    __syncthreads();
    if (tid < 128) {
        int rr = tm*128 + tid;
        int b = rr / PP, p = rr - b*PP;
        rowb[tid] = (g_sort[b]*PP + p) * ENCD;
    }
    __syncthreads();
    float acc[8][4];
    #pragma unroll
    for (int i = 0; i < 8; i++)
        #pragma unroll
        for (int j = 0; j < 4; j++) acc[i][j] = 0.f;
    const int ty = tid >> 4, tx = tid & 15;
    const int m0 = ty*8, n0 = tx*4;
    const int am = tid >> 3, ak = (tid & 7) * 4;
    const int bn = tid >> 3, bk = (tid & 7) * 4;

    float4 av4[4], bv4[2];
    #pragma unroll
    for (int j = 0; j < 4; j++)
        av4[j] = *(const float4*)(img + rowb[j*32 + am] + ak);
    #pragma unroll
    for (int j = 0; j < 2; j++)
        bv4[j] = *(const float4*)(W_enc + (long)(tn*64 + j*32 + bn)*ENCD + bk);

    for (int kc = 0; kc < ENCD; kc += 32) {
        #pragma unroll
        for (int j = 0; j < 4; j++) {
            int m = j*32 + am;
            As[(ak+0)*132+m] = av4[j].x; As[(ak+1)*132+m] = av4[j].y;
            As[(ak+2)*132+m] = av4[j].z; As[(ak+3)*132+m] = av4[j].w;
        }
        #pragma unroll
        for (int j = 0; j < 2; j++) {
            int n = j*32 + bn;
            Bs[(bk+0)*68+n] = bv4[j].x; Bs[(bk+1)*68+n] = bv4[j].y;
            Bs[(bk+2)*68+n] = bv4[j].z; Bs[(bk+3)*68+n] = bv4[j].w;
        }
        __syncthreads();
        if (kc + 32 < ENCD) {
            #pragma unroll
            for (int j = 0; j < 4; j++)
                av4[j] = *(const float4*)(img + rowb[j*32 + am] + kc + 32 + ak);
            #pragma unroll
            for (int j = 0; j < 2; j++)
                bv4[j] = *(const float4*)(W_enc + (long)(tn*64 + j*32 + bn)*ENCD + kc + 32 + bk);
        }
        #pragma unroll
        for (int k = 0; k < 32; k++) {
            float4 a0 = *(const float4*)&As[k*132 + m0];
            float4 a1 = *(const float4*)&As[k*132 + m0 + 4];
            float4 b0 = *(const float4*)&Bs[k*68 + n0];
            float avv[8] = {a0.x,a0.y,a0.z,a0.w,a1.x,a1.y,a1.z,a1.w};
            float bvv[4] = {b0.x,b0.y,b0.z,b0.w};
            #pragma unroll
            for (int i = 0; i < 8; i++)
                #pragma unroll
                for (int j = 0; j < 4; j++)
                    acc[i][j] = fmaf(avv[i], bvv[j], acc[i][j]);
        }
        __syncthreads();
    }
    #pragma unroll
    for (int i = 0; i < 8; i++) {
        int row = tm*128 + m0 + i;
        #pragma unroll
        for (int j = 0; j < 4; j++) {
            int col = tn*64 + n0 + j;
            g_enc[(long)row*512 + col] = acc[i][j] + b_enc[col];
        }
    }
}

// ---------------- 128x64 dense tile, K=512, pipelined: final FC ----------------
__device__ void fc_task(int tm, int tn,
                        const float* __restrict__ W_fc, const float* __restrict__ b_fc,
                        float* __restrict__ out, float* pool)
{
    float* As = pool;
    float* Bs = pool + 4224;
    const int tid = threadIdx.x;
    __syncthreads();
    float acc[8][4];
    #pragma unroll
    for (int i = 0; i < 8; i++)
        #pragma unroll
        for (int j = 0; j < 4; j++) acc[i][j] = 0.f;
    const int ty = tid >> 4, tx = tid & 15;
    const int m0 = ty*8, n0 = tx*4;
    const int am = tid >> 3, ak = (tid & 7) * 4;
    const int bn = tid >> 3, bk = (tid & 7) * 4;

    float4 av4[4], bv4[2];
    #pragma unroll
    for (int j = 0; j < 4; j++)
        av4[j] = *(const float4*)(g_hnall + (long)(tm*128 + j*32 + am)*512 + ak);
    #pragma unroll
    for (int j = 0; j < 2; j++) {
        int ng = tn*64 + j*32 + bn;
        bv4[j] = (ng < VV) ? *(const float4*)(W_fc + (long)ng*512 + bk)
                           : make_float4(0.f,0.f,0.f,0.f);
    }

    for (int kc = 0; kc < 512; kc += 32) {
        #pragma unroll
        for (int j = 0; j < 4; j++) {
            int m = j*32 + am;
            As[(ak+0)*132+m] = av4[j].x; As[(ak+1)*132+m] = av4[j].y;
            As[(ak+2)*132+m] = av4[j].z; As[(ak+3)*132+m] = av4[j].w;
        }
        #pragma unroll
        for (int j = 0; j < 2; j++) {
            int n = j*32 + bn;
            Bs[(bk+0)*68+n] = bv4[j].x; Bs[(bk+1)*68+n] = bv4[j].y;
            Bs[(bk+2)*68+n] = bv4[j].z; Bs[(bk+3)*68+n] = bv4[j].w;
        }
        __syncthreads();
        if (kc + 32 < 512) {
            #pragma unroll
            for (int j = 0; j < 4; j++)
                av4[j] = *(const float4*)(g_hnall + (long)(tm*128 + j*32 + am)*512 + kc + 32 + ak);
            #pragma unroll
            for (int j = 0; j < 2; j++) {
                int ng = tn*64 + j*32 + bn;
                bv4[j] = (ng < VV) ? *(const float4*)(W_fc + (long)ng*512 + kc + 32 + bk)
                                   : make_float4(0.f,0.f,0.f,0.f);
            }
        }
        #pragma unroll
        for (int k = 0; k < 32; k++) {
            float4 a0 = *(const float4*)&As[k*132 + m0];
            float4 a1 = *(const float4*)&As[k*132 + m0 + 4];
            float4 b0 = *(const float4*)&Bs[k*68 + n0];
            float avv[8] = {a0.x,a0.y,a0.z,a0.w,a1.x,a1.y,a1.z,a1.w};
            float bvv[4] = {b0.x,b0.y,b0.z,b0.w};
            #pragma unroll
            for (int i = 0; i < 8; i++)
                #pragma unroll
                for (int j = 0; j < 4; j++)
                    acc[i][j] = fmaf(avv[i], bvv[j], acc[i][j]);
        }
        __syncthreads();
    }
    #pragma unroll
    for (int i = 0; i < 8; i++) {
        int r = tm*128 + m0 + i;
        if (r < TT*BSZ) {
            int tt = r >> 5, bb = r & 31;
            bool act = tt < g_dlen[bb];
            long obase = OFF_PRED + ((long)bb*TT + tt)*VV;
            #pragma unroll
            for (int j = 0; j < 4; j++) {
                int col = tn*64 + n0 + j;
                if (col < VV) out[obase + col] = act ? (acc[i][j] + b_fc[col]) : 0.f;
            }
        }
    }
}

// ---------------- attention: reduce pDec + scores (2-row ILP) + softmax ----------------
__device__ void attn_task(int b, int t, const float* __restrict__ b_dec,
                          const float* __restrict__ w_full, const float* __restrict__ b_full,
                          float* __restrict__ out, float* pool)
{
    float* dec_s = pool;
    float* wf    = pool + 512;
    float* sc    = pool + 1024;
    float* red   = pool + 1280;
    const int tid = threadIdx.x;
    __syncthreads();
    for (int a = tid; a < 512; a += 256) {
        float s = b_dec[a];
        #pragma unroll
        for (int sk = 0; sk < 16; sk++) s += g_pDec[sk*16384 + b*512 + a];
        dec_s[a] = s;
        wf[a] = w_full[a];
    }
    __syncthreads();
    int wid = tid >> 5, lane = tid & 31;
    float bf = b_full[0];
    const float* ds = dec_s + lane*16;
    const float* wl = wf + lane*16;
    // two rows per iteration: independent load + shfl chains
    for (int p = wid; p < PP; p += 16) {
        int p2 = p + 8;
        bool has2 = (p2 < PP);
        const float* er  = g_enc + ((long)b*PP + p)*512 + lane*16;
        const float* er2 = g_enc + ((long)b*PP + (has2 ? p2 : p))*512 + lane*16;
        float s = 0.f, s2v = 0.f;
        #pragma unroll
        for (int q = 0; q < 4; q++) {
            float4 e  = *(const float4*)(er + q*4);
            float4 e2 = *(const float4*)(er2 + q*4);
            float4 d  = *(const float4*)(ds + q*4);
            float4 w  = *(const float4*)(wl + q*4);
            s   = fmaf(fmaxf(e.x + d.x, 0.f), w.x, s);
            s2v = fmaf(fmaxf(e2.x + d.x, 0.f), w.x, s2v);
            s   = fmaf(fmaxf(e.y + d.y, 0.f), w.y, s);
            s2v = fmaf(fmaxf(e2.y + d.y, 0.f), w.y, s2v);
            s   = fmaf(fmaxf(e.z + d.z, 0.f), w.z, s);
            s2v = fmaf(fmaxf(e2.z + d.z, 0.f), w.z, s2v);
            s   = fmaf(fmaxf(e.w + d.w, 0.f), w.w, s);
            s2v = fmaf(fmaxf(e2.w + d.w, 0.f), w.w, s2v);
        }
        #pragma unroll
        for (int off = 16; off > 0; off >>= 1) {
            s   += __shfl_xor_sync(0xffffffffu, s, off);
            s2v += __shfl_xor_sync(0xffffffffu, s2v, off);
        }
        if (lane == 0) {
            sc[p] = s + bf;
            if (has2) sc[p2] = s2v + bf;
        }
    }
    __syncthreads();
    float v = (tid < PP) ? sc[tid] : -3.0e38f;
    red[tid] = v; __syncthreads();
    for (int s2 = 128; s2 > 0; s2 >>= 1) {
        if (tid < s2) red[tid] = fmaxf(red[tid], red[tid + s2]);
        __syncthreads();
    }
    float mx = red[0];
    __syncthreads();
    float ev = (tid < PP) ? expf(sc[tid] - mx) : 0.f;
    red[tid] = ev; __syncthreads();
    for (int s2 = 128; s2 > 0; s2 >>= 1) {
        if (tid < s2) red[tid] += red[tid + s2];
        __syncthreads();
    }
    float inv = 1.f / red[0];
    if (tid < PP) {
        float al = ev * inv;
        g_alpha[b*PP + tid] = al;
        out[OFF_ALPHA + ((long)b*TT + t)*PP + tid] = al;
    }
}

// ---------------- main persistent kernel ----------------
__global__ void __launch_bounds__(256, 2)
persist(const float* __restrict__ img, const int* __restrict__ toks, const int* __restrict__ lens,
        const float* __restrict__ W_enc, const float* __restrict__ b_enc,
        const float* __restrict__ W_dec, const float* __restrict__ b_dec,
        const float* __restrict__ w_full, const float* __restrict__ b_full,
        const float* __restrict__ emb,
        const float* __restrict__ W_ih, const float* __restrict__ b_ih,
        const float* __restrict__ W_hh, const float* __restrict__ b_hh,
        const float* __restrict__ W_h0, const float* __restrict__ b_h0,
        const float* __restrict__ W_c0, const float* __restrict__ b_c0,
        const float* __restrict__ W_beta, const float* __restrict__ b_beta,
        const float* __restrict__ W_fc, const float* __restrict__ b_fc,
        float* __restrict__ out)
{
    __shared__ __align__(16) float pool[9700];
    const int bid = blockIdx.x;
    const int tid = threadIdx.x;

    // ---- P0 ----
    if (bid == 0) {
        if (tid < BSZ) {
            int li = lens[tid];
            int r = 0;
            for (int j = 0; j < BSZ; j++) {
                int lj = lens[j];
                if (lj > li || (lj == li && j < tid)) r++;
            }
            g_sort[r] = tid;
        }
        __syncthreads();
        if (tid < BSZ) {
            int si = g_sort[tid];
            int dl = lens[si] - 1;
            g_dlen[tid] = dl;
            out[OFF_DLEN + tid] = (float)dl;
            out[OFF_SORT + tid] = (float)si;
        }
        __syncthreads();
        if (tid < TT) {
            int a = 0;
            for (int j = 0; j < BSZ; j++) a += (g_dlen[j] > tid) ? 1 : 0;
            g_act[tid] = a;
        }
        for (int idx = tid; idx < BSZ*LL; idx += 256) {
            int b = idx / LL, l = idx - b*LL;
            int tk = toks[g_sort[b]*LL + l];
            g_toks[idx] = tk;
            out[OFF_TOKS + idx] = (float)tk;
        }
    } else if (bid == 1) {
        for (int i = tid; i < 2048; i += 256) g_bcomb[i] = b_ih[i] + b_hh[i];
    } else if (bid == 2) {
        for (int i = tid; i < 32*512; i += 256) g_hnall[1632L*512 + i] = 0.f;
    }
    gridbar();

    // ---- P1: enc_att (392) | embg (408) | mean (32) ----
    for (int task = bid; task < 832; task += GRID) {
        if (task < 392) {
            enc_task(task >> 3, task & 7, img, W_enc, b_enc, pool);
        } else if (task < 800) {
            int id = task - 392;
            int tt = id >> 3, nt = id & 7;
            gemm32(emb, 512, g_toks + tt, LL, W_ih, 2560, 0,
                   2048, nt*256, 0, 512, g_embg + (long)tt*65536, 2048, pool);
        } else {
            int b = task - 800;
            __syncthreads();
            long srow = (long)g_sort[b] * PP * ENCD;
            int e0 = tid * 8;
            float a[8] = {0,0,0,0,0,0,0,0};
            #pragma unroll 4
            for (int p = 0; p < PP; p++) {
                const float* r = img + srow + (long)p*ENCD + e0;
                float4 v0 = *(const float4*)r;
                float4 v1 = *(const float4*)(r + 4);
                a[0]+=v0.x; a[1]+=v0.y; a[2]+=v0.z; a[3]+=v0.w;
                a[4]+=v1.x; a[5]+=v1.y; a[6]+=v1.z; a[7]+=v1.w;
            }
            #pragma unroll
            for (int i = 0; i < 8; i++)
                g_mean[b*2048 + e0 + i] = a[i] * (1.f/196.f);
        }
    }
    gridbar();

    // ---- P2: h0/c0 partials ----
    for (int task = bid; task < 32; task += GRID) {
        int half = task >> 4, nt = (task >> 3) & 1, sk = task & 7;
        gemm32(g_mean, 2048, (const int*)0, 0, half ? W_c0 : W_h0, 2048, 0,
               512, nt*256, sk*256, 256, g_pIH + (long)(half*8 + sk)*16384, 512, pool);
    }
    gridbar();

    // ---- P3: reduce h0/c0 ----
    for (int task = bid; task < 32; task += GRID) {
        int b = task;
        for (int j = tid; j < 512; j += 256) {
            float s = b_h0[j], s2 = b_c0[j];
            #pragma unroll
            for (int s8 = 0; s8 < 8; s8++) {
                s  += g_pIH[s8*16384 + b*512 + j];
                s2 += g_pIH[(8+s8)*16384 + b*512 + j];
            }
            g_h[b*512 + j] = s;
            g_c[b*512 + j] = s2;
        }
    }
    gridbar();

    // ---- decode loop ----
    for (int t = 0; t < TT; t++) {
        const int A = g_act[t];

        // Ph1: dec SK16(32) | hh SK16(128) | beta SK16(128) = 288
        for (int task = bid; task < 288; task += GRID) {
            if (task < 32) {
                int nt = task >> 4, sk = task & 15;
                gemm32(g_h, 512, (const int*)0, 0, W_dec, 512, 0,
                       512, nt*256, sk*32, 32, g_pDec + (long)sk*16384, 512, pool);
            } else if (task < 160) {
                int rid = task - 32, nt = rid >> 4, sk = rid & 15;
                gemm32(g_h, 512, (const int*)0, 0, W_hh, 512, 0,
                       2048, nt*256, sk*32, 32, g_pHH + (long)sk*65536, 2048, pool);
            } else {
                int rid = task - 160, nt = rid >> 4, sk = rid & 15;
                gemm32(g_h, 512, (const int*)0, 0, W_beta, 512, 0,
                       2048, nt*256, sk*32, 32, g_pBeta + (long)sk*65536, 2048, pool);
            }
        }
        gridbar();

        // Ph2: attn(32) | gates-base(32) | beta-sigmoid(64)
        for (int task = bid; task < 128; task += GRID) {
            if (task < 32) {
                int b = task;
                if (b < A) {
                    attn_task(b, t, b_dec, w_full, b_full, out, pool);
                } else if (tid < PP) {
                    out[OFF_ALPHA + ((long)b*TT + t)*PP + tid] = 0.f;
                }
            } else if (task < 64) {
                int b = task - 32;
                if (b >= A) continue;
                int c0 = tid * 8;
                float4 s0 = *(const float4*)(g_bcomb + c0);
                float4 s1 = *(const float4*)(g_bcomb + c0 + 4);
                float4 e0 = *(const float4*)(g_embg + (long)t*65536 + b*2048 + c0);
                float4 e1 = *(const float4*)(g_embg + (long)t*65536 + b*2048 + c0 + 4);
                s0.x+=e0.x; s0.y+=e0.y; s0.z+=e0.z; s0.w+=e0.w;
                s1.x+=e1.x; s1.y+=e1.y; s1.z+=e1.z; s1.w+=e1.w;
                #pragma unroll
                for (int sk = 0; sk < 16; sk++) {
                    float4 p0 = *(const float4*)(g_pHH + (long)sk*65536 + b*2048 + c0);
                    float4 p1 = *(const float4*)(g_pHH + (long)sk*65536 + b*2048 + c0 + 4);
                    s0.x+=p0.x; s0.y+=p0.y; s0.z+=p0.z; s0.w+=p0.w;
                    s1.x+=p1.x; s1.y+=p1.y; s1.z+=p1.z; s1.w+=p1.w;
                }
                *(float4*)(g_gates + b*2048 + c0) = s0;
                *(float4*)(g_gates + b*2048 + c0 + 4) = s1;
            } else {
                int rid = task - 64;
                int b = rid >> 1, half = rid & 1;
                if (b >= A) continue;
                int c0 = half*1024 + tid*4;
                float4 s = *(const float4*)(b_beta + c0);
                #pragma unroll
                for (int sk = 0; sk < 16; sk++) {
                    float4 p = *(const float4*)(g_pBeta + (long)sk*65536 + b*2048 + c0);
                    s.x+=p.x; s.y+=p.y; s.z+=p.z; s.w+=p.w;
                }
                float4 o;
                o.x = sigm(s.x); o.y = sigm(s.y); o.z = sigm(s.z); o.w = sigm(s.w);
                *(float4*)(g_betasig + b*2048 + c0) = o;
            }
        }
        gridbar();

        // Ph3: awe * gate -> x2 (64 tasks), 4 independent accumulator chains
        for (int task = bid; task < 64; task += GRID) {
            int b = task >> 1, ch = task & 1;
            if (b >= A) continue;
            float* al = pool;
            __syncthreads();
            if (tid < PP) al[tid] = g_alpha[b*PP + tid];
            __syncthreads();
            int c0 = ch*1024 + tid*4;
            const float* base = img + ((long)(g_sort[b]*PP))*ENCD + c0;
            float4 s0 = make_float4(0.f,0.f,0.f,0.f);
            float4 s1 = make_float4(0.f,0.f,0.f,0.f);
            float4 s2 = make_float4(0.f,0.f,0.f,0.f);
            float4 s3 = make_float4(0.f,0.f,0.f,0.f);
            #pragma unroll 7
            for (int p = 0; p < PP; p += 4) {
                float4 v0 = *(const float4*)(base + (long)(p+0)*ENCD);
                float4 v1 = *(const float4*)(base + (long)(p+1)*ENCD);
                float4 v2 = *(const float4*)(base + (long)(p+2)*ENCD);
                float4 v3 = *(const float4*)(base + (long)(p+3)*ENCD);
                float a0 = al[p+0], a1 = al[p+1], a2 = al[p+2], a3 = al[p+3];
                s0.x = fmaf(a0, v0.x, s0.x); s0.y = fmaf(a0, v0.y, s0.y);
                s0.z = fmaf(a0, v0.z, s0.z); s0.w = fmaf(a0, v0.w, s0.w);
                s1.x = fmaf(a1, v1.x, s1.x); s1.y = fmaf(a1, v1.y, s1.y);
                s1.z = fmaf(a1, v1.z, s1.z); s1.w = fmaf(a1, v1.w, s1.w);
                s2.x = fmaf(a2, v2.x, s2.x); s2.y = fmaf(a2, v2.y, s2.y);
                s2.z = fmaf(a2, v2.z, s2.z); s2.w = fmaf(a2, v2.w, s2.w);
                s3.x = fmaf(a3, v3.x, s3.x); s3.y = fmaf(a3, v3.y, s3.y);
                s3.z = fmaf(a3, v3.z, s3.z); s3.w = fmaf(a3, v3.w, s3.w);
            }
            float4 s;
            s.x = (s0.x + s1.x) + (s2.x + s3.x);
            s.y = (s0.y + s1.y) + (s2.y + s3.y);
            s.z = (s0.z + s1.z) + (s2.z + s3.z);
            s.w = (s0.w + s1.w) + (s2.w + s3.w);
            float4 g = *(const float4*)(g_betasig + b*2048 + c0);
            s.x *= g.x; s.y *= g.y; s.z *= g.z; s.w *= g.w;
            *(float4*)(g_x2 + b*2048 + c0) = s;
        }
        gridbar();

        // Ph4: x2 @ W_ih[:,512:]^T (256 tasks: 8 ntiles x SK32 k64)
        for (int task = bid; task < 256; task += GRID) {
            int nt = task >> 5, sk = task & 31;
            gemm32(g_x2, 2048, (const int*)0, 0, W_ih, 2560, 512,
                   2048, nt*256, sk*64, 64, g_pIH + (long)sk*65536, 2048, pool);
        }
        gridbar();

        // Ph5: gate reduce + LSTM pointwise (64 tasks), only active b
        for (int task = bid; task < 64; task += GRID) {
            int b = task >> 1, half = task & 1;
            if (b >= A) continue;
            int j = half*256 + tid;
            float gi = g_gates[b*2048 + j];
            float gf = g_gates[b*2048 + j + 512];
            float gg = g_gates[b*2048 + j + 1024];
            float go = g_gates[b*2048 + j + 1536];
            #pragma unroll
            for (int sk = 0; sk < 32; sk++) {
                const float* p = g_pIH + (long)sk*65536 + b*2048;
                gi += p[j]; gf += p[j + 512]; gg += p[j + 1024]; go += p[j + 1536];
            }
            float c = g_c[b*512 + j];
            float cn = sigm(gf)*c + sigm(gi)*tanhf(gg);
            float hn = sigm(go)*tanhf(cn);
            g_hnall[((long)t*32 + b)*512 + j] = hn;
            g_c[b*512 + j] = cn;
            g_h[b*512 + j] = hn;
        }
        gridbar();
    }

    // ---- epilogue: preds = Hn_all @ W_fc^T + b_fc ----
    for (int task = bid; task < 13*157; task += GRID) {
        int tm = task / 157, tn = task - tm*157;
        fc_task(tm, tn, W_fc, b_fc, out, pool);
    }
}

// ---------------- host launcher ----------------
extern "C" void kernel_launch(void* const* d_in, const int* in_sizes, int n_in,
                              void* d_out, int out_size) {
    persist<<<GRID, 256>>>(
        (const float*)d_in[0],  (const int*)d_in[1],   (const int*)d_in[2],
        (const float*)d_in[3],  (const float*)d_in[4],
        (const float*)d_in[5],  (const float*)d_in[6],
        (const float*)d_in[7],  (const float*)d_in[8],
        (const float*)d_in[9],
        (const float*)d_in[10], (const float*)d_in[11],
        (const float*)d_in[12], (const float*)d_in[13],
        (const float*)d_in[14], (const float*)d_in[15],
        (const float*)d_in[16], (const float*)d_in[17],
        (const float*)d_in[18], (const float*)d_in[19],
        (const float*)d_in[20], (const float*)d_in[21],
        (float*)d_out);
    (void)in_sizes; (void)n_in; (void)out_size;
}

// round 14
// speedup vs baseline: 1.9051x; 1.0371x over previous
#include <cuda_runtime.h>
#include <math.h>

#define BSZ 32
#define PP 196
#define ENCD 2048
#define ATTD 512
#define DECD 512
#define VV 10000
#define LL 52
#define TT 51
#define GRID 296

#define OFF_PRED  0L
#define OFF_TOKS  ((long)BSZ*TT*VV)
#define OFF_DLEN  (OFF_TOKS + (long)BSZ*LL)
#define OFF_ALPHA (OFF_DLEN + (long)BSZ)
#define OFF_SORT  (OFF_ALPHA + (long)BSZ*TT*PP)

// ---------------- static device scratch ----------------
__device__ float g_enc[6272L*512];
__device__ float g_embg[51L*32*2048];
__device__ float g_pDec[16L*32*512];
__device__ float g_pHH[16L*32*2048];
__device__ float g_pBeta[16L*32*2048];
__device__ float g_pIH[32L*32*2048];
__device__ float g_mean[32*2048];
__device__ float g_h[32*512];
__device__ float g_c[32*512];
__device__ float g_hnall[1664L*512];
__device__ float g_gates[32*2048];
__device__ float g_betasig[32*2048];
__device__ float g_x2[32*2048];
__device__ float g_alpha[32*196];
__device__ float g_bcomb[2048];
__device__ int   g_sort[32];
__device__ int   g_dlen[32];
__device__ int   g_act[TT];
__device__ int   g_toks[32*LL];
__device__ unsigned g_barcnt;
__device__ volatile unsigned g_bargen;

__device__ __forceinline__ float sigm(float x) { return 1.f / (1.f + expf(-x)); }

// ---------------- packed f32x2 helpers ----------------
__device__ __forceinline__ unsigned long long pk2dup(float v) {
    unsigned long long r;
    asm("mov.b64 %0, {%1, %1};" : "=l"(r) : "f"(v));
    return r;
}
__device__ __forceinline__ void upk2(unsigned long long v, float& lo, float& hi) {
    asm("mov.b64 {%0, %1}, %2;" : "=f"(lo), "=f"(hi) : "l"(v));
}
__device__ __forceinline__ unsigned long long fma2(unsigned long long a,
                                                   unsigned long long b,
                                                   unsigned long long c) {
    unsigned long long d;
    asm("fma.rn.f32x2 %0, %1, %2, %3;" : "=l"(d) : "l"(a), "l"(b), "l"(c));
    return d;
}

// ---------------- grid-wide software barrier ----------------
__device__ __forceinline__ void gridbar() {
    __syncthreads();
    if (threadIdx.x == 0) {
        __threadfence();
        unsigned gen = g_bargen;
        if (atomicAdd(&g_barcnt, 1u) == GRID - 1) {
            g_barcnt = 0;
            __threadfence();
            g_bargen = gen + 1;
        } else {
            while (g_bargen == gen) { __nanosleep(150); }
        }
        __threadfence();
    }
    __syncthreads();
}

// ---------------- 32-row GEMM partial tile, f32x2 packed FMA ----------------
__device__ void gemm32(const float* __restrict__ X, int ldx,
                       const int* __restrict__ gidx, int gstride,
                       const float* __restrict__ W, int ldw, int wcol0,
                       int Nfull, int nbase, int k0, int klen,
                       float* __restrict__ part, int Nld, float* pool)
{
    float* Xs = pool;                 // 32k x 36
    float* Ws = pool + 1184;          // 32k x 264
    int* roff = (int*)(pool + 1184 + 32*264);
    const int tid = threadIdx.x;
    __syncthreads();
    if (tid < 32) roff[tid] = (gidx ? gidx[tid * gstride] : tid) * ldx;
    __syncthreads();

    const int m0 = (tid >> 5) * 4;
    const int lane4 = (tid & 31) * 4;
    const int xm = tid >> 3, xk = (tid & 7) * 4;
    const int wn = tid >> 3, wk = (tid & 7) * 4;

    unsigned long long accp[4][4];
    #pragma unroll
    for (int i = 0; i < 4; i++)
        #pragma unroll
        for (int j = 0; j < 4; j++) accp[i][j] = 0ull;

    float4 xv = *(const float4*)(X + roff[xm] + k0 + xk);
    float4 wv[8];
    #pragma unroll
    for (int j = 0; j < 8; j++) {
        int ng = nbase + j*32 + wn;
        wv[j] = (ng < Nfull) ? *(const float4*)(W + (long)ng*ldw + wcol0 + k0 + wk)
                             : make_float4(0.f, 0.f, 0.f, 0.f);
    }

    for (int kk = 0; kk < klen; kk += 32) {
        Xs[(xk+0)*36 + xm] = xv.x; Xs[(xk+1)*36 + xm] = xv.y;
        Xs[(xk+2)*36 + xm] = xv.z; Xs[(xk+3)*36 + xm] = xv.w;
        #pragma unroll
        for (int j = 0; j < 8; j++) {
            int n = j*32 + wn;
            Ws[(wk+0)*264 + n] = wv[j].x; Ws[(wk+1)*264 + n] = wv[j].y;
            Ws[(wk+2)*264 + n] = wv[j].z; Ws[(wk+3)*264 + n] = wv[j].w;
        }
        __syncthreads();
        if (kk + 32 < klen) {
            int kc = k0 + kk + 32;
            xv = *(const float4*)(X + roff[xm] + kc + xk);
            #pragma unroll
            for (int j = 0; j < 8; j++) {
                int ng = nbase + j*32 + wn;
                wv[j] = (ng < Nfull) ? *(const float4*)(W + (long)ng*ldw + wcol0 + kc + wk)
                                     : make_float4(0.f, 0.f, 0.f, 0.f);
            }
        }
        #pragma unroll
        for (int k = 0; k < 32; k++) {
            float4 a = *(const float4*)&Xs[k*36 + m0];
            unsigned long long ad[4] = {pk2dup(a.x), pk2dup(a.y), pk2dup(a.z), pk2dup(a.w)};
            ulonglong2 wA = *(const ulonglong2*)&Ws[k*264 + lane4];        // cols (0,1),(2,3)
            ulonglong2 wB = *(const ulonglong2*)&Ws[k*264 + 128 + lane4];  // cols (4,5),(6,7)
            #pragma unroll
            for (int i = 0; i < 4; i++) {
                accp[i][0] = fma2(ad[i], wA.x, accp[i][0]);
                accp[i][1] = fma2(ad[i], wA.y, accp[i][1]);
                accp[i][2] = fma2(ad[i], wB.x, accp[i][2]);
                accp[i][3] = fma2(ad[i], wB.y, accp[i][3]);
            }
        }
        __syncthreads();
    }
    #pragma unroll
    for (int i = 0; i < 4; i++) {
        ulonglong2 o0; o0.x = accp[i][0]; o0.y = accp[i][1];
        ulonglong2 o1; o1.x = accp[i][2]; o1.y = accp[i][3];
        *(ulonglong2*)&part[(long)(m0+i)*Nld + nbase + lane4]       = o0;
        *(ulonglong2*)&part[(long)(m0+i)*Nld + nbase + 128 + lane4] = o1;
    }
}

// ---------------- 128x64 dense tile, K=2048, f32x2: enc_att ----------------
__device__ void enc_task(int tm, int tn, const float* __restrict__ img,
                         const float* __restrict__ W_enc, const float* __restrict__ b_enc,
                         float* pool)
{
    float* As = pool;
    float* Bs = pool + 4224;
    int* rowb = (int*)(pool + 6400);
    const int tid = threadIdx.x;
    __syncthreads();
    if (tid < 128) {
        int rr = tm*128 + tid;
        int b = rr / PP, p = rr - b*PP;
        rowb[tid] = (g_sort[b]*PP + p) * ENCD;
    }
    __syncthreads();
    unsigned long long accp[8][2];
    #pragma unroll
    for (int i = 0; i < 8; i++) { accp[i][0] = 0ull; accp[i][1] = 0ull; }
    const int ty = tid >> 4, tx = tid & 15;
    const int m0 = ty*8, n0 = tx*4;
    const int am = tid >> 3, ak = (tid & 7) * 4;
    const int bn = tid >> 3, bk = (tid & 7) * 4;

    float4 av4[4], bv4[2];
    #pragma unroll
    for (int j = 0; j < 4; j++)
        av4[j] = *(const float4*)(img + rowb[j*32 + am] + ak);
    #pragma unroll
    for (int j = 0; j < 2; j++)
        bv4[j] = *(const float4*)(W_enc + (long)(tn*64 + j*32 + bn)*ENCD + bk);

    for (int kc = 0; kc < ENCD; kc += 32) {
        #pragma unroll
        for (int j = 0; j < 4; j++) {
            int m = j*32 + am;
            As[(ak+0)*132+m] = av4[j].x; As[(ak+1)*132+m] = av4[j].y;
            As[(ak+2)*132+m] = av4[j].z; As[(ak+3)*132+m] = av4[j].w;
        }
        #pragma unroll
        for (int j = 0; j < 2; j++) {
            int n = j*32 + bn;
            Bs[(bk+0)*68+n] = bv4[j].x; Bs[(bk+1)*68+n] = bv4[j].y;
            Bs[(bk+2)*68+n] = bv4[j].z; Bs[(bk+3)*68+n] = bv4[j].w;
        }
        __syncthreads();
        if (kc + 32 < ENCD) {
            #pragma unroll
            for (int j = 0; j < 4; j++)
                av4[j] = *(const float4*)(img + rowb[j*32 + am] + kc + 32 + ak);
            #pragma unroll
            for (int j = 0; j < 2; j++)
                bv4[j] = *(const float4*)(W_enc + (long)(tn*64 + j*32 + bn)*ENCD + kc + 32 + bk);
        }
        #pragma unroll
        for (int k = 0; k < 32; k++) {
            float4 a0 = *(const float4*)&As[k*132 + m0];
            float4 a1 = *(const float4*)&As[k*132 + m0 + 4];
            ulonglong2 bp = *(const ulonglong2*)&Bs[k*68 + n0];
            unsigned long long ad[8] = {pk2dup(a0.x), pk2dup(a0.y), pk2dup(a0.z), pk2dup(a0.w),
                                        pk2dup(a1.x), pk2dup(a1.y), pk2dup(a1.z), pk2dup(a1.w)};
            #pragma unroll
            for (int i = 0; i < 8; i++) {
                accp[i][0] = fma2(ad[i], bp.x, accp[i][0]);
                accp[i][1] = fma2(ad[i], bp.y, accp[i][1]);
            }
        }
        __syncthreads();
    }
    int colb = tn*64 + n0;
    float4 bias = *(const float4*)(b_enc + colb);
    #pragma unroll
    for (int i = 0; i < 8; i++) {
        int row = tm*128 + m0 + i;
        float c0, c1, c2, c3;
        upk2(accp[i][0], c0, c1);
        upk2(accp[i][1], c2, c3);
        float4 o = make_float4(c0 + bias.x, c1 + bias.y, c2 + bias.z, c3 + bias.w);
        *(float4*)&g_enc[(long)row*512 + colb] = o;
    }
}

// ---------------- 128x64 dense tile, K=512, f32x2: final FC ----------------
__device__ void fc_task(int tm, int tn,
                        const float* __restrict__ W_fc, const float* __restrict__ b_fc,
                        float* __restrict__ out, float* pool)
{
    float* As = pool;
    float* Bs = pool + 4224;
    const int tid = threadIdx.x;
    __syncthreads();
    unsigned long long accp[8][2];
    #pragma unroll
    for (int i = 0; i < 8; i++) { accp[i][0] = 0ull; accp[i][1] = 0ull; }
    const int ty = tid >> 4, tx = tid & 15;
    const int m0 = ty*8, n0 = tx*4;
    const int am = tid >> 3, ak = (tid & 7) * 4;
    const int bn = tid >> 3, bk = (tid & 7) * 4;

    float4 av4[4], bv4[2];
    #pragma unroll
    for (int j = 0; j < 4; j++)
        av4[j] = *(const float4*)(g_hnall + (long)(tm*128 + j*32 + am)*512 + ak);
    #pragma unroll
    for (int j = 0; j < 2; j++) {
        int ng = tn*64 + j*32 + bn;
        bv4[j] = (ng < VV) ? *(const float4*)(W_fc + (long)ng*512 + bk)
                           : make_float4(0.f,0.f,0.f,0.f);
    }

    for (int kc = 0; kc < 512; kc += 32) {
        #pragma unroll
        for (int j = 0; j < 4; j++) {
            int m = j*32 + am;
            As[(ak+0)*132+m] = av4[j].x; As[(ak+1)*132+m] = av4[j].y;
            As[(ak+2)*132+m] = av4[j].z; As[(ak+3)*132+m] = av4[j].w;
        }
        #pragma unroll
        for (int j = 0; j < 2; j++) {
            int n = j*32 + bn;
            Bs[(bk+0)*68+n] = bv4[j].x; Bs[(bk+1)*68+n] = bv4[j].y;
            Bs[(bk+2)*68+n] = bv4[j].z; Bs[(bk+3)*68+n] = bv4[j].w;
        }
        __syncthreads();
        if (kc + 32 < 512) {
            #pragma unroll
            for (int j = 0; j < 4; j++)
                av4[j] = *(const float4*)(g_hnall + (long)(tm*128 + j*32 + am)*512 + kc + 32 + ak);
            #pragma unroll
            for (int j = 0; j < 2; j++) {
                int ng = tn*64 + j*32 + bn;
                bv4[j] = (ng < VV) ? *(const float4*)(W_fc + (long)ng*512 + kc + 32 + bk)
                                   : make_float4(0.f,0.f,0.f,0.f);
            }
        }
        #pragma unroll
        for (int k = 0; k < 32; k++) {
            float4 a0 = *(const float4*)&As[k*132 + m0];
            float4 a1 = *(const float4*)&As[k*132 + m0 + 4];
            ulonglong2 bp = *(const ulonglong2*)&Bs[k*68 + n0];
            unsigned long long ad[8] = {pk2dup(a0.x), pk2dup(a0.y), pk2dup(a0.z), pk2dup(a0.w),
                                        pk2dup(a1.x), pk2dup(a1.y), pk2dup(a1.z), pk2dup(a1.w)};
            #pragma unroll
            for (int i = 0; i < 8; i++) {
                accp[i][0] = fma2(ad[i], bp.x, accp[i][0]);
                accp[i][1] = fma2(ad[i], bp.y, accp[i][1]);
            }
        }
        __syncthreads();
    }
    #pragma unroll
    for (int i = 0; i < 8; i++) {
        int r = tm*128 + m0 + i;
        if (r < TT*BSZ) {
            int tt = r >> 5, bb = r & 31;
            bool act = tt < g_dlen[bb];
            long obase = OFF_PRED + ((long)bb*TT + tt)*VV;
            float c[4];
            upk2(accp[i][0], c[0], c[1]);
            upk2(accp[i][1], c[2], c[3]);
            #pragma unroll
            for (int j = 0; j < 4; j++) {
                int col = tn*64 + n0 + j;
                if (col < VV) out[obase + col] = act ? (c[j] + b_fc[col]) : 0.f;
            }
        }
    }
}

// ---------------- attention: reduce pDec + scores (2-row ILP) + softmax ----------------
__device__ void attn_task(int b, int t, const float* __restrict__ b_dec,
                          const float* __restrict__ w_full, const float* __restrict__ b_full,
                          float* __restrict__ out, float* pool)
{
    float* dec_s = pool;
    float* wf    = pool + 512;
    float* sc    = pool + 1024;
    float* red   = pool + 1280;
    const int tid = threadIdx.x;
    __syncthreads();
    for (int a = tid; a < 512; a += 256) {
        float s = b_dec[a];
        #pragma unroll
        for (int sk = 0; sk < 16; sk++) s += g_pDec[sk*16384 + b*512 + a];
        dec_s[a] = s;
        wf[a] = w_full[a];
    }
    __syncthreads();
    int wid = tid >> 5, lane = tid & 31;
    float bf = b_full[0];
    const float* ds = dec_s + lane*16;
    const float* wl = wf + lane*16;
    for (int p = wid; p < PP; p += 16) {
        int p2 = p + 8;
        bool has2 = (p2 < PP);
        const float* er  = g_enc + ((long)b*PP + p)*512 + lane*16;
        const float* er2 = g_enc + ((long)b*PP + (has2 ? p2 : p))*512 + lane*16;
        float s = 0.f, s2v = 0.f;
        #pragma unroll
        for (int q = 0; q < 4; q++) {
            float4 e  = *(const float4*)(er + q*4);
            float4 e2 = *(const float4*)(er2 + q*4);
            float4 d  = *(const float4*)(ds + q*4);
            float4 w  = *(const float4*)(wl + q*4);
            s   = fmaf(fmaxf(e.x + d.x, 0.f), w.x, s);
            s2v = fmaf(fmaxf(e2.x + d.x, 0.f), w.x, s2v);
            s   = fmaf(fmaxf(e.y + d.y, 0.f), w.y, s);
            s2v = fmaf(fmaxf(e2.y + d.y, 0.f), w.y, s2v);
            s   = fmaf(fmaxf(e.z + d.z, 0.f), w.z, s);
            s2v = fmaf(fmaxf(e2.z + d.z, 0.f), w.z, s2v);
            s   = fmaf(fmaxf(e.w + d.w, 0.f), w.w, s);
            s2v = fmaf(fmaxf(e2.w + d.w, 0.f), w.w, s2v);
        }
        #pragma unroll
        for (int off = 16; off > 0; off >>= 1) {
            s   += __shfl_xor_sync(0xffffffffu, s, off);
            s2v += __shfl_xor_sync(0xffffffffu, s2v, off);
        }
        if (lane == 0) {
            sc[p] = s + bf;
            if (has2) sc[p2] = s2v + bf;
        }
    }
    __syncthreads();
    float v = (tid < PP) ? sc[tid] : -3.0e38f;
    red[tid] = v; __syncthreads();
    for (int s2 = 128; s2 > 0; s2 >>= 1) {
        if (tid < s2) red[tid] = fmaxf(red[tid], red[tid + s2]);
        __syncthreads();
    }
    float mx = red[0];
    __syncthreads();
    float ev = (tid < PP) ? expf(sc[tid] - mx) : 0.f;
    red[tid] = ev; __syncthreads();
    for (int s2 = 128; s2 > 0; s2 >>= 1) {
        if (tid < s2) red[tid] += red[tid + s2];
        __syncthreads();
    }
    float inv = 1.f / red[0];
    if (tid < PP) {
        float al = ev * inv;
        g_alpha[b*PP + tid] = al;
        out[OFF_ALPHA + ((long)b*TT + t)*PP + tid] = al;
    }
}

// ---------------- main persistent kernel ----------------
__global__ void __launch_bounds__(256, 2)
persist(const float* __restrict__ img, const int* __restrict__ toks, const int* __restrict__ lens,
        const float* __restrict__ W_enc, const float* __restrict__ b_enc,
        const float* __restrict__ W_dec, const float* __restrict__ b_dec,
        const float* __restrict__ w_full, const float* __restrict__ b_full,
        const float* __restrict__ emb,
        const float* __restrict__ W_ih, const float* __restrict__ b_ih,
        const float* __restrict__ W_hh, const float* __restrict__ b_hh,
        const float* __restrict__ W_h0, const float* __restrict__ b_h0,
        const float* __restrict__ W_c0, const float* __restrict__ b_c0,
        const float* __restrict__ W_beta, const float* __restrict__ b_beta,
        const float* __restrict__ W_fc, const float* __restrict__ b_fc,
        float* __restrict__ out)
{
    __shared__ __align__(16) float pool[9700];
    const int bid = blockIdx.x;
    const int tid = threadIdx.x;

    // ---- P0 ----
    if (bid == 0) {
        if (tid < BSZ) {
            int li = lens[tid];
            int r = 0;
            for (int j = 0; j < BSZ; j++) {
                int lj = lens[j];
                if (lj > li || (lj == li && j < tid)) r++;
            }
            g_sort[r] = tid;
        }
        __syncthreads();
        if (tid < BSZ) {
            int si = g_sort[tid];
            int dl = lens[si] - 1;
            g_dlen[tid] = dl;
            out[OFF_DLEN + tid] = (float)dl;
            out[OFF_SORT + tid] = (float)si;
        }
        __syncthreads();
        if (tid < TT) {
            int a = 0;
            for (int j = 0; j < BSZ; j++) a += (g_dlen[j] > tid) ? 1 : 0;
            g_act[tid] = a;
        }
        for (int idx = tid; idx < BSZ*LL; idx += 256) {
            int b = idx / LL, l = idx - b*LL;
            int tk = toks[g_sort[b]*LL + l];
            g_toks[idx] = tk;
            out[OFF_TOKS + idx] = (float)tk;
        }
    } else if (bid == 1) {
        for (int i = tid; i < 2048; i += 256) g_bcomb[i] = b_ih[i] + b_hh[i];
    } else if (bid == 2) {
        for (int i = tid; i < 32*512; i += 256) g_hnall[1632L*512 + i] = 0.f;
    }
    gridbar();

    // ---- P1: enc_att (392) | embg (408) | mean (32) ----
    for (int task = bid; task < 832; task += GRID) {
        if (task < 392) {
            enc_task(task >> 3, task & 7, img, W_enc, b_enc, pool);
        } else if (task < 800) {
            int id = task - 392;
            int tt = id >> 3, nt = id & 7;
            gemm32(emb, 512, g_toks + tt, LL, W_ih, 2560, 0,
                   2048, nt*256, 0, 512, g_embg + (long)tt*65536, 2048, pool);
        } else {
            int b = task - 800;
            __syncthreads();
            long srow = (long)g_sort[b] * PP * ENCD;
            int e0 = tid * 8;
            float a[8] = {0,0,0,0,0,0,0,0};
            #pragma unroll 4
            for (int p = 0; p < PP; p++) {
                const float* r = img + srow + (long)p*ENCD + e0;
                float4 v0 = *(const float4*)r;
                float4 v1 = *(const float4*)(r + 4);
                a[0]+=v0.x; a[1]+=v0.y; a[2]+=v0.z; a[3]+=v0.w;
                a[4]+=v1.x; a[5]+=v1.y; a[6]+=v1.z; a[7]+=v1.w;
            }
            #pragma unroll
            for (int i = 0; i < 8; i++)
                g_mean[b*2048 + e0 + i] = a[i] * (1.f/196.f);
        }
    }
    gridbar();

    // ---- P2: h0/c0 partials ----
    for (int task = bid; task < 32; task += GRID) {
        int half = task >> 4, nt = (task >> 3) & 1, sk = task & 7;
        gemm32(g_mean, 2048, (const int*)0, 0, half ? W_c0 : W_h0, 2048, 0,
               512, nt*256, sk*256, 256, g_pIH + (long)(half*8 + sk)*16384, 512, pool);
    }
    gridbar();

    // ---- P3: reduce h0/c0 ----
    for (int task = bid; task < 32; task += GRID) {
        int b = task;
        for (int j = tid; j < 512; j += 256) {
            float s = b_h0[j], s2 = b_c0[j];
            #pragma unroll
            for (int s8 = 0; s8 < 8; s8++) {
                s  += g_pIH[s8*16384 + b*512 + j];
                s2 += g_pIH[(8+s8)*16384 + b*512 + j];
            }
            g_h[b*512 + j] = s;
            g_c[b*512 + j] = s2;
        }
    }
    gridbar();

    // ---- decode loop ----
    for (int t = 0; t < TT; t++) {
        const int A = g_act[t];

        // Ph1: dec SK16(32) | hh SK16(128) | beta SK16(128) = 288
        for (int task = bid; task < 288; task += GRID) {
            if (task < 32) {
                int nt = task >> 4, sk = task & 15;
                gemm32(g_h, 512, (const int*)0, 0, W_dec, 512, 0,
                       512, nt*256, sk*32, 32, g_pDec + (long)sk*16384, 512, pool);
            } else if (task < 160) {
                int rid = task - 32, nt = rid >> 4, sk = rid & 15;
                gemm32(g_h, 512, (const int*)0, 0, W_hh, 512, 0,
                       2048, nt*256, sk*32, 32, g_pHH + (long)sk*65536, 2048, pool);
            } else {
                int rid = task - 160, nt = rid >> 4, sk = rid & 15;
                gemm32(g_h, 512, (const int*)0, 0, W_beta, 512, 0,
                       2048, nt*256, sk*32, 32, g_pBeta + (long)sk*65536, 2048, pool);
            }
        }
        gridbar();

        // Ph2: attn(32) | gates-base(32) | beta-sigmoid(64)
        for (int task = bid; task < 128; task += GRID) {
            if (task < 32) {
                int b = task;
                if (b < A) {
                    attn_task(b, t, b_dec, w_full, b_full, out, pool);
                } else if (tid < PP) {
                    out[OFF_ALPHA + ((long)b*TT + t)*PP + tid] = 0.f;
                }
            } else if (task < 64) {
                int b = task - 32;
                if (b >= A) continue;
                int c0 = tid * 8;
                float4 s0 = *(const float4*)(g_bcomb + c0);
                float4 s1 = *(const float4*)(g_bcomb + c0 + 4);
                float4 e0 = *(const float4*)(g_embg + (long)t*65536 + b*2048 + c0);
                float4 e1 = *(const float4*)(g_embg + (long)t*65536 + b*2048 + c0 + 4);
                s0.x+=e0.x; s0.y+=e0.y; s0.z+=e0.z; s0.w+=e0.w;
                s1.x+=e1.x; s1.y+=e1.y; s1.z+=e1.z; s1.w+=e1.w;
                #pragma unroll
                for (int sk = 0; sk < 16; sk++) {
                    float4 p0 = *(const float4*)(g_pHH + (long)sk*65536 + b*2048 + c0);
                    float4 p1 = *(const float4*)(g_pHH + (long)sk*65536 + b*2048 + c0 + 4);
                    s0.x+=p0.x; s0.y+=p0.y; s0.z+=p0.z; s0.w+=p0.w;
                    s1.x+=p1.x; s1.y+=p1.y; s1.z+=p1.z; s1.w+=p1.w;
                }
                *(float4*)(g_gates + b*2048 + c0) = s0;
                *(float4*)(g_gates + b*2048 + c0 + 4) = s1;
            } else {
                int rid = task - 64;
                int b = rid >> 1, half = rid & 1;
                if (b >= A) continue;
                int c0 = half*1024 + tid*4;
                float4 s = *(const float4*)(b_beta + c0);
                #pragma unroll
                for (int sk = 0; sk < 16; sk++) {
                    float4 p = *(const float4*)(g_pBeta + (long)sk*65536 + b*2048 + c0);
                    s.x+=p.x; s.y+=p.y; s.z+=p.z; s.w+=p.w;
                }
                float4 o;
                o.x = sigm(s.x); o.y = sigm(s.y); o.z = sigm(s.z); o.w = sigm(s.w);
                *(float4*)(g_betasig + b*2048 + c0) = o;
            }
        }
        gridbar();

        // Ph3: awe * gate -> x2 (64 tasks), 4 independent accumulator chains
        for (int task = bid; task < 64; task += GRID) {
            int b = task >> 1, ch = task & 1;
            if (b >= A) continue;
            float* al = pool;
            __syncthreads();
            if (tid < PP) al[tid] = g_alpha[b*PP + tid];
            __syncthreads();
            int c0 = ch*1024 + tid*4;
            const float* base = img + ((long)(g_sort[b]*PP))*ENCD + c0;
            float4 s0 = make_float4(0.f,0.f,0.f,0.f);
            float4 s1 = make_float4(0.f,0.f,0.f,0.f);
            float4 s2 = make_float4(0.f,0.f,0.f,0.f);
            float4 s3 = make_float4(0.f,0.f,0.f,0.f);
            #pragma unroll 7
            for (int p = 0; p < PP; p += 4) {
                float4 v0 = *(const float4*)(base + (long)(p+0)*ENCD);
                float4 v1 = *(const float4*)(base + (long)(p+1)*ENCD);
                float4 v2 = *(const float4*)(base + (long)(p+2)*ENCD);
                float4 v3 = *(const float4*)(base + (long)(p+3)*ENCD);
                float a0 = al[p+0], a1 = al[p+1], a2 = al[p+2], a3 = al[p+3];
                s0.x = fmaf(a0, v0.x, s0.x); s0.y = fmaf(a0, v0.y, s0.y);
                s0.z = fmaf(a0, v0.z, s0.z); s0.w = fmaf(a0, v0.w, s0.w);
                s1.x = fmaf(a1, v1.x, s1.x); s1.y = fmaf(a1, v1.y, s1.y);
                s1.z = fmaf(a1, v1.z, s1.z); s1.w = fmaf(a1, v1.w, s1.w);
                s2.x = fmaf(a2, v2.x, s2.x); s2.y = fmaf(a2, v2.y, s2.y);
                s2.z = fmaf(a2, v2.z, s2.z); s2.w = fmaf(a2, v2.w, s2.w);
                s3.x = fmaf(a3, v3.x, s3.x); s3.y = fmaf(a3, v3.y, s3.y);
                s3.z = fmaf(a3, v3.z, s3.z); s3.w = fmaf(a3, v3.w, s3.w);
            }
            float4 s;
            s.x = (s0.x + s1.x) + (s2.x + s3.x);
            s.y = (s0.y + s1.y) + (s2.y + s3.y);
            s.z = (s0.z + s1.z) + (s2.z + s3.z);
            s.w = (s0.w + s1.w) + (s2.w + s3.w);
            float4 g = *(const float4*)(g_betasig + b*2048 + c0);
            s.x *= g.x; s.y *= g.y; s.z *= g.z; s.w *= g.w;
            *(float4*)(g_x2 + b*2048 + c0) = s;
        }
        gridbar();

        // Ph4: x2 @ W_ih[:,512:]^T (256 tasks: 8 ntiles x SK32 k64)
        for (int task = bid; task < 256; task += GRID) {
            int nt = task >> 5, sk = task & 31;
            gemm32(g_x2, 2048, (const int*)0, 0, W_ih, 2560, 512,
                   2048, nt*256, sk*64, 64, g_pIH + (long)sk*65536, 2048, pool);
        }
        gridbar();

        // Ph5: gate reduce + LSTM pointwise (64 tasks), only active b
        for (int task = bid; task < 64; task += GRID) {
            int b = task >> 1, half = task & 1;
            if (b >= A) continue;
            int j = half*256 + tid;
            float gi = g_gates[b*2048 + j];
            float gf = g_gates[b*2048 + j + 512];
            float gg = g_gates[b*2048 + j + 1024];
            float go = g_gates[b*2048 + j + 1536];
            #pragma unroll
            for (int sk = 0; sk < 32; sk++) {
                const float* p = g_pIH + (long)sk*65536 + b*2048;
                gi += p[j]; gf += p[j + 512]; gg += p[j + 1024]; go += p[j + 1536];
            }
            float c = g_c[b*512 + j];
            float cn = sigm(gf)*c + sigm(gi)*tanhf(gg);
            float hn = sigm(go)*tanhf(cn);
            g_hnall[((long)t*32 + b)*512 + j] = hn;
            g_c[b*512 + j] = cn;
            g_h[b*512 + j] = hn;
        }
        gridbar();
    }

    // ---- epilogue: preds = Hn_all @ W_fc^T + b_fc ----
    for (int task = bid; task < 13*157; task += GRID) {
        int tm = task / 157, tn = task - tm*157;
        fc_task(tm, tn, W_fc, b_fc, out, pool);
    }
}

// ---------------- host launcher ----------------
extern "C" void kernel_launch(void* const* d_in, const int* in_sizes, int n_in,
                              void* d_out, int out_size) {
    persist<<<GRID, 256>>>(
        (const float*)d_in[0],  (const int*)d_in[1],   (const int*)d_in[2],
        (const float*)d_in[3],  (const float*)d_in[4],
        (const float*)d_in[5],  (const float*)d_in[6],
        (const float*)d_in[7],  (const float*)d_in[8],
        (const float*)d_in[9],
        (const float*)d_in[10], (const float*)d_in[11],
        (const float*)d_in[12], (const float*)d_in[13],
        (const float*)d_in[14], (const float*)d_in[15],
        (const float*)d_in[16], (const float*)d_in[17],
        (const float*)d_in[18], (const float*)d_in[19],
        (const float*)d_in[20], (const float*)d_in[21],
        (float*)d_out);
    (void)in_sizes; (void)n_in; (void)out_size;
}

// round 15
// speedup vs baseline: 2.1738x; 1.1410x over previous
#include <cuda_runtime.h>
#include <math.h>

#define BSZ 32
#define PP 196
#define ENCD 2048
#define ATTD 512
#define DECD 512
#define VV 10000
#define LL 52
#define TT 51
#define GRID 296

#define OFF_PRED  0L
#define OFF_TOKS  ((long)BSZ*TT*VV)
#define OFF_DLEN  (OFF_TOKS + (long)BSZ*LL)
#define OFF_ALPHA (OFF_DLEN + (long)BSZ)
#define OFF_SORT  (OFF_ALPHA + (long)BSZ*TT*PP)

// ---------------- static device scratch ----------------
__device__ float g_enc[6272L*512];
__device__ float g_embg[51L*32*2048];
__device__ float g_pDec[16L*32*512];
__device__ float g_pHH[16L*32*2048];
__device__ float g_pBeta[16L*32*2048];
__device__ float g_pIH[32L*32*2048];
__device__ float g_mean[32*2048];
__device__ float g_h[32*512];
__device__ float g_c[32*512];
__device__ float g_hnall[1664L*512];
__device__ float g_gates[32*2048];
__device__ float g_betasig[32*2048];
__device__ float g_x2[32*2048];
__device__ float g_sc[32*PP];
__device__ float g_bcomb[2048];
__device__ int   g_sort[32];
__device__ int   g_dlen[32];
__device__ int   g_act[TT];
__device__ int   g_toks[32*LL];
__device__ unsigned g_barcnt;
__device__ volatile unsigned g_bargen;

__device__ __forceinline__ float sigm(float x) { return 1.f / (1.f + expf(-x)); }

// ---------------- packed f32x2 helpers ----------------
__device__ __forceinline__ unsigned long long pk2dup(float v) {
    unsigned long long r;
    asm("mov.b64 %0, {%1, %1};" : "=l"(r) : "f"(v));
    return r;
}
__device__ __forceinline__ void upk2(unsigned long long v, float& lo, float& hi) {
    asm("mov.b64 {%0, %1}, %2;" : "=f"(lo), "=f"(hi) : "l"(v));
}
__device__ __forceinline__ unsigned long long fma2(unsigned long long a,
                                                   unsigned long long b,
                                                   unsigned long long c) {
    unsigned long long d;
    asm("fma.rn.f32x2 %0, %1, %2, %3;" : "=l"(d) : "l"(a), "l"(b), "l"(c));
    return d;
}

// ---------------- grid-wide software barrier ----------------
__device__ __forceinline__ void gridbar() {
    __syncthreads();
    if (threadIdx.x == 0) {
        __threadfence();
        unsigned gen = g_bargen;
        if (atomicAdd(&g_barcnt, 1u) == GRID - 1) {
            g_barcnt = 0;
            __threadfence();
            g_bargen = gen + 1;
        } else {
            while (g_bargen == gen) { __nanosleep(150); }
        }
        __threadfence();
    }
    __syncthreads();
}

// ---------------- 32-row GEMM partial tile, f32x2 packed FMA ----------------
__device__ void gemm32(const float* __restrict__ X, int ldx,
                       const int* __restrict__ gidx, int gstride,
                       const float* __restrict__ W, int ldw, int wcol0,
                       int Nfull, int nbase, int k0, int klen,
                       float* __restrict__ part, int Nld, float* pool)
{
    float* Xs = pool;                 // 32k x 36
    float* Ws = pool + 1184;          // 32k x 264
    int* roff = (int*)(pool + 1184 + 32*264);
    const int tid = threadIdx.x;
    __syncthreads();
    if (tid < 32) roff[tid] = (gidx ? gidx[tid * gstride] : tid) * ldx;
    __syncthreads();

    const int m0 = (tid >> 5) * 4;
    const int lane4 = (tid & 31) * 4;
    const int xm = tid >> 3, xk = (tid & 7) * 4;
    const int wn = tid >> 3, wk = (tid & 7) * 4;

    unsigned long long accp[4][4];
    #pragma unroll
    for (int i = 0; i < 4; i++)
        #pragma unroll
        for (int j = 0; j < 4; j++) accp[i][j] = 0ull;

    float4 xv = *(const float4*)(X + roff[xm] + k0 + xk);
    float4 wv[8];
    #pragma unroll
    for (int j = 0; j < 8; j++) {
        int ng = nbase + j*32 + wn;
        wv[j] = (ng < Nfull) ? *(const float4*)(W + (long)ng*ldw + wcol0 + k0 + wk)
                             : make_float4(0.f, 0.f, 0.f, 0.f);
    }

    for (int kk = 0; kk < klen; kk += 32) {
        Xs[(xk+0)*36 + xm] = xv.x; Xs[(xk+1)*36 + xm] = xv.y;
        Xs[(xk+2)*36 + xm] = xv.z; Xs[(xk+3)*36 + xm] = xv.w;
        #pragma unroll
        for (int j = 0; j < 8; j++) {
            int n = j*32 + wn;
            Ws[(wk+0)*264 + n] = wv[j].x; Ws[(wk+1)*264 + n] = wv[j].y;
            Ws[(wk+2)*264 + n] = wv[j].z; Ws[(wk+3)*264 + n] = wv[j].w;
        }
        __syncthreads();
        if (kk + 32 < klen) {
            int kc = k0 + kk + 32;
            xv = *(const float4*)(X + roff[xm] + kc + xk);
            #pragma unroll
            for (int j = 0; j < 8; j++) {
                int ng = nbase + j*32 + wn;
                wv[j] = (ng < Nfull) ? *(const float4*)(W + (long)ng*ldw + wcol0 + kc + wk)
                                     : make_float4(0.f, 0.f, 0.f, 0.f);
            }
        }
        #pragma unroll
        for (int k = 0; k < 32; k++) {
            float4 a = *(const float4*)&Xs[k*36 + m0];
            unsigned long long ad[4] = {pk2dup(a.x), pk2dup(a.y), pk2dup(a.z), pk2dup(a.w)};
            ulonglong2 wA = *(const ulonglong2*)&Ws[k*264 + lane4];
            ulonglong2 wB = *(const ulonglong2*)&Ws[k*264 + 128 + lane4];
            #pragma unroll
            for (int i = 0; i < 4; i++) {
                accp[i][0] = fma2(ad[i], wA.x, accp[i][0]);
                accp[i][1] = fma2(ad[i], wA.y, accp[i][1]);
                accp[i][2] = fma2(ad[i], wB.x, accp[i][2]);
                accp[i][3] = fma2(ad[i], wB.y, accp[i][3]);
            }
        }
        __syncthreads();
    }
    #pragma unroll
    for (int i = 0; i < 4; i++) {
        ulonglong2 o0; o0.x = accp[i][0]; o0.y = accp[i][1];
        ulonglong2 o1; o1.x = accp[i][2]; o1.y = accp[i][3];
        *(ulonglong2*)&part[(long)(m0+i)*Nld + nbase + lane4]       = o0;
        *(ulonglong2*)&part[(long)(m0+i)*Nld + nbase + 128 + lane4] = o1;
    }
}

// ---------------- 128x64 dense tile, K=2048, f32x2: enc_att ----------------
__device__ void enc_task(int tm, int tn, const float* __restrict__ img,
                         const float* __restrict__ W_enc, const float* __restrict__ b_enc,
                         float* pool)
{
    float* As = pool;
    float* Bs = pool + 4224;
    int* rowb = (int*)(pool + 6400);
    const int tid = threadIdx.x;
    __syncthreads();
    if (tid < 128) {
        int rr = tm*128 + tid;
        int b = rr / PP, p = rr - b*PP;
        rowb[tid] = (g_sort[b]*PP + p) * ENCD;
    }
    __syncthreads();
    unsigned long long accp[8][2];
    #pragma unroll
    for (int i = 0; i < 8; i++) { accp[i][0] = 0ull; accp[i][1] = 0ull; }
    const int ty = tid >> 4, tx = tid & 15;
    const int m0 = ty*8, n0 = tx*4;
    const int am = tid >> 3, ak = (tid & 7) * 4;
    const int bn = tid >> 3, bk = (tid & 7) * 4;

    float4 av4[4], bv4[2];
    #pragma unroll
    for (int j = 0; j < 4; j++)
        av4[j] = *(const float4*)(img + rowb[j*32 + am] + ak);
    #pragma unroll
    for (int j = 0; j < 2; j++)
        bv4[j] = *(const float4*)(W_enc + (long)(tn*64 + j*32 + bn)*ENCD + bk);

    for (int kc = 0; kc < ENCD; kc += 32) {
        #pragma unroll
        for (int j = 0; j < 4; j++) {
            int m = j*32 + am;
            As[(ak+0)*132+m] = av4[j].x; As[(ak+1)*132+m] = av4[j].y;
            As[(ak+2)*132+m] = av4[j].z; As[(ak+3)*132+m] = av4[j].w;
        }
        #pragma unroll
        for (int j = 0; j < 2; j++) {
            int n = j*32 + bn;
            Bs[(bk+0)*68+n] = bv4[j].x; Bs[(bk+1)*68+n] = bv4[j].y;
            Bs[(bk+2)*68+n] = bv4[j].z; Bs[(bk+3)*68+n] = bv4[j].w;
        }
        __syncthreads();
        if (kc + 32 < ENCD) {
            #pragma unroll
            for (int j = 0; j < 4; j++)
                av4[j] = *(const float4*)(img + rowb[j*32 + am] + kc + 32 + ak);
            #pragma unroll
            for (int j = 0; j < 2; j++)
                bv4[j] = *(const float4*)(W_enc + (long)(tn*64 + j*32 + bn)*ENCD + kc + 32 + bk);
        }
        #pragma unroll
        for (int k = 0; k < 32; k++) {
            float4 a0 = *(const float4*)&As[k*132 + m0];
            float4 a1 = *(const float4*)&As[k*132 + m0 + 4];
            ulonglong2 bp = *(const ulonglong2*)&Bs[k*68 + n0];
            unsigned long long ad[8] = {pk2dup(a0.x), pk2dup(a0.y), pk2dup(a0.z), pk2dup(a0.w),
                                        pk2dup(a1.x), pk2dup(a1.y), pk2dup(a1.z), pk2dup(a1.w)};
            #pragma unroll
            for (int i = 0; i < 8; i++) {
                accp[i][0] = fma2(ad[i], bp.x, accp[i][0]);
                accp[i][1] = fma2(ad[i], bp.y, accp[i][1]);
            }
        }
        __syncthreads();
    }
    int colb = tn*64 + n0;
    float4 bias = *(const float4*)(b_enc + colb);
    #pragma unroll
    for (int i = 0; i < 8; i++) {
        int row = tm*128 + m0 + i;
        float c0, c1, c2, c3;
        upk2(accp[i][0], c0, c1);
        upk2(accp[i][1], c2, c3);
        float4 o = make_float4(c0 + bias.x, c1 + bias.y, c2 + bias.z, c3 + bias.w);
        *(float4*)&g_enc[(long)row*512 + colb] = o;
    }
}

// ---------------- 128x64 dense tile, K=512, f32x2: final FC ----------------
__device__ void fc_task(int tm, int tn,
                        const float* __restrict__ W_fc, const float* __restrict__ b_fc,
                        float* __restrict__ out, float* pool)
{
    float* As = pool;
    float* Bs = pool + 4224;
    const int tid = threadIdx.x;
    __syncthreads();
    unsigned long long accp[8][2];
    #pragma unroll
    for (int i = 0; i < 8; i++) { accp[i][0] = 0ull; accp[i][1] = 0ull; }
    const int ty = tid >> 4, tx = tid & 15;
    const int m0 = ty*8, n0 = tx*4;
    const int am = tid >> 3, ak = (tid & 7) * 4;
    const int bn = tid >> 3, bk = (tid & 7) * 4;

    float4 av4[4], bv4[2];
    #pragma unroll
    for (int j = 0; j < 4; j++)
        av4[j] = *(const float4*)(g_hnall + (long)(tm*128 + j*32 + am)*512 + ak);
    #pragma unroll
    for (int j = 0; j < 2; j++) {
        int ng = tn*64 + j*32 + bn;
        bv4[j] = (ng < VV) ? *(const float4*)(W_fc + (long)ng*512 + bk)
                           : make_float4(0.f,0.f,0.f,0.f);
    }

    for (int kc = 0; kc < 512; kc += 32) {
        #pragma unroll
        for (int j = 0; j < 4; j++) {
            int m = j*32 + am;
            As[(ak+0)*132+m] = av4[j].x; As[(ak+1)*132+m] = av4[j].y;
            As[(ak+2)*132+m] = av4[j].z; As[(ak+3)*132+m] = av4[j].w;
        }
        #pragma unroll
        for (int j = 0; j < 2; j++) {
            int n = j*32 + bn;
            Bs[(bk+0)*68+n] = bv4[j].x; Bs[(bk+1)*68+n] = bv4[j].y;
            Bs[(bk+2)*68+n] = bv4[j].z; Bs[(bk+3)*68+n] = bv4[j].w;
        }
        __syncthreads();
        if (kc + 32 < 512) {
            #pragma unroll
            for (int j = 0; j < 4; j++)
                av4[j] = *(const float4*)(g_hnall + (long)(tm*128 + j*32 + am)*512 + kc + 32 + ak);
            #pragma unroll
            for (int j = 0; j < 2; j++) {
                int ng = tn*64 + j*32 + bn;
                bv4[j] = (ng < VV) ? *(const float4*)(W_fc + (long)ng*512 + kc + 32 + bk)
                                   : make_float4(0.f,0.f,0.f,0.f);
            }
        }
        #pragma unroll
        for (int k = 0; k < 32; k++) {
            float4 a0 = *(const float4*)&As[k*132 + m0];
            float4 a1 = *(const float4*)&As[k*132 + m0 + 4];
            ulonglong2 bp = *(const ulonglong2*)&Bs[k*68 + n0];
            unsigned long long ad[8] = {pk2dup(a0.x), pk2dup(a0.y), pk2dup(a0.z), pk2dup(a0.w),
                                        pk2dup(a1.x), pk2dup(a1.y), pk2dup(a1.z), pk2dup(a1.w)};
            #pragma unroll
            for (int i = 0; i < 8; i++) {
                accp[i][0] = fma2(ad[i], bp.x, accp[i][0]);
                accp[i][1] = fma2(ad[i], bp.y, accp[i][1]);
            }
        }
        __syncthreads();
    }
    #pragma unroll
    for (int i = 0; i < 8; i++) {
        int r = tm*128 + m0 + i;
        if (r < TT*BSZ) {
            int tt = r >> 5, bb = r & 31;
            bool act = tt < g_dlen[bb];
            long obase = OFF_PRED + ((long)bb*TT + tt)*VV;
            float c[4];
            upk2(accp[i][0], c[0], c[1]);
            upk2(accp[i][1], c[2], c[3]);
            #pragma unroll
            for (int j = 0; j < 4; j++) {
                int col = tn*64 + n0 + j;
                if (col < VV) out[obase + col] = act ? (c[j] + b_fc[col]) : 0.f;
            }
        }
    }
}

// ---------------- score task: raw attention scores for p-half ----------------
__device__ void score_task(int b, int ph, const float* __restrict__ b_dec,
                           const float* __restrict__ w_full, const float* __restrict__ b_full,
                           float* pool)
{
    float* dec_s = pool;
    float* wf    = pool + 512;
    const int tid = threadIdx.x;
    __syncthreads();
    for (int a = tid; a < 512; a += 256) {
        float s = b_dec[a];
        #pragma unroll
        for (int sk = 0; sk < 16; sk++) s += g_pDec[sk*16384 + b*512 + a];
        dec_s[a] = s;
        wf[a] = w_full[a];
    }
    __syncthreads();
    int wid = tid >> 5, lane = tid & 31;
    float bf = b_full[0];
    const float* ds = dec_s + lane*16;
    const float* wl = wf + lane*16;
    const int pbeg = ph * 98, pend = pbeg + 98;
    for (int p = pbeg + wid; p < pend; p += 16) {
        int p2 = p + 8;
        bool has2 = (p2 < pend);
        const float* er  = g_enc + ((long)b*PP + p)*512 + lane*16;
        const float* er2 = g_enc + ((long)b*PP + (has2 ? p2 : p))*512 + lane*16;
        float s = 0.f, s2v = 0.f;
        #pragma unroll
        for (int q = 0; q < 4; q++) {
            float4 e  = *(const float4*)(er + q*4);
            float4 e2 = *(const float4*)(er2 + q*4);
            float4 d  = *(const float4*)(ds + q*4);
            float4 w  = *(const float4*)(wl + q*4);
            s   = fmaf(fmaxf(e.x + d.x, 0.f), w.x, s);
            s2v = fmaf(fmaxf(e2.x + d.x, 0.f), w.x, s2v);
            s   = fmaf(fmaxf(e.y + d.y, 0.f), w.y, s);
            s2v = fmaf(fmaxf(e2.y + d.y, 0.f), w.y, s2v);
            s   = fmaf(fmaxf(e.z + d.z, 0.f), w.z, s);
            s2v = fmaf(fmaxf(e2.z + d.z, 0.f), w.z, s2v);
            s   = fmaf(fmaxf(e.w + d.w, 0.f), w.w, s);
            s2v = fmaf(fmaxf(e2.w + d.w, 0.f), w.w, s2v);
        }
        #pragma unroll
        for (int off = 16; off > 0; off >>= 1) {
            s   += __shfl_xor_sync(0xffffffffu, s, off);
            s2v += __shfl_xor_sync(0xffffffffu, s2v, off);
        }
        if (lane == 0) {
            g_sc[b*PP + p] = s + bf;
            if (has2) g_sc[b*PP + p2] = s2v + bf;
        }
    }
}

// ---------------- awe task: local softmax + img scan (512 cols, float2) ----------------
__device__ void awe_task(int b, int ch, int t, const float* __restrict__ img,
                         float* __restrict__ out, float* pool)
{
    float* sc  = pool;          // 256
    float* red = pool + 256;    // 256
    float* al  = pool + 512;    // 256
    const int tid = threadIdx.x;
    __syncthreads();
    float v = (tid < PP) ? g_sc[b*PP + tid] : -3.0e38f;
    if (tid < PP) sc[tid] = v;
    red[tid] = v; __syncthreads();
    for (int s2 = 128; s2 > 0; s2 >>= 1) {
        if (tid < s2) red[tid] = fmaxf(red[tid], red[tid + s2]);
        __syncthreads();
    }
    float mx = red[0];
    __syncthreads();
    float ev = (tid < PP) ? expf(sc[tid] - mx) : 0.f;
    red[tid] = ev; __syncthreads();
    for (int s2 = 128; s2 > 0; s2 >>= 1) {
        if (tid < s2) red[tid] += red[tid + s2];
        __syncthreads();
    }
    float inv = 1.f / red[0];
    float alv = ev * inv;
    if (tid < PP) al[tid] = alv;
    if (ch == 0 && tid < PP)
        out[OFF_ALPHA + ((long)b*TT + t)*PP + tid] = alv;
    __syncthreads();

    int c0 = ch*512 + tid*2;
    const float* base = img + ((long)(g_sort[b]*PP))*ENCD + c0;
    float2 s0 = make_float2(0.f,0.f), s1 = make_float2(0.f,0.f);
    float2 s2 = make_float2(0.f,0.f), s3 = make_float2(0.f,0.f);
    #pragma unroll 7
    for (int p = 0; p < PP; p += 4) {
        float2 v0 = *(const float2*)(base + (long)(p+0)*ENCD);
        float2 v1 = *(const float2*)(base + (long)(p+1)*ENCD);
        float2 v2 = *(const float2*)(base + (long)(p+2)*ENCD);
        float2 v3 = *(const float2*)(base + (long)(p+3)*ENCD);
        float a0 = al[p+0], a1 = al[p+1], a2 = al[p+2], a3 = al[p+3];
        s0.x = fmaf(a0, v0.x, s0.x); s0.y = fmaf(a0, v0.y, s0.y);
        s1.x = fmaf(a1, v1.x, s1.x); s1.y = fmaf(a1, v1.y, s1.y);
        s2.x = fmaf(a2, v2.x, s2.x); s2.y = fmaf(a2, v2.y, s2.y);
        s3.x = fmaf(a3, v3.x, s3.x); s3.y = fmaf(a3, v3.y, s3.y);
    }
    float2 s;
    s.x = (s0.x + s1.x) + (s2.x + s3.x);
    s.y = (s0.y + s1.y) + (s2.y + s3.y);
    float2 g = *(const float2*)(g_betasig + b*2048 + c0);
    s.x *= g.x; s.y *= g.y;
    *(float2*)(g_x2 + b*2048 + c0) = s;
}

// ---------------- main persistent kernel ----------------
__global__ void __launch_bounds__(256, 2)
persist(const float* __restrict__ img, const int* __restrict__ toks, const int* __restrict__ lens,
        const float* __restrict__ W_enc, const float* __restrict__ b_enc,
        const float* __restrict__ W_dec, const float* __restrict__ b_dec,
        const float* __restrict__ w_full, const float* __restrict__ b_full,
        const float* __restrict__ emb,
        const float* __restrict__ W_ih, const float* __restrict__ b_ih,
        const float* __restrict__ W_hh, const float* __restrict__ b_hh,
        const float* __restrict__ W_h0, const float* __restrict__ b_h0,
        const float* __restrict__ W_c0, const float* __restrict__ b_c0,
        const float* __restrict__ W_beta, const float* __restrict__ b_beta,
        const float* __restrict__ W_fc, const float* __restrict__ b_fc,
        float* __restrict__ out)
{
    __shared__ __align__(16) float pool[9700];
    const int bid = blockIdx.x;
    const int tid = threadIdx.x;

    // ---- P0 ----
    if (bid == 0) {
        if (tid < BSZ) {
            int li = lens[tid];
            int r = 0;
            for (int j = 0; j < BSZ; j++) {
                int lj = lens[j];
                if (lj > li || (lj == li && j < tid)) r++;
            }
            g_sort[r] = tid;
        }
        __syncthreads();
        if (tid < BSZ) {
            int si = g_sort[tid];
            int dl = lens[si] - 1;
            g_dlen[tid] = dl;
            out[OFF_DLEN + tid] = (float)dl;
            out[OFF_SORT + tid] = (float)si;
        }
        __syncthreads();
        if (tid < TT) {
            int a = 0;
            for (int j = 0; j < BSZ; j++) a += (g_dlen[j] > tid) ? 1 : 0;
            g_act[tid] = a;
        }
        for (int idx = tid; idx < BSZ*LL; idx += 256) {
            int b = idx / LL, l = idx - b*LL;
            int tk = toks[g_sort[b]*LL + l];
            g_toks[idx] = tk;
            out[OFF_TOKS + idx] = (float)tk;
        }
    } else if (bid == 1) {
        for (int i = tid; i < 2048; i += 256) g_bcomb[i] = b_ih[i] + b_hh[i];
    } else if (bid == 2) {
        for (int i = tid; i < 32*512; i += 256) g_hnall[1632L*512 + i] = 0.f;
    }
    gridbar();

    // ---- P1: enc_att (392) | embg (408) | mean (32) ----
    for (int task = bid; task < 832; task += GRID) {
        if (task < 392) {
            enc_task(task >> 3, task & 7, img, W_enc, b_enc, pool);
        } else if (task < 800) {
            int id = task - 392;
            int tt = id >> 3, nt = id & 7;
            gemm32(emb, 512, g_toks + tt, LL, W_ih, 2560, 0,
                   2048, nt*256, 0, 512, g_embg + (long)tt*65536, 2048, pool);
        } else {
            int b = task - 800;
            __syncthreads();
            long srow = (long)g_sort[b] * PP * ENCD;
            int e0 = tid * 8;
            float a[8] = {0,0,0,0,0,0,0,0};
            #pragma unroll 4
            for (int p = 0; p < PP; p++) {
                const float* r = img + srow + (long)p*ENCD + e0;
                float4 v0 = *(const float4*)r;
                float4 v1 = *(const float4*)(r + 4);
                a[0]+=v0.x; a[1]+=v0.y; a[2]+=v0.z; a[3]+=v0.w;
                a[4]+=v1.x; a[5]+=v1.y; a[6]+=v1.z; a[7]+=v1.w;
            }
            #pragma unroll
            for (int i = 0; i < 8; i++)
                g_mean[b*2048 + e0 + i] = a[i] * (1.f/196.f);
        }
    }
    gridbar();

    // ---- P2: h0/c0 partials ----
    for (int task = bid; task < 32; task += GRID) {
        int half = task >> 4, nt = (task >> 3) & 1, sk = task & 7;
        gemm32(g_mean, 2048, (const int*)0, 0, half ? W_c0 : W_h0, 2048, 0,
               512, nt*256, sk*256, 256, g_pIH + (long)(half*8 + sk)*16384, 512, pool);
    }
    gridbar();

    // ---- P3: reduce h0/c0 ----
    for (int task = bid; task < 32; task += GRID) {
        int b = task;
        for (int j = tid; j < 512; j += 256) {
            float s = b_h0[j], s2 = b_c0[j];
            #pragma unroll
            for (int s8 = 0; s8 < 8; s8++) {
                s  += g_pIH[s8*16384 + b*512 + j];
                s2 += g_pIH[(8+s8)*16384 + b*512 + j];
            }
            g_h[b*512 + j] = s;
            g_c[b*512 + j] = s2;
        }
    }
    gridbar();

    // ---- decode loop ----
    for (int t = 0; t < TT; t++) {
        const int A = g_act[t];

        // Ph1: dec SK16(32) | hh SK16(128) | beta SK16(128) = 288
        for (int task = bid; task < 288; task += GRID) {
            if (task < 32) {
                int nt = task >> 4, sk = task & 15;
                gemm32(g_h, 512, (const int*)0, 0, W_dec, 512, 0,
                       512, nt*256, sk*32, 32, g_pDec + (long)sk*16384, 512, pool);
            } else if (task < 160) {
                int rid = task - 32, nt = rid >> 4, sk = rid & 15;
                gemm32(g_h, 512, (const int*)0, 0, W_hh, 512, 0,
                       2048, nt*256, sk*32, 32, g_pHH + (long)sk*65536, 2048, pool);
            } else {
                int rid = task - 160, nt = rid >> 4, sk = rid & 15;
                gemm32(g_h, 512, (const int*)0, 0, W_beta, 512, 0,
                       2048, nt*256, sk*32, 32, g_pBeta + (long)sk*65536, 2048, pool);
            }
        }
        gridbar();

        // Ph2: scores (64: b x 2 p-halves) | gates-base(32) | beta-sigmoid(64) = 160
        for (int task = bid; task < 160; task += GRID) {
            if (task < 64) {
                int b = task >> 1, ph = task & 1;
                if (b < A) {
                    score_task(b, ph, b_dec, w_full, b_full, pool);
                } else if (ph == 0 && tid < PP) {
                    out[OFF_ALPHA + ((long)b*TT + t)*PP + tid] = 0.f;
                }
            } else if (task < 96) {
                int b = task - 64;
                if (b >= A) continue;
                int c0 = tid * 8;
                float4 s0 = *(const float4*)(g_bcomb + c0);
                float4 s1 = *(const float4*)(g_bcomb + c0 + 4);
                float4 e0 = *(const float4*)(g_embg + (long)t*65536 + b*2048 + c0);
                float4 e1 = *(const float4*)(g_embg + (long)t*65536 + b*2048 + c0 + 4);
                s0.x+=e0.x; s0.y+=e0.y; s0.z+=e0.z; s0.w+=e0.w;
                s1.x+=e1.x; s1.y+=e1.y; s1.z+=e1.z; s1.w+=e1.w;
                #pragma unroll
                for (int sk = 0; sk < 16; sk++) {
                    float4 p0 = *(const float4*)(g_pHH + (long)sk*65536 + b*2048 + c0);
                    float4 p1 = *(const float4*)(g_pHH + (long)sk*65536 + b*2048 + c0 + 4);
                    s0.x+=p0.x; s0.y+=p0.y; s0.z+=p0.z; s0.w+=p0.w;
                    s1.x+=p1.x; s1.y+=p1.y; s1.z+=p1.z; s1.w+=p1.w;
                }
                *(float4*)(g_gates + b*2048 + c0) = s0;
                *(float4*)(g_gates + b*2048 + c0 + 4) = s1;
            } else {
                int rid = task - 96;
                int b = rid >> 1, half = rid & 1;
                if (b >= A) continue;
                int c0 = half*1024 + tid*4;
                float4 s = *(const float4*)(b_beta + c0);
                #pragma unroll
                for (int sk = 0; sk < 16; sk++) {
                    float4 p = *(const float4*)(g_pBeta + (long)sk*65536 + b*2048 + c0);
                    s.x+=p.x; s.y+=p.y; s.z+=p.z; s.w+=p.w;
                }
                float4 o;
                o.x = sigm(s.x); o.y = sigm(s.y); o.z = sigm(s.z); o.w = sigm(s.w);
                *(float4*)(g_betasig + b*2048 + c0) = o;
            }
        }
        gridbar();

        // Ph3: awe (128: b x 4 chunks of 512 cols), local softmax, only active b
        for (int task = bid; task < 128; task += GRID) {
            int b = task >> 2, ch = task & 3;
            if (b >= A) continue;
            awe_task(b, ch, t, img, out, pool);
        }
        gridbar();

        // Ph4: x2 @ W_ih[:,512:]^T (256 tasks: 8 ntiles x SK32 k64)
        for (int task = bid; task < 256; task += GRID) {
            int nt = task >> 5, sk = task & 31;
            gemm32(g_x2, 2048, (const int*)0, 0, W_ih, 2560, 512,
                   2048, nt*256, sk*64, 64, g_pIH + (long)sk*65536, 2048, pool);
        }
        gridbar();

        // Ph5: gate reduce + LSTM pointwise (64 tasks), only active b
        for (int task = bid; task < 64; task += GRID) {
            int b = task >> 1, half = task & 1;
            if (b >= A) continue;
            int j = half*256 + tid;
            float gi = g_gates[b*2048 + j];
            float gf = g_gates[b*2048 + j + 512];
            float gg = g_gates[b*2048 + j + 1024];
            float go = g_gates[b*2048 + j + 1536];
            #pragma unroll
            for (int sk = 0; sk < 32; sk++) {
                const float* p = g_pIH + (long)sk*65536 + b*2048;
                gi += p[j]; gf += p[j + 512]; gg += p[j + 1024]; go += p[j + 1536];
            }
            float c = g_c[b*512 + j];
            float cn = sigm(gf)*c + sigm(gi)*tanhf(gg);
            float hn = sigm(go)*tanhf(cn);
            g_hnall[((long)t*32 + b)*512 + j] = hn;
            g_c[b*512 + j] = cn;
            g_h[b*512 + j] = hn;
        }
        gridbar();
    }

    // ---- epilogue: preds = Hn_all @ W_fc^T + b_fc ----
    for (int task = bid; task < 13*157; task += GRID) {
        int tm = task / 157, tn = task - tm*157;
        fc_task(tm, tn, W_fc, b_fc, out, pool);
    }
}

// ---------------- host launcher ----------------
extern "C" void kernel_launch(void* const* d_in, const int* in_sizes, int n_in,
                              void* d_out, int out_size) {
    persist<<<GRID, 256>>>(
        (const float*)d_in[0],  (const int*)d_in[1],   (const int*)d_in[2],
        (const float*)d_in[3],  (const float*)d_in[4],
        (const float*)d_in[5],  (const float*)d_in[6],
        (const float*)d_in[7],  (const float*)d_in[8],
        (const float*)d_in[9],
        (const float*)d_in[10], (const float*)d_in[11],
        (const float*)d_in[12], (const float*)d_in[13],
        (const float*)d_in[14], (const float*)d_in[15],
        (const float*)d_in[16], (const float*)d_in[17],
        (const float*)d_in[18], (const float*)d_in[19],
        (const float*)d_in[20], (const float*)d_in[21],
        (float*)d_out);
    (void)in_sizes; (void)n_in; (void)out_size;
}

// round 16
// speedup vs baseline: 2.2696x; 1.0441x over previous
#include <cuda_runtime.h>
#include <math.h>

#define BSZ 32
#define PP 196
#define ENCD 2048
#define ATTD 512
#define DECD 512
#define VV 10000
#define LL 52
#define TT 51
#define GRID 296

#define OFF_PRED  0L
#define OFF_TOKS  ((long)BSZ*TT*VV)
#define OFF_DLEN  (OFF_TOKS + (long)BSZ*LL)
#define OFF_ALPHA (OFF_DLEN + (long)BSZ)
#define OFF_SORT  (OFF_ALPHA + (long)BSZ*TT*PP)

// ---------------- static device scratch ----------------
__device__ float g_enc[6272L*512];
__device__ float g_embg[51L*32*2048];
__device__ float g_pDec[16L*32*512];
__device__ float g_pHH[16L*32*2048];
__device__ float g_pBeta[16L*32*2048];
__device__ float g_pIH[32L*32*2048];
__device__ float g_mean[32*2048];
__device__ float g_h[32*512];
__device__ float g_c[32*512];
__device__ float g_hnall[1664L*512];
__device__ float g_gates[32*2048];
__device__ float g_betasig[32*2048];
__device__ float g_x2[32*2048];
__device__ float g_sc[32*PP];
__device__ float g_bcomb[2048];
__device__ int   g_sort[32];
__device__ int   g_dlen[32];
__device__ int   g_act[TT];
__device__ int   g_toks[32*LL];
__device__ unsigned g_barcnt;
__device__ volatile unsigned g_bargen;

__device__ __forceinline__ float sigm(float x) { return 1.f / (1.f + expf(-x)); }

// ---------------- packed f32x2 helpers ----------------
__device__ __forceinline__ unsigned long long pk2dup(float v) {
    unsigned long long r;
    asm("mov.b64 %0, {%1, %1};" : "=l"(r) : "f"(v));
    return r;
}
__device__ __forceinline__ void upk2(unsigned long long v, float& lo, float& hi) {
    asm("mov.b64 {%0, %1}, %2;" : "=f"(lo), "=f"(hi) : "l"(v));
}
__device__ __forceinline__ unsigned long long fma2(unsigned long long a,
                                                   unsigned long long b,
                                                   unsigned long long c) {
    unsigned long long d;
    asm("fma.rn.f32x2 %0, %1, %2, %3;" : "=l"(d) : "l"(a), "l"(b), "l"(c));
    return d;
}

// ---------------- grid-wide software barrier ----------------
__device__ __forceinline__ void gridbar() {
    __syncthreads();
    if (threadIdx.x == 0) {
        __threadfence();
        unsigned gen = g_bargen;
        if (atomicAdd(&g_barcnt, 1u) == GRID - 1) {
            g_barcnt = 0;
            __threadfence();
            g_bargen = gen + 1;
        } else {
            while (g_bargen == gen) { __nanosleep(150); }
        }
        __threadfence();
    }
    __syncthreads();
}

// ---------------- 32-row GEMM partial tile, f32x2 packed FMA ----------------
__device__ void gemm32(const float* __restrict__ X, int ldx,
                       const int* __restrict__ gidx, int gstride,
                       const float* __restrict__ W, int ldw, int wcol0,
                       int Nfull, int nbase, int k0, int klen,
                       float* __restrict__ part, int Nld, float* pool)
{
    float* Xs = pool;                 // 32k x 36
    float* Ws = pool + 1184;          // 32k x 264
    int* roff = (int*)(pool + 1184 + 32*264);
    const int tid = threadIdx.x;
    __syncthreads();
    if (tid < 32) roff[tid] = (gidx ? gidx[tid * gstride] : tid) * ldx;
    __syncthreads();

    const int m0 = (tid >> 5) * 4;
    const int lane4 = (tid & 31) * 4;
    const int xm = tid >> 3, xk = (tid & 7) * 4;
    const int wn = tid >> 3, wk = (tid & 7) * 4;

    unsigned long long accp[4][4];
    #pragma unroll
    for (int i = 0; i < 4; i++)
        #pragma unroll
        for (int j = 0; j < 4; j++) accp[i][j] = 0ull;

    float4 xv = *(const float4*)(X + roff[xm] + k0 + xk);
    float4 wv[8];
    #pragma unroll
    for (int j = 0; j < 8; j++) {
        int ng = nbase + j*32 + wn;
        wv[j] = (ng < Nfull) ? *(const float4*)(W + (long)ng*ldw + wcol0 + k0 + wk)
                             : make_float4(0.f, 0.f, 0.f, 0.f);
    }

    for (int kk = 0; kk < klen; kk += 32) {
        Xs[(xk+0)*36 + xm] = xv.x; Xs[(xk+1)*36 + xm] = xv.y;
        Xs[(xk+2)*36 + xm] = xv.z; Xs[(xk+3)*36 + xm] = xv.w;
        #pragma unroll
        for (int j = 0; j < 8; j++) {
            int n = j*32 + wn;
            Ws[(wk+0)*264 + n] = wv[j].x; Ws[(wk+1)*264 + n] = wv[j].y;
            Ws[(wk+2)*264 + n] = wv[j].z; Ws[(wk+3)*264 + n] = wv[j].w;
        }
        __syncthreads();
        if (kk + 32 < klen) {
            int kc = k0 + kk + 32;
            xv = *(const float4*)(X + roff[xm] + kc + xk);
            #pragma unroll
            for (int j = 0; j < 8; j++) {
                int ng = nbase + j*32 + wn;
                wv[j] = (ng < Nfull) ? *(const float4*)(W + (long)ng*ldw + wcol0 + kc + wk)
                                     : make_float4(0.f, 0.f, 0.f, 0.f);
            }
        }
        #pragma unroll
        for (int k = 0; k < 32; k++) {
            float4 a = *(const float4*)&Xs[k*36 + m0];
            unsigned long long ad[4] = {pk2dup(a.x), pk2dup(a.y), pk2dup(a.z), pk2dup(a.w)};
            ulonglong2 wA = *(const ulonglong2*)&Ws[k*264 + lane4];
            ulonglong2 wB = *(const ulonglong2*)&Ws[k*264 + 128 + lane4];
            #pragma unroll
            for (int i = 0; i < 4; i++) {
                accp[i][0] = fma2(ad[i], wA.x, accp[i][0]);
                accp[i][1] = fma2(ad[i], wA.y, accp[i][1]);
                accp[i][2] = fma2(ad[i], wB.x, accp[i][2]);
                accp[i][3] = fma2(ad[i], wB.y, accp[i][3]);
            }
        }
        __syncthreads();
    }
    #pragma unroll
    for (int i = 0; i < 4; i++) {
        ulonglong2 o0; o0.x = accp[i][0]; o0.y = accp[i][1];
        ulonglong2 o1; o1.x = accp[i][2]; o1.y = accp[i][3];
        *(ulonglong2*)&part[(long)(m0+i)*Nld + nbase + lane4]       = o0;
        *(ulonglong2*)&part[(long)(m0+i)*Nld + nbase + 128 + lane4] = o1;
    }
}

// ---------------- 128x64 dense tile, K=2048, f32x2: enc_att ----------------
__device__ void enc_task(int tm, int tn, const float* __restrict__ img,
                         const float* __restrict__ W_enc, const float* __restrict__ b_enc,
                         float* pool)
{
    float* As = pool;
    float* Bs = pool + 4224;
    int* rowb = (int*)(pool + 6400);
    const int tid = threadIdx.x;
    __syncthreads();
    if (tid < 128) {
        int rr = tm*128 + tid;
        int b = rr / PP, p = rr - b*PP;
        rowb[tid] = (g_sort[b]*PP + p) * ENCD;
    }
    __syncthreads();
    unsigned long long accp[8][2];
    #pragma unroll
    for (int i = 0; i < 8; i++) { accp[i][0] = 0ull; accp[i][1] = 0ull; }
    const int ty = tid >> 4, tx = tid & 15;
    const int m0 = ty*8, n0 = tx*4;
    const int am = tid >> 3, ak = (tid & 7) * 4;
    const int bn = tid >> 3, bk = (tid & 7) * 4;

    float4 av4[4], bv4[2];
    #pragma unroll
    for (int j = 0; j < 4; j++)
        av4[j] = *(const float4*)(img + rowb[j*32 + am] + ak);
    #pragma unroll
    for (int j = 0; j < 2; j++)
        bv4[j] = *(const float4*)(W_enc + (long)(tn*64 + j*32 + bn)*ENCD + bk);

    for (int kc = 0; kc < ENCD; kc += 32) {
        #pragma unroll
        for (int j = 0; j < 4; j++) {
            int m = j*32 + am;
            As[(ak+0)*132+m] = av4[j].x; As[(ak+1)*132+m] = av4[j].y;
            As[(ak+2)*132+m] = av4[j].z; As[(ak+3)*132+m] = av4[j].w;
        }
        #pragma unroll
        for (int j = 0; j < 2; j++) {
            int n = j*32 + bn;
            Bs[(bk+0)*68+n] = bv4[j].x; Bs[(bk+1)*68+n] = bv4[j].y;
            Bs[(bk+2)*68+n] = bv4[j].z; Bs[(bk+3)*68+n] = bv4[j].w;
        }
        __syncthreads();
        if (kc + 32 < ENCD) {
            #pragma unroll
            for (int j = 0; j < 4; j++)
                av4[j] = *(const float4*)(img + rowb[j*32 + am] + kc + 32 + ak);
            #pragma unroll
            for (int j = 0; j < 2; j++)
                bv4[j] = *(const float4*)(W_enc + (long)(tn*64 + j*32 + bn)*ENCD + kc + 32 + bk);
        }
        #pragma unroll
        for (int k = 0; k < 32; k++) {
            float4 a0 = *(const float4*)&As[k*132 + m0];
            float4 a1 = *(const float4*)&As[k*132 + m0 + 4];
            ulonglong2 bp = *(const ulonglong2*)&Bs[k*68 + n0];
            unsigned long long ad[8] = {pk2dup(a0.x), pk2dup(a0.y), pk2dup(a0.z), pk2dup(a0.w),
                                        pk2dup(a1.x), pk2dup(a1.y), pk2dup(a1.z), pk2dup(a1.w)};
            #pragma unroll
            for (int i = 0; i < 8; i++) {
                accp[i][0] = fma2(ad[i], bp.x, accp[i][0]);
                accp[i][1] = fma2(ad[i], bp.y, accp[i][1]);
            }
        }
        __syncthreads();
    }
    int colb = tn*64 + n0;
    float4 bias = *(const float4*)(b_enc + colb);
    #pragma unroll
    for (int i = 0; i < 8; i++) {
        int row = tm*128 + m0 + i;
        float c0, c1, c2, c3;
        upk2(accp[i][0], c0, c1);
        upk2(accp[i][1], c2, c3);
        float4 o = make_float4(c0 + bias.x, c1 + bias.y, c2 + bias.z, c3 + bias.w);
        *(float4*)&g_enc[(long)row*512 + colb] = o;
    }
}

// ---------------- 128x64 dense tile, K=512, f32x2: final FC ----------------
__device__ void fc_task(int tm, int tn,
                        const float* __restrict__ W_fc, const float* __restrict__ b_fc,
                        float* __restrict__ out, float* pool)
{
    float* As = pool;
    float* Bs = pool + 4224;
    const int tid = threadIdx.x;
    __syncthreads();
    unsigned long long accp[8][2];
    #pragma unroll
    for (int i = 0; i < 8; i++) { accp[i][0] = 0ull; accp[i][1] = 0ull; }
    const int ty = tid >> 4, tx = tid & 15;
    const int m0 = ty*8, n0 = tx*4;
    const int am = tid >> 3, ak = (tid & 7) * 4;
    const int bn = tid >> 3, bk = (tid & 7) * 4;

    float4 av4[4], bv4[2];
    #pragma unroll
    for (int j = 0; j < 4; j++)
        av4[j] = *(const float4*)(g_hnall + (long)(tm*128 + j*32 + am)*512 + ak);
    #pragma unroll
    for (int j = 0; j < 2; j++) {
        int ng = tn*64 + j*32 + bn;
        bv4[j] = (ng < VV) ? *(const float4*)(W_fc + (long)ng*512 + bk)
                           : make_float4(0.f,0.f,0.f,0.f);
    }

    for (int kc = 0; kc < 512; kc += 32) {
        #pragma unroll
        for (int j = 0; j < 4; j++) {
            int m = j*32 + am;
            As[(ak+0)*132+m] = av4[j].x; As[(ak+1)*132+m] = av4[j].y;
            As[(ak+2)*132+m] = av4[j].z; As[(ak+3)*132+m] = av4[j].w;
        }
        #pragma unroll
        for (int j = 0; j < 2; j++) {
            int n = j*32 + bn;
            Bs[(bk+0)*68+n] = bv4[j].x; Bs[(bk+1)*68+n] = bv4[j].y;
            Bs[(bk+2)*68+n] = bv4[j].z; Bs[(bk+3)*68+n] = bv4[j].w;
        }
        __syncthreads();
        if (kc + 32 < 512) {
            #pragma unroll
            for (int j = 0; j < 4; j++)
                av4[j] = *(const float4*)(g_hnall + (long)(tm*128 + j*32 + am)*512 + kc + 32 + ak);
            #pragma unroll
            for (int j = 0; j < 2; j++) {
                int ng = tn*64 + j*32 + bn;
                bv4[j] = (ng < VV) ? *(const float4*)(W_fc + (long)ng*512 + kc + 32 + bk)
                                   : make_float4(0.f,0.f,0.f,0.f);
            }
        }
        #pragma unroll
        for (int k = 0; k < 32; k++) {
            float4 a0 = *(const float4*)&As[k*132 + m0];
            float4 a1 = *(const float4*)&As[k*132 + m0 + 4];
            ulonglong2 bp = *(const ulonglong2*)&Bs[k*68 + n0];
            unsigned long long ad[8] = {pk2dup(a0.x), pk2dup(a0.y), pk2dup(a0.z), pk2dup(a0.w),
                                        pk2dup(a1.x), pk2dup(a1.y), pk2dup(a1.z), pk2dup(a1.w)};
            #pragma unroll
            for (int i = 0; i < 8; i++) {
                accp[i][0] = fma2(ad[i], bp.x, accp[i][0]);
                accp[i][1] = fma2(ad[i], bp.y, accp[i][1]);
            }
        }
        __syncthreads();
    }
    #pragma unroll
    for (int i = 0; i < 8; i++) {
        int r = tm*128 + m0 + i;
        if (r < TT*BSZ) {
            int tt = r >> 5, bb = r & 31;
            bool act = tt < g_dlen[bb];
            long obase = OFF_PRED + ((long)bb*TT + tt)*VV;
            float c[4];
            upk2(accp[i][0], c[0], c[1]);
            upk2(accp[i][1], c[2], c[3]);
            #pragma unroll
            for (int j = 0; j < 4; j++) {
                int col = tn*64 + n0 + j;
                if (col < VV) out[obase + col] = act ? (c[j] + b_fc[col]) : 0.f;
            }
        }
    }
}

// ---------------- score task: raw attention scores for p-quarter ----------------
__device__ void score_task(int b, int pq, const float* __restrict__ b_dec,
                           const float* __restrict__ w_full, const float* __restrict__ b_full,
                           float* pool)
{
    float* dec_s = pool;
    float* wf    = pool + 512;
    const int tid = threadIdx.x;
    __syncthreads();
    for (int a = tid; a < 512; a += 256) {
        float s = b_dec[a];
        #pragma unroll
        for (int sk = 0; sk < 16; sk++) s += g_pDec[sk*16384 + b*512 + a];
        dec_s[a] = s;
        wf[a] = w_full[a];
    }
    __syncthreads();
    int wid = tid >> 5, lane = tid & 31;
    float bf = b_full[0];
    const float* ds = dec_s + lane*16;
    const float* wl = wf + lane*16;
    const int pbeg = pq * 49;
    const int pend = (pq == 3) ? PP : (pbeg + 49);
    for (int p = pbeg + wid; p < pend; p += 16) {
        int p2 = p + 8;
        bool has2 = (p2 < pend);
        const float* er  = g_enc + ((long)b*PP + p)*512 + lane*16;
        const float* er2 = g_enc + ((long)b*PP + (has2 ? p2 : p))*512 + lane*16;
        float s = 0.f, s2v = 0.f;
        #pragma unroll
        for (int q = 0; q < 4; q++) {
            float4 e  = *(const float4*)(er + q*4);
            float4 e2 = *(const float4*)(er2 + q*4);
            float4 d  = *(const float4*)(ds + q*4);
            float4 w  = *(const float4*)(wl + q*4);
            s   = fmaf(fmaxf(e.x + d.x, 0.f), w.x, s);
            s2v = fmaf(fmaxf(e2.x + d.x, 0.f), w.x, s2v);
            s   = fmaf(fmaxf(e.y + d.y, 0.f), w.y, s);
            s2v = fmaf(fmaxf(e2.y + d.y, 0.f), w.y, s2v);
            s   = fmaf(fmaxf(e.z + d.z, 0.f), w.z, s);
            s2v = fmaf(fmaxf(e2.z + d.z, 0.f), w.z, s2v);
            s   = fmaf(fmaxf(e.w + d.w, 0.f), w.w, s);
            s2v = fmaf(fmaxf(e2.w + d.w, 0.f), w.w, s2v);
        }
        #pragma unroll
        for (int off = 16; off > 0; off >>= 1) {
            s   += __shfl_xor_sync(0xffffffffu, s, off);
            s2v += __shfl_xor_sync(0xffffffffu, s2v, off);
        }
        if (lane == 0) {
            g_sc[b*PP + p] = s + bf;
            if (has2) g_sc[b*PP + p2] = s2v + bf;
        }
    }
}

// ---------------- awe task: local softmax + img scan (256 cols) ----------------
__device__ void awe_task(int b, int ch, int t, const float* __restrict__ img,
                         float* __restrict__ out, float* pool)
{
    float* sc  = pool;          // 256
    float* red = pool + 256;    // 256
    float* al  = pool + 512;    // 256
    const int tid = threadIdx.x;
    __syncthreads();
    float v = (tid < PP) ? g_sc[b*PP + tid] : -3.0e38f;
    if (tid < PP) sc[tid] = v;
    red[tid] = v; __syncthreads();
    for (int s2 = 128; s2 > 0; s2 >>= 1) {
        if (tid < s2) red[tid] = fmaxf(red[tid], red[tid + s2]);
        __syncthreads();
    }
    float mx = red[0];
    __syncthreads();
    float ev = (tid < PP) ? expf(sc[tid] - mx) : 0.f;
    red[tid] = ev; __syncthreads();
    for (int s2 = 128; s2 > 0; s2 >>= 1) {
        if (tid < s2) red[tid] += red[tid + s2];
        __syncthreads();
    }
    float inv = 1.f / red[0];
    float alv = ev * inv;
    if (tid < PP) al[tid] = alv;
    if (ch == 0 && tid < PP)
        out[OFF_ALPHA + ((long)b*TT + t)*PP + tid] = alv;
    __syncthreads();

    int c0 = ch*256 + tid;
    const float* base = img + ((long)(g_sort[b]*PP))*ENCD + c0;
    float s0 = 0.f, s1 = 0.f, s2a = 0.f, s3 = 0.f;
    #pragma unroll 7
    for (int p = 0; p < PP; p += 4) {
        float v0 = base[(long)(p+0)*ENCD];
        float v1 = base[(long)(p+1)*ENCD];
        float v2 = base[(long)(p+2)*ENCD];
        float v3 = base[(long)(p+3)*ENCD];
        s0 = fmaf(al[p+0], v0, s0);
        s1 = fmaf(al[p+1], v1, s1);
        s2a = fmaf(al[p+2], v2, s2a);
        s3 = fmaf(al[p+3], v3, s3);
    }
    float s = (s0 + s1) + (s2a + s3);
    g_x2[b*2048 + c0] = s * g_betasig[b*2048 + c0];
}

// ---------------- main persistent kernel ----------------
__global__ void __launch_bounds__(256, 2)
persist(const float* __restrict__ img, const int* __restrict__ toks, const int* __restrict__ lens,
        const float* __restrict__ W_enc, const float* __restrict__ b_enc,
        const float* __restrict__ W_dec, const float* __restrict__ b_dec,
        const float* __restrict__ w_full, const float* __restrict__ b_full,
        const float* __restrict__ emb,
        const float* __restrict__ W_ih, const float* __restrict__ b_ih,
        const float* __restrict__ W_hh, const float* __restrict__ b_hh,
        const float* __restrict__ W_h0, const float* __restrict__ b_h0,
        const float* __restrict__ W_c0, const float* __restrict__ b_c0,
        const float* __restrict__ W_beta, const float* __restrict__ b_beta,
        const float* __restrict__ W_fc, const float* __restrict__ b_fc,
        float* __restrict__ out)
{
    __shared__ __align__(16) float pool[9700];
    const int bid = blockIdx.x;
    const int tid = threadIdx.x;

    // ---- P0 ----
    if (bid == 0) {
        if (tid < BSZ) {
            int li = lens[tid];
            int r = 0;
            for (int j = 0; j < BSZ; j++) {
                int lj = lens[j];
                if (lj > li || (lj == li && j < tid)) r++;
            }
            g_sort[r] = tid;
        }
        __syncthreads();
        if (tid < BSZ) {
            int si = g_sort[tid];
            int dl = lens[si] - 1;
            g_dlen[tid] = dl;
            out[OFF_DLEN + tid] = (float)dl;
            out[OFF_SORT + tid] = (float)si;
        }
        __syncthreads();
        if (tid < TT) {
            int a = 0;
            for (int j = 0; j < BSZ; j++) a += (g_dlen[j] > tid) ? 1 : 0;
            g_act[tid] = a;
        }
        for (int idx = tid; idx < BSZ*LL; idx += 256) {
            int b = idx / LL, l = idx - b*LL;
            int tk = toks[g_sort[b]*LL + l];
            g_toks[idx] = tk;
            out[OFF_TOKS + idx] = (float)tk;
        }
    } else if (bid == 1) {
        for (int i = tid; i < 2048; i += 256) g_bcomb[i] = b_ih[i] + b_hh[i];
    } else if (bid == 2) {
        for (int i = tid; i < 32*512; i += 256) g_hnall[1632L*512 + i] = 0.f;
    }
    gridbar();

    // ---- P1: enc_att (392) | embg (408) | mean (32) ----
    for (int task = bid; task < 832; task += GRID) {
        if (task < 392) {
            enc_task(task >> 3, task & 7, img, W_enc, b_enc, pool);
        } else if (task < 800) {
            int id = task - 392;
            int tt = id >> 3, nt = id & 7;
            gemm32(emb, 512, g_toks + tt, LL, W_ih, 2560, 0,
                   2048, nt*256, 0, 512, g_embg + (long)tt*65536, 2048, pool);
        } else {
            int b = task - 800;
            __syncthreads();
            long srow = (long)g_sort[b] * PP * ENCD;
            int e0 = tid * 8;
            float a[8] = {0,0,0,0,0,0,0,0};
            #pragma unroll 4
            for (int p = 0; p < PP; p++) {
                const float* r = img + srow + (long)p*ENCD + e0;
                float4 v0 = *(const float4*)r;
                float4 v1 = *(const float4*)(r + 4);
                a[0]+=v0.x; a[1]+=v0.y; a[2]+=v0.z; a[3]+=v0.w;
                a[4]+=v1.x; a[5]+=v1.y; a[6]+=v1.z; a[7]+=v1.w;
            }
            #pragma unroll
            for (int i = 0; i < 8; i++)
                g_mean[b*2048 + e0 + i] = a[i] * (1.f/196.f);
        }
    }
    gridbar();

    // ---- P2: h0/c0 partials ----
    for (int task = bid; task < 32; task += GRID) {
        int half = task >> 4, nt = (task >> 3) & 1, sk = task & 7;
        gemm32(g_mean, 2048, (const int*)0, 0, half ? W_c0 : W_h0, 2048, 0,
               512, nt*256, sk*256, 256, g_pIH + (long)(half*8 + sk)*16384, 512, pool);
    }
    gridbar();

    // ---- P3: reduce h0/c0 ----
    for (int task = bid; task < 32; task += GRID) {
        int b = task;
        for (int j = tid; j < 512; j += 256) {
            float s = b_h0[j], s2 = b_c0[j];
            #pragma unroll
            for (int s8 = 0; s8 < 8; s8++) {
                s  += g_pIH[s8*16384 + b*512 + j];
                s2 += g_pIH[(8+s8)*16384 + b*512 + j];
            }
            g_h[b*512 + j] = s;
            g_c[b*512 + j] = s2;
        }
    }
    gridbar();

    // ---- decode loop ----
    for (int t = 0; t < TT; t++) {
        const int A = g_act[t];

        // Ph1: dec SK16(32) | hh SK16(128) | beta SK16(128) = 288
        for (int task = bid; task < 288; task += GRID) {
            if (task < 32) {
                int nt = task >> 4, sk = task & 15;
                gemm32(g_h, 512, (const int*)0, 0, W_dec, 512, 0,
                       512, nt*256, sk*32, 32, g_pDec + (long)sk*16384, 512, pool);
            } else if (task < 160) {
                int rid = task - 32, nt = rid >> 4, sk = rid & 15;
                gemm32(g_h, 512, (const int*)0, 0, W_hh, 512, 0,
                       2048, nt*256, sk*32, 32, g_pHH + (long)sk*65536, 2048, pool);
            } else {
                int rid = task - 160, nt = rid >> 4, sk = rid & 15;
                gemm32(g_h, 512, (const int*)0, 0, W_beta, 512, 0,
                       2048, nt*256, sk*32, 32, g_pBeta + (long)sk*65536, 2048, pool);
            }
        }
        gridbar();

        // Ph2: scores (128: b x 4 p-quarters) | gates-base(32) | beta-sigmoid(64) = 224
        for (int task = bid; task < 224; task += GRID) {
            if (task < 128) {
                int b = task >> 2, pq = task & 3;
                if (b < A) {
                    score_task(b, pq, b_dec, w_full, b_full, pool);
                } else if (pq == 0 && tid < PP) {
                    out[OFF_ALPHA + ((long)b*TT + t)*PP + tid] = 0.f;
                }
            } else if (task < 160) {
                int b = task - 128;
                if (b >= A) continue;
                int c0 = tid * 8;
                float4 s0 = *(const float4*)(g_bcomb + c0);
                float4 s1 = *(const float4*)(g_bcomb + c0 + 4);
                float4 e0 = *(const float4*)(g_embg + (long)t*65536 + b*2048 + c0);
                float4 e1 = *(const float4*)(g_embg + (long)t*65536 + b*2048 + c0 + 4);
                s0.x+=e0.x; s0.y+=e0.y; s0.z+=e0.z; s0.w+=e0.w;
                s1.x+=e1.x; s1.y+=e1.y; s1.z+=e1.z; s1.w+=e1.w;
                #pragma unroll
                for (int sk = 0; sk < 16; sk++) {
                    float4 p0 = *(const float4*)(g_pHH + (long)sk*65536 + b*2048 + c0);
                    float4 p1 = *(const float4*)(g_pHH + (long)sk*65536 + b*2048 + c0 + 4);
                    s0.x+=p0.x; s0.y+=p0.y; s0.z+=p0.z; s0.w+=p0.w;
                    s1.x+=p1.x; s1.y+=p1.y; s1.z+=p1.z; s1.w+=p1.w;
                }
                *(float4*)(g_gates + b*2048 + c0) = s0;
                *(float4*)(g_gates + b*2048 + c0 + 4) = s1;
            } else {
                int rid = task - 160;
                int b = rid >> 1, half = rid & 1;
                if (b >= A) continue;
                int c0 = half*1024 + tid*4;
                float4 s = *(const float4*)(b_beta + c0);
                #pragma unroll
                for (int sk = 0; sk < 16; sk++) {
                    float4 p = *(const float4*)(g_pBeta + (long)sk*65536 + b*2048 + c0);
                    s.x+=p.x; s.y+=p.y; s.z+=p.z; s.w+=p.w;
                }
                float4 o;
                o.x = sigm(s.x); o.y = sigm(s.y); o.z = sigm(s.z); o.w = sigm(s.w);
                *(float4*)(g_betasig + b*2048 + c0) = o;
            }
        }
        gridbar();

        // Ph3: awe (256: b x 8 chunks of 256 cols), local softmax, only active b
        for (int task = bid; task < 256; task += GRID) {
            int b = task >> 3, ch = task & 7;
            if (b >= A) continue;
            awe_task(b, ch, t, img, out, pool);
        }
        gridbar();

        // Ph4: x2 @ W_ih[:,512:]^T (256 tasks: 8 ntiles x SK32 k64)
        for (int task = bid; task < 256; task += GRID) {
            int nt = task >> 5, sk = task & 31;
            gemm32(g_x2, 2048, (const int*)0, 0, W_ih, 2560, 512,
                   2048, nt*256, sk*64, 64, g_pIH + (long)sk*65536, 2048, pool);
        }
        gridbar();

        // Ph5: gate reduce + LSTM (128 tasks: b x j-quarter, 2 slice-groups)
        for (int task = bid; task < 128; task += GRID) {
            int b = task >> 2, quarter = task & 3;
            if (b >= A) continue;
            float* partial = pool;    // 4 x 128
            const int j = quarter*128 + (tid & 127);
            const int grp = tid >> 7;
            float gi = 0.f, gf = 0.f, gg = 0.f, go = 0.f;
            const int skb = grp * 16;
            #pragma unroll
            for (int sk = 0; sk < 16; sk++) {
                const float* p = g_pIH + (long)(skb + sk)*65536 + b*2048;
                gi += p[j]; gf += p[j + 512]; gg += p[j + 1024]; go += p[j + 1536];
            }
            __syncthreads();
            if (grp == 1) {
                partial[(tid & 127)]       = gi;
                partial[(tid & 127) + 128] = gf;
                partial[(tid & 127) + 256] = gg;
                partial[(tid & 127) + 384] = go;
            }
            __syncthreads();
            if (grp == 0) {
                gi += partial[tid]       + g_gates[b*2048 + j];
                gf += partial[tid + 128] + g_gates[b*2048 + j + 512];
                gg += partial[tid + 256] + g_gates[b*2048 + j + 1024];
                go += partial[tid + 384] + g_gates[b*2048 + j + 1536];
                float c = g_c[b*512 + j];
                float cn = sigm(gf)*c + sigm(gi)*tanhf(gg);
                float hn = sigm(go)*tanhf(cn);
                g_hnall[((long)t*32 + b)*512 + j] = hn;
                g_c[b*512 + j] = cn;
                g_h[b*512 + j] = hn;
            }
            __syncthreads();
        }
        gridbar();
    }

    // ---- epilogue: preds = Hn_all @ W_fc^T + b_fc ----
    for (int task = bid; task < 13*157; task += GRID) {
        int tm = task / 157, tn = task - tm*157;
        fc_task(tm, tn, W_fc, b_fc, out, pool);
    }
}

// ---------------- host launcher ----------------
extern "C" void kernel_launch(void* const* d_in, const int* in_sizes, int n_in,
                              void* d_out, int out_size) {
    persist<<<GRID, 256>>>(
        (const float*)d_in[0],  (const int*)d_in[1],   (const int*)d_in[2],
        (const float*)d_in[3],  (const float*)d_in[4],
        (const float*)d_in[5],  (const float*)d_in[6],
        (const float*)d_in[7],  (const float*)d_in[8],
        (const float*)d_in[9],
        (const float*)d_in[10], (const float*)d_in[11],
        (const float*)d_in[12], (const float*)d_in[13],
        (const float*)d_in[14], (const float*)d_in[15],
        (const float*)d_in[16], (const float*)d_in[17],
        (const float*)d_in[18], (const float*)d_in[19],
        (const float*)d_in[20], (const float*)d_in[21],
        (float*)d_out);
    (void)in_sizes; (void)n_in; (void)out_size;
}

// round 17
// speedup vs baseline: 2.3163x; 1.0205x over previous
#include <cuda_runtime.h>
#include <math.h>

#define BSZ 32
#define PP 196
#define ENCD 2048
#define ATTD 512
#define DECD 512
#define VV 10000
#define LL 52
#define TT 51
#define GRID 296

#define OFF_PRED  0L
#define OFF_TOKS  ((long)BSZ*TT*VV)
#define OFF_DLEN  (OFF_TOKS + (long)BSZ*LL)
#define OFF_ALPHA (OFF_DLEN + (long)BSZ)
#define OFF_SORT  (OFF_ALPHA + (long)BSZ*TT*PP)

// ---------------- static device scratch ----------------
__device__ float g_enc[6272L*512];
__device__ float g_embg[51L*32*2048];
__device__ float g_pDec[8L*32*512];
__device__ float g_pHH[8L*32*2048];
__device__ float g_pBeta[8L*32*2048];
__device__ float g_pIH[16L*32*2048];      // also h0/c0 partials [16][32][512]
__device__ float g_mean[32*2048];
__device__ float g_h[32*512];
__device__ float g_c[32*512];
__device__ float g_hnall[1664L*512];
__device__ float g_gates[32*2048];
__device__ float g_betasig[32*2048];
__device__ float g_x2[32*2048];
__device__ float g_sc[32*PP];
__device__ float g_bcomb[2048];
__device__ int   g_sort[32];
__device__ int   g_dlen[32];
__device__ int   g_act[TT];
__device__ int   g_toks[32*LL];
__device__ unsigned g_barcnt;
__device__ volatile unsigned g_bargen;

__device__ __forceinline__ float sigm(float x) { return 1.f / (1.f + expf(-x)); }

// ---------------- packed f32x2 helpers ----------------
__device__ __forceinline__ unsigned long long pk2dup(float v) {
    unsigned long long r;
    asm("mov.b64 %0, {%1, %1};" : "=l"(r) : "f"(v));
    return r;
}
__device__ __forceinline__ void upk2(unsigned long long v, float& lo, float& hi) {
    asm("mov.b64 {%0, %1}, %2;" : "=f"(lo), "=f"(hi) : "l"(v));
}
__device__ __forceinline__ unsigned long long fma2(unsigned long long a,
                                                   unsigned long long b,
                                                   unsigned long long c) {
    unsigned long long d;
    asm("fma.rn.f32x2 %0, %1, %2, %3;" : "=l"(d) : "l"(a), "l"(b), "l"(c));
    return d;
}

// ---------------- grid-wide software barrier (hybrid spin) ----------------
__device__ __forceinline__ void gridbar() {
    __syncthreads();
    if (threadIdx.x == 0) {
        __threadfence();
        unsigned gen = g_bargen;
        if (atomicAdd(&g_barcnt, 1u) == GRID - 1) {
            g_barcnt = 0;
            __threadfence();
            g_bargen = gen + 1;
        } else {
            int spins = 0;
            while (g_bargen == gen) {
                if (++spins > 32) __nanosleep(100);
            }
        }
        __threadfence();
    }
    __syncthreads();
}

// ---------------- 32-row GEMM partial tile, N-tile 256 (TN8), f32x2 ----------------
__device__ void gemm32(const float* __restrict__ X, int ldx,
                       const int* __restrict__ gidx, int gstride,
                       const float* __restrict__ W, int ldw, int wcol0,
                       int Nfull, int nbase, int k0, int klen,
                       float* __restrict__ part, int Nld, float* pool)
{
    float* Xs = pool;                 // 32k x 36
    float* Ws = pool + 1184;          // 32k x 264
    int* roff = (int*)(pool + 1184 + 32*264);
    const int tid = threadIdx.x;
    __syncthreads();
    if (tid < 32) roff[tid] = (gidx ? gidx[tid * gstride] : tid) * ldx;
    __syncthreads();

    const int m0 = (tid >> 5) * 4;
    const int lane4 = (tid & 31) * 4;
    const int xm = tid >> 3, xk = (tid & 7) * 4;
    const int wn = tid >> 3, wk = (tid & 7) * 4;

    unsigned long long accp[4][4];
    #pragma unroll
    for (int i = 0; i < 4; i++)
        #pragma unroll
        for (int j = 0; j < 4; j++) accp[i][j] = 0ull;

    float4 xv = *(const float4*)(X + roff[xm] + k0 + xk);
    float4 wv[8];
    #pragma unroll
    for (int j = 0; j < 8; j++) {
        int ng = nbase + j*32 + wn;
        wv[j] = (ng < Nfull) ? *(const float4*)(W + (long)ng*ldw + wcol0 + k0 + wk)
                             : make_float4(0.f, 0.f, 0.f, 0.f);
    }

    for (int kk = 0; kk < klen; kk += 32) {
        Xs[(xk+0)*36 + xm] = xv.x; Xs[(xk+1)*36 + xm] = xv.y;
        Xs[(xk+2)*36 + xm] = xv.z; Xs[(xk+3)*36 + xm] = xv.w;
        #pragma unroll
        for (int j = 0; j < 8; j++) {
            int n = j*32 + wn;
            Ws[(wk+0)*264 + n] = wv[j].x; Ws[(wk+1)*264 + n] = wv[j].y;
            Ws[(wk+2)*264 + n] = wv[j].z; Ws[(wk+3)*264 + n] = wv[j].w;
        }
        __syncthreads();
        if (kk + 32 < klen) {
            int kc = k0 + kk + 32;
            xv = *(const float4*)(X + roff[xm] + kc + xk);
            #pragma unroll
            for (int j = 0; j < 8; j++) {
                int ng = nbase + j*32 + wn;
                wv[j] = (ng < Nfull) ? *(const float4*)(W + (long)ng*ldw + wcol0 + kc + wk)
                                     : make_float4(0.f, 0.f, 0.f, 0.f);
            }
        }
        #pragma unroll
        for (int k = 0; k < 32; k++) {
            float4 a = *(const float4*)&Xs[k*36 + m0];
            unsigned long long ad[4] = {pk2dup(a.x), pk2dup(a.y), pk2dup(a.z), pk2dup(a.w)};
            ulonglong2 wA = *(const ulonglong2*)&Ws[k*264 + lane4];
            ulonglong2 wB = *(const ulonglong2*)&Ws[k*264 + 128 + lane4];
            #pragma unroll
            for (int i = 0; i < 4; i++) {
                accp[i][0] = fma2(ad[i], wA.x, accp[i][0]);
                accp[i][1] = fma2(ad[i], wA.y, accp[i][1]);
                accp[i][2] = fma2(ad[i], wB.x, accp[i][2]);
                accp[i][3] = fma2(ad[i], wB.y, accp[i][3]);
            }
        }
        __syncthreads();
    }
    #pragma unroll
    for (int i = 0; i < 4; i++) {
        ulonglong2 o0; o0.x = accp[i][0]; o0.y = accp[i][1];
        ulonglong2 o1; o1.x = accp[i][2]; o1.y = accp[i][3];
        *(ulonglong2*)&part[(long)(m0+i)*Nld + nbase + lane4]       = o0;
        *(ulonglong2*)&part[(long)(m0+i)*Nld + nbase + 128 + lane4] = o1;
    }
}

// ---------------- 32-row GEMM partial tile, N-tile 128 (TN4), f32x2, deep-k ----------------
__device__ void gemm128(const float* __restrict__ X, int ldx,
                        const float* __restrict__ W, int ldw, int wcol0,
                        int nbase, int k0, int klen,
                        float* __restrict__ part, int Nld, float* pool)
{
    float* Xs = pool;                 // 32k x 36
    float* Ws = pool + 1184;          // 32k x 136
    const int tid = threadIdx.x;
    __syncthreads();

    const int m0 = (tid >> 5) * 4;
    const int lane4 = (tid & 31) * 4;
    const int xm = tid >> 3, xk = (tid & 7) * 4;
    const int wn = tid >> 3, wk = (tid & 7) * 4;

    unsigned long long accp[4][2];
    #pragma unroll
    for (int i = 0; i < 4; i++) { accp[i][0] = 0ull; accp[i][1] = 0ull; }

    float4 xv = *(const float4*)(X + (long)xm*ldx + k0 + xk);
    float4 wv[4];
    #pragma unroll
    for (int j = 0; j < 4; j++)
        wv[j] = *(const float4*)(W + (long)(nbase + j*32 + wn)*ldw + wcol0 + k0 + wk);

    for (int kk = 0; kk < klen; kk += 32) {
        Xs[(xk+0)*36 + xm] = xv.x; Xs[(xk+1)*36 + xm] = xv.y;
        Xs[(xk+2)*36 + xm] = xv.z; Xs[(xk+3)*36 + xm] = xv.w;
        #pragma unroll
        for (int j = 0; j < 4; j++) {
            int n = j*32 + wn;
            Ws[(wk+0)*136 + n] = wv[j].x; Ws[(wk+1)*136 + n] = wv[j].y;
            Ws[(wk+2)*136 + n] = wv[j].z; Ws[(wk+3)*136 + n] = wv[j].w;
        }
        __syncthreads();
        if (kk + 32 < klen) {
            int kc = k0 + kk + 32;
            xv = *(const float4*)(X + (long)xm*ldx + kc + xk);
            #pragma unroll
            for (int j = 0; j < 4; j++)
                wv[j] = *(const float4*)(W + (long)(nbase + j*32 + wn)*ldw + wcol0 + kc + wk);
        }
        #pragma unroll
        for (int k = 0; k < 32; k++) {
            float4 a = *(const float4*)&Xs[k*36 + m0];
            unsigned long long ad[4] = {pk2dup(a.x), pk2dup(a.y), pk2dup(a.z), pk2dup(a.w)};
            ulonglong2 wA = *(const ulonglong2*)&Ws[k*136 + lane4];
            #pragma unroll
            for (int i = 0; i < 4; i++) {
                accp[i][0] = fma2(ad[i], wA.x, accp[i][0]);
                accp[i][1] = fma2(ad[i], wA.y, accp[i][1]);
            }
        }
        __syncthreads();
    }
    #pragma unroll
    for (int i = 0; i < 4; i++) {
        ulonglong2 o; o.x = accp[i][0]; o.y = accp[i][1];
        *(ulonglong2*)&part[(long)(m0+i)*Nld + nbase + lane4] = o;
    }
}

// ---------------- 128x64 dense tile, K=2048, f32x2: enc_att ----------------
__device__ void enc_task(int tm, int tn, const float* __restrict__ img,
                         const float* __restrict__ W_enc, const float* __restrict__ b_enc,
                         float* pool)
{
    float* As = pool;
    float* Bs = pool + 4224;
    int* rowb = (int*)(pool + 6400);
    const int tid = threadIdx.x;
    __syncthreads();
    if (tid < 128) {
        int rr = tm*128 + tid;
        int b = rr / PP, p = rr - b*PP;
        rowb[tid] = (g_sort[b]*PP + p) * ENCD;
    }
    __syncthreads();
    unsigned long long accp[8][2];
    #pragma unroll
    for (int i = 0; i < 8; i++) { accp[i][0] = 0ull; accp[i][1] = 0ull; }
    const int ty = tid >> 4, tx = tid & 15;
    const int m0 = ty*8, n0 = tx*4;
    const int am = tid >> 3, ak = (tid & 7) * 4;
    const int bn = tid >> 3, bk = (tid & 7) * 4;

    float4 av4[4], bv4[2];
    #pragma unroll
    for (int j = 0; j < 4; j++)
        av4[j] = *(const float4*)(img + rowb[j*32 + am] + ak);
    #pragma unroll
    for (int j = 0; j < 2; j++)
        bv4[j] = *(const float4*)(W_enc + (long)(tn*64 + j*32 + bn)*ENCD + bk);

    for (int kc = 0; kc < ENCD; kc += 32) {
        #pragma unroll
        for (int j = 0; j < 4; j++) {
            int m = j*32 + am;
            As[(ak+0)*132+m] = av4[j].x; As[(ak+1)*132+m] = av4[j].y;
            As[(ak+2)*132+m] = av4[j].z; As[(ak+3)*132+m] = av4[j].w;
        }
        #pragma unroll
        for (int j = 0; j < 2; j++) {
            int n = j*32 + bn;
            Bs[(bk+0)*68+n] = bv4[j].x; Bs[(bk+1)*68+n] = bv4[j].y;
            Bs[(bk+2)*68+n] = bv4[j].z; Bs[(bk+3)*68+n] = bv4[j].w;
        }
        __syncthreads();
        if (kc + 32 < ENCD) {
            #pragma unroll
            for (int j = 0; j < 4; j++)
                av4[j] = *(const float4*)(img + rowb[j*32 + am] + kc + 32 + ak);
            #pragma unroll
            for (int j = 0; j < 2; j++)
                bv4[j] = *(const float4*)(W_enc + (long)(tn*64 + j*32 + bn)*ENCD + kc + 32 + bk);
        }
        #pragma unroll
        for (int k = 0; k < 32; k++) {
            float4 a0 = *(const float4*)&As[k*132 + m0];
            float4 a1 = *(const float4*)&As[k*132 + m0 + 4];
            ulonglong2 bp = *(const ulonglong2*)&Bs[k*68 + n0];
            unsigned long long ad[8] = {pk2dup(a0.x), pk2dup(a0.y), pk2dup(a0.z), pk2dup(a0.w),
                                        pk2dup(a1.x), pk2dup(a1.y), pk2dup(a1.z), pk2dup(a1.w)};
            #pragma unroll
            for (int i = 0; i < 8; i++) {
                accp[i][0] = fma2(ad[i], bp.x, accp[i][0]);
                accp[i][1] = fma2(ad[i], bp.y, accp[i][1]);
            }
        }
        __syncthreads();
    }
    int colb = tn*64 + n0;
    float4 bias = *(const float4*)(b_enc + colb);
    #pragma unroll
    for (int i = 0; i < 8; i++) {
        int row = tm*128 + m0 + i;
        float c0, c1, c2, c3;
        upk2(accp[i][0], c0, c1);
        upk2(accp[i][1], c2, c3);
        float4 o = make_float4(c0 + bias.x, c1 + bias.y, c2 + bias.z, c3 + bias.w);
        *(float4*)&g_enc[(long)row*512 + colb] = o;
    }
}

// ---------------- 128x64 dense tile, K=512, f32x2: final FC ----------------
__device__ void fc_task(int tm, int tn,
                        const float* __restrict__ W_fc, const float* __restrict__ b_fc,
                        float* __restrict__ out, float* pool)
{
    float* As = pool;
    float* Bs = pool + 4224;
    const int tid = threadIdx.x;
    __syncthreads();
    unsigned long long accp[8][2];
    #pragma unroll
    for (int i = 0; i < 8; i++) { accp[i][0] = 0ull; accp[i][1] = 0ull; }
    const int ty = tid >> 4, tx = tid & 15;
    const int m0 = ty*8, n0 = tx*4;
    const int am = tid >> 3, ak = (tid & 7) * 4;
    const int bn = tid >> 3, bk = (tid & 7) * 4;

    float4 av4[4], bv4[2];
    #pragma unroll
    for (int j = 0; j < 4; j++)
        av4[j] = *(const float4*)(g_hnall + (long)(tm*128 + j*32 + am)*512 + ak);
    #pragma unroll
    for (int j = 0; j < 2; j++) {
        int ng = tn*64 + j*32 + bn;
        bv4[j] = (ng < VV) ? *(const float4*)(W_fc + (long)ng*512 + bk)
                           : make_float4(0.f,0.f,0.f,0.f);
    }

    for (int kc = 0; kc < 512; kc += 32) {
        #pragma unroll
        for (int j = 0; j < 4; j++) {
            int m = j*32 + am;
            As[(ak+0)*132+m] = av4[j].x; As[(ak+1)*132+m] = av4[j].y;
            As[(ak+2)*132+m] = av4[j].z; As[(ak+3)*132+m] = av4[j].w;
        }
        #pragma unroll
        for (int j = 0; j < 2; j++) {
            int n = j*32 + bn;
            Bs[(bk+0)*68+n] = bv4[j].x; Bs[(bk+1)*68+n] = bv4[j].y;
            Bs[(bk+2)*68+n] = bv4[j].z; Bs[(bk+3)*68+n] = bv4[j].w;
        }
        __syncthreads();
        if (kc + 32 < 512) {
            #pragma unroll
            for (int j = 0; j < 4; j++)
                av4[j] = *(const float4*)(g_hnall + (long)(tm*128 + j*32 + am)*512 + kc + 32 + ak);
            #pragma unroll
            for (int j = 0; j < 2; j++) {
                int ng = tn*64 + j*32 + bn;
                bv4[j] = (ng < VV) ? *(const float4*)(W_fc + (long)ng*512 + kc + 32 + bk)
                                   : make_float4(0.f,0.f,0.f,0.f);
            }
        }
        #pragma unroll
        for (int k = 0; k < 32; k++) {
            float4 a0 = *(const float4*)&As[k*132 + m0];
            float4 a1 = *(const float4*)&As[k*132 + m0 + 4];
            ulonglong2 bp = *(const ulonglong2*)&Bs[k*68 + n0];
            unsigned long long ad[8] = {pk2dup(a0.x), pk2dup(a0.y), pk2dup(a0.z), pk2dup(a0.w),
                                        pk2dup(a1.x), pk2dup(a1.y), pk2dup(a1.z), pk2dup(a1.w)};
            #pragma unroll
            for (int i = 0; i < 8; i++) {
                accp[i][0] = fma2(ad[i], bp.x, accp[i][0]);
                accp[i][1] = fma2(ad[i], bp.y, accp[i][1]);
            }
        }
        __syncthreads();
    }
    #pragma unroll
    for (int i = 0; i < 8; i++) {
        int r = tm*128 + m0 + i;
        if (r < TT*BSZ) {
            int tt = r >> 5, bb = r & 31;
            bool act = tt < g_dlen[bb];
            long obase = OFF_PRED + ((long)bb*TT + tt)*VV;
            float c[4];
            upk2(accp[i][0], c[0], c[1]);
            upk2(accp[i][1], c[2], c[3]);
            #pragma unroll
            for (int j = 0; j < 4; j++) {
                int col = tn*64 + n0 + j;
                if (col < VV) out[obase + col] = act ? (c[j] + b_fc[col]) : 0.f;
            }
        }
    }
}

// ---------------- score task: raw attention scores for p-quarter ----------------
__device__ void score_task(int b, int pq, const float* __restrict__ b_dec,
                           const float* __restrict__ w_full, const float* __restrict__ b_full,
                           float* pool)
{
    float* dec_s = pool;
    float* wf    = pool + 512;
    const int tid = threadIdx.x;
    __syncthreads();
    for (int a = tid; a < 512; a += 256) {
        float s = b_dec[a];
        #pragma unroll
        for (int sk = 0; sk < 8; sk++) s += g_pDec[sk*16384 + b*512 + a];
        dec_s[a] = s;
        wf[a] = w_full[a];
    }
    __syncthreads();
    int wid = tid >> 5, lane = tid & 31;
    float bf = b_full[0];
    const float* ds = dec_s + lane*16;
    const float* wl = wf + lane*16;
    const int pbeg = pq * 49;
    const int pend = (pq == 3) ? PP : (pbeg + 49);
    for (int p = pbeg + wid; p < pend; p += 16) {
        int p2 = p + 8;
        bool has2 = (p2 < pend);
        const float* er  = g_enc + ((long)b*PP + p)*512 + lane*16;
        const float* er2 = g_enc + ((long)b*PP + (has2 ? p2 : p))*512 + lane*16;
        float s = 0.f, s2v = 0.f;
        #pragma unroll
        for (int q = 0; q < 4; q++) {
            float4 e  = *(const float4*)(er + q*4);
            float4 e2 = *(const float4*)(er2 + q*4);
            float4 d  = *(const float4*)(ds + q*4);
            float4 w  = *(const float4*)(wl + q*4);
            s   = fmaf(fmaxf(e.x + d.x, 0.f), w.x, s);
            s2v = fmaf(fmaxf(e2.x + d.x, 0.f), w.x, s2v);
            s   = fmaf(fmaxf(e.y + d.y, 0.f), w.y, s);
            s2v = fmaf(fmaxf(e2.y + d.y, 0.f), w.y, s2v);
            s   = fmaf(fmaxf(e.z + d.z, 0.f), w.z, s);
            s2v = fmaf(fmaxf(e2.z + d.z, 0.f), w.z, s2v);
            s   = fmaf(fmaxf(e.w + d.w, 0.f), w.w, s);
            s2v = fmaf(fmaxf(e2.w + d.w, 0.f), w.w, s2v);
        }
        #pragma unroll
        for (int off = 16; off > 0; off >>= 1) {
            s   += __shfl_xor_sync(0xffffffffu, s, off);
            s2v += __shfl_xor_sync(0xffffffffu, s2v, off);
        }
        if (lane == 0) {
            g_sc[b*PP + p] = s + bf;
            if (has2) g_sc[b*PP + p2] = s2v + bf;
        }
    }
}

// ---------------- awe task: local softmax + img scan (256 cols) ----------------
__device__ void awe_task(int b, int ch, int t, const float* __restrict__ img,
                         float* __restrict__ out, float* pool)
{
    float* sc  = pool;
    float* red = pool + 256;
    float* al  = pool + 512;
    const int tid = threadIdx.x;
    __syncthreads();
    float v = (tid < PP) ? g_sc[b*PP + tid] : -3.0e38f;
    if (tid < PP) sc[tid] = v;
    red[tid] = v; __syncthreads();
    for (int s2 = 128; s2 > 0; s2 >>= 1) {
        if (tid < s2) red[tid] = fmaxf(red[tid], red[tid + s2]);
        __syncthreads();
    }
    float mx = red[0];
    __syncthreads();
    float ev = (tid < PP) ? expf(sc[tid] - mx) : 0.f;
    red[tid] = ev; __syncthreads();
    for (int s2 = 128; s2 > 0; s2 >>= 1) {
        if (tid < s2) red[tid] += red[tid + s2];
        __syncthreads();
    }
    float inv = 1.f / red[0];
    float alv = ev * inv;
    if (tid < PP) al[tid] = alv;
    if (ch == 0 && tid < PP)
        out[OFF_ALPHA + ((long)b*TT + t)*PP + tid] = alv;
    __syncthreads();

    int c0 = ch*256 + tid;
    const float* base = img + ((long)(g_sort[b]*PP))*ENCD + c0;
    float s0 = 0.f, s1 = 0.f, s2a = 0.f, s3 = 0.f;
    #pragma unroll 7
    for (int p = 0; p < PP; p += 4) {
        float v0 = base[(long)(p+0)*ENCD];
        float v1 = base[(long)(p+1)*ENCD];
        float v2 = base[(long)(p+2)*ENCD];
        float v3 = base[(long)(p+3)*ENCD];
        s0 = fmaf(al[p+0], v0, s0);
        s1 = fmaf(al[p+1], v1, s1);
        s2a = fmaf(al[p+2], v2, s2a);
        s3 = fmaf(al[p+3], v3, s3);
    }
    float s = (s0 + s1) + (s2a + s3);
    g_x2[b*2048 + c0] = s * g_betasig[b*2048 + c0];
}

// ---------------- main persistent kernel ----------------
__global__ void __launch_bounds__(256, 2)
persist(const float* __restrict__ img, const int* __restrict__ toks, const int* __restrict__ lens,
        const float* __restrict__ W_enc, const float* __restrict__ b_enc,
        const float* __restrict__ W_dec, const float* __restrict__ b_dec,
        const float* __restrict__ w_full, const float* __restrict__ b_full,
        const float* __restrict__ emb,
        const float* __restrict__ W_ih, const float* __restrict__ b_ih,
        const float* __restrict__ W_hh, const float* __restrict__ b_hh,
        const float* __restrict__ W_h0, const float* __restrict__ b_h0,
        const float* __restrict__ W_c0, const float* __restrict__ b_c0,
        const float* __restrict__ W_beta, const float* __restrict__ b_beta,
        const float* __restrict__ W_fc, const float* __restrict__ b_fc,
        float* __restrict__ out)
{
    __shared__ __align__(16) float pool[9700];
    const int bid = blockIdx.x;
    const int tid = threadIdx.x;

    // ---- P0 ----
    if (bid == 0) {
        if (tid < BSZ) {
            int li = lens[tid];
            int r = 0;
            for (int j = 0; j < BSZ; j++) {
                int lj = lens[j];
                if (lj > li || (lj == li && j < tid)) r++;
            }
            g_sort[r] = tid;
        }
        __syncthreads();
        if (tid < BSZ) {
            int si = g_sort[tid];
            int dl = lens[si] - 1;
            g_dlen[tid] = dl;
            out[OFF_DLEN + tid] = (float)dl;
            out[OFF_SORT + tid] = (float)si;
        }
        __syncthreads();
        if (tid < TT) {
            int a = 0;
            for (int j = 0; j < BSZ; j++) a += (g_dlen[j] > tid) ? 1 : 0;
            g_act[tid] = a;
        }
        for (int idx = tid; idx < BSZ*LL; idx += 256) {
            int b = idx / LL, l = idx - b*LL;
            int tk = toks[g_sort[b]*LL + l];
            g_toks[idx] = tk;
            out[OFF_TOKS + idx] = (float)tk;
        }
    } else if (bid == 1) {
        for (int i = tid; i < 2048; i += 256) g_bcomb[i] = b_ih[i] + b_hh[i];
    } else if (bid == 2) {
        for (int i = tid; i < 32*512; i += 256) g_hnall[1632L*512 + i] = 0.f;
    }
    gridbar();

    // ---- P1: enc_att (392) | embg (408) | mean (32) ----
    for (int task = bid; task < 832; task += GRID) {
        if (task < 392) {
            enc_task(task >> 3, task & 7, img, W_enc, b_enc, pool);
        } else if (task < 800) {
            int id = task - 392;
            int tt = id >> 3, nt = id & 7;
            gemm32(emb, 512, g_toks + tt, LL, W_ih, 2560, 0,
                   2048, nt*256, 0, 512, g_embg + (long)tt*65536, 2048, pool);
        } else {
            int b = task - 800;
            __syncthreads();
            long srow = (long)g_sort[b] * PP * ENCD;
            int e0 = tid * 8;
            float a[8] = {0,0,0,0,0,0,0,0};
            #pragma unroll 4
            for (int p = 0; p < PP; p++) {
                const float* r = img + srow + (long)p*ENCD + e0;
                float4 v0 = *(const float4*)r;
                float4 v1 = *(const float4*)(r + 4);
                a[0]+=v0.x; a[1]+=v0.y; a[2]+=v0.z; a[3]+=v0.w;
                a[4]+=v1.x; a[5]+=v1.y; a[6]+=v1.z; a[7]+=v1.w;
            }
            #pragma unroll
            for (int i = 0; i < 8; i++)
                g_mean[b*2048 + e0 + i] = a[i] * (1.f/196.f);
        }
    }
    gridbar();

    // ---- P2: h0/c0 partials (pIH as [16][32][512]) ----
    for (int task = bid; task < 32; task += GRID) {
        int half = task >> 4, nt = (task >> 3) & 1, sk = task & 7;
        gemm32(g_mean, 2048, (const int*)0, 0, half ? W_c0 : W_h0, 2048, 0,
               512, nt*256, sk*256, 256, g_pIH + (long)(half*8 + sk)*16384, 512, pool);
    }
    gridbar();

    // ---- P3: reduce h0/c0 ----
    for (int task = bid; task < 32; task += GRID) {
        int b = task;
        for (int j = tid; j < 512; j += 256) {
            float s = b_h0[j], s2 = b_c0[j];
            #pragma unroll
            for (int s8 = 0; s8 < 8; s8++) {
                s  += g_pIH[s8*16384 + b*512 + j];
                s2 += g_pIH[(8+s8)*16384 + b*512 + j];
            }
            g_h[b*512 + j] = s;
            g_c[b*512 + j] = s2;
        }
    }
    gridbar();

    // ---- decode loop ----
    for (int t = 0; t < TT; t++) {
        const int A = g_act[t];

        // Ph1: dec (4nt x SK8 = 32) | hh (16nt x SK8 = 128) | beta (128) = 288, klen=64
        for (int task = bid; task < 288; task += GRID) {
            if (task < 32) {
                int nt = task >> 3, sk = task & 7;
                gemm128(g_h, 512, W_dec, 512, 0,
                        nt*128, sk*64, 64, g_pDec + (long)sk*16384, 512, pool);
            } else if (task < 160) {
                int rid = task - 32, nt = rid >> 3, sk = rid & 7;
                gemm128(g_h, 512, W_hh, 512, 0,
                        nt*128, sk*64, 64, g_pHH + (long)sk*65536, 2048, pool);
            } else {
                int rid = task - 160, nt = rid >> 3, sk = rid & 7;
                gemm128(g_h, 512, W_beta, 512, 0,
                        nt*128, sk*64, 64, g_pBeta + (long)sk*65536, 2048, pool);
            }
        }
        gridbar();

        // Ph2: scores (128) | gates-base(32) | beta-sigmoid(64) = 224
        for (int task = bid; task < 224; task += GRID) {
            if (task < 128) {
                int b = task >> 2, pq = task & 3;
                if (b < A) {
                    score_task(b, pq, b_dec, w_full, b_full, pool);
                } else if (pq == 0 && tid < PP) {
                    out[OFF_ALPHA + ((long)b*TT + t)*PP + tid] = 0.f;
                }
            } else if (task < 160) {
                int b = task - 128;
                if (b >= A) continue;
                int c0 = tid * 8;
                float4 s0 = *(const float4*)(g_bcomb + c0);
                float4 s1 = *(const float4*)(g_bcomb + c0 + 4);
                float4 e0 = *(const float4*)(g_embg + (long)t*65536 + b*2048 + c0);
                float4 e1 = *(const float4*)(g_embg + (long)t*65536 + b*2048 + c0 + 4);
                s0.x+=e0.x; s0.y+=e0.y; s0.z+=e0.z; s0.w+=e0.w;
                s1.x+=e1.x; s1.y+=e1.y; s1.z+=e1.z; s1.w+=e1.w;
                #pragma unroll
                for (int sk = 0; sk < 8; sk++) {
                    float4 p0 = *(const float4*)(g_pHH + (long)sk*65536 + b*2048 + c0);
                    float4 p1 = *(const float4*)(g_pHH + (long)sk*65536 + b*2048 + c0 + 4);
                    s0.x+=p0.x; s0.y+=p0.y; s0.z+=p0.z; s0.w+=p0.w;
                    s1.x+=p1.x; s1.y+=p1.y; s1.z+=p1.z; s1.w+=p1.w;
                }
                *(float4*)(g_gates + b*2048 + c0) = s0;
                *(float4*)(g_gates + b*2048 + c0 + 4) = s1;
            } else {
                int rid = task - 160;
                int b = rid >> 1, half = rid & 1;
                if (b >= A) continue;
                int c0 = half*1024 + tid*4;
                float4 s = *(const float4*)(b_beta + c0);
                #pragma unroll
                for (int sk = 0; sk < 8; sk++) {
                    float4 p = *(const float4*)(g_pBeta + (long)sk*65536 + b*2048 + c0);
                    s.x+=p.x; s.y+=p.y; s.z+=p.z; s.w+=p.w;
                }
                float4 o;
                o.x = sigm(s.x); o.y = sigm(s.y); o.z = sigm(s.z); o.w = sigm(s.w);
                *(float4*)(g_betasig + b*2048 + c0) = o;
            }
        }
        gridbar();

        // Ph3: awe (256: b x 8 chunks of 256 cols), local softmax
        for (int task = bid; task < 256; task += GRID) {
            int b = task >> 3, ch = task & 7;
            if (b >= A) continue;
            awe_task(b, ch, t, img, out, pool);
        }
        gridbar();

        // Ph4: x2 @ W_ih[:,512:]^T (256: 16nt x SK16, klen=128)
        for (int task = bid; task < 256; task += GRID) {
            int nt = task >> 4, sk = task & 15;
            gemm128(g_x2, 2048, W_ih, 2560, 512,
                    nt*128, sk*128, 128, g_pIH + (long)sk*65536, 2048, pool);
        }
        gridbar();

        // Ph5: gate reduce + LSTM (128: b x j-quarter, 2 slice-groups of 8)
        for (int task = bid; task < 128; task += GRID) {
            int b = task >> 2, quarter = task & 3;
            if (b >= A) continue;
            float* partial = pool;
            const int j = quarter*128 + (tid & 127);
            const int grp = tid >> 7;
            float gi = 0.f, gf = 0.f, gg = 0.f, go = 0.f;
            const int skb = grp * 8;
            #pragma unroll
            for (int sk = 0; sk < 8; sk++) {
                const float* p = g_pIH + (long)(skb + sk)*65536 + b*2048;
                gi += p[j]; gf += p[j + 512]; gg += p[j + 1024]; go += p[j + 1536];
            }
            __syncthreads();
            if (grp == 1) {
                partial[(tid & 127)]       = gi;
                partial[(tid & 127) + 128] = gf;
                partial[(tid & 127) + 256] = gg;
                partial[(tid & 127) + 384] = go;
            }
            __syncthreads();
            if (grp == 0) {
                gi += partial[tid]       + g_gates[b*2048 + j];
                gf += partial[tid + 128] + g_gates[b*2048 + j + 512];
                gg += partial[tid + 256] + g_gates[b*2048 + j + 1024];
                go += partial[tid + 384] + g_gates[b*2048 + j + 1536];
                float c = g_c[b*512 + j];
                float cn = sigm(gf)*c + sigm(gi)*tanhf(gg);
                float hn = sigm(go)*tanhf(cn);
                g_hnall[((long)t*32 + b)*512 + j] = hn;
                g_c[b*512 + j] = cn;
                g_h[b*512 + j] = hn;
            }
            __syncthreads();
        }
        gridbar();
    }

    // ---- epilogue: preds = Hn_all @ W_fc^T + b_fc ----
    for (int task = bid; task < 13*157; task += GRID) {
        int tm = task / 157, tn = task - tm*157;
        fc_task(tm, tn, W_fc, b_fc, out, pool);
    }
}

// ---------------- host launcher ----------------
extern "C" void kernel_launch(void* const* d_in, const int* in_sizes, int n_in,
                              void* d_out, int out_size) {
    persist<<<GRID, 256>>>(
        (const float*)d_in[0],  (const int*)d_in[1],   (const int*)d_in[2],
        (const float*)d_in[3],  (const float*)d_in[4],
        (const float*)d_in[5],  (const float*)d_in[6],
        (const float*)d_in[7],  (const float*)d_in[8],
        (const float*)d_in[9],
        (const float*)d_in[10], (const float*)d_in[11],
        (const float*)d_in[12], (const float*)d_in[13],
        (const float*)d_in[14], (const float*)d_in[15],
        (const float*)d_in[16], (const float*)d_in[17],
        (const float*)d_in[18], (const float*)d_in[19],
        (const float*)d_in[20], (const float*)d_in[21],
        (float*)d_out);
    (void)in_sizes; (void)n_in; (void)out_size;
}